// round 7
// baseline (speedup 1.0000x reference)
#include <cuda_runtime.h>
#include <cuda_fp16.h>
#include <math.h>

#define BB   8
#define TT   150
#define DD   30
#define HH   5
#define HDD  6
#define LL   3
#define NI   40     // BB*HH
#define KL   300
#define KA   74
#define KV   35
#define AA   10     // a-values per attention block (5 fp16x2 pairs)
#define ATTG 600    // k_att grid (2 items per block, one wave)

// ---------------- device scratch (no allocations allowed) ----------------
__device__ float g_h[2][TT*BB*DD];            // per-stream hidden state [T,B,D]
__device__ float g_K[2][LL][NI*TT*HDD];       // per (s,l): [i, t, e]
__device__ float g_V[2][LL][NI*TT*HDD];
__device__ float g_Q[2][NI*TT*HDD];           // current-layer Q
__device__ float g_attn[2][TT*BB*DD];         // attention output [T,B,D]

__device__ __forceinline__ float warpsum(float v){
    #pragma unroll
    for (int o=16;o>0;o>>=1) v += __shfl_xor_sync(0xffffffffu, v, o);
    return v;
}

// ---------------- 1. fused pre-stage: proj + all K/V + Q(l=0) -------------
// one block per (t,b); everything is row-local.
__global__ void __launch_bounds__(96) k_pre(
    const float* __restrict__ xl, const float* __restrict__ xa,
    const float* __restrict__ xv, const float* __restrict__ Wl,
    const float* __restrict__ Wa, const float* __restrict__ Wv,
    const float* __restrict__ in_w, const float* __restrict__ in_b,
    const float* __restrict__ n1g, const float* __restrict__ n1b){
    int r = blockIdx.x;                  // 0..T*B-1
    int t = r / BB, b = r % BB;
    int w = threadIdx.x >> 5, lane = threadIdx.x & 31;
    __shared__ float sx[KL+KA+KV];
    __shared__ float xn[3][DD];
    __shared__ float axk[DD], axv[DD], axq[DD];
    for (int k=threadIdx.x; k<KL; k+=96) sx[k]        = xl[(b*TT+t)*KL + k];
    for (int k=threadIdx.x; k<KA; k+=96) sx[KL+k]     = xa[(b*TT+t)*KA + k];
    for (int k=threadIdx.x; k<KV; k+=96) sx[KL+KA+k]  = xv[(b*TT+t)*KV + k];
    __syncthreads();
    // modality projection: warp w -> mod w
    float pv = 0.f;
    {
        const float* W  = (w==0)? Wl : (w==1)? Wa : Wv;
        int K           = (w==0)? KL : (w==1)? KA : KV;
        const float* xs = sx + ((w==0)? 0 : (w==1)? KL : KL+KA);
        if (lane < DD){
            const float* wr = W + lane*K;
            for (int k=0;k<K;k++) pv = fmaf(xs[k], wr[k], pv);
            if (w==0){ int o=(t*BB+b)*DD+lane; g_h[0][o]=pv; g_h[1][o]=pv; }
        }
    }
    // LN normalize (no affine yet)
    {
        float x = (lane<DD)? pv : 0.f;
        float sum = warpsum(x), sq = warpsum(x*x);
        float m = sum*(1.f/DD), var = sq*(1.f/DD)-m*m, rs = rsqrtf(var+1e-5f);
        if (lane<DD) xn[w][lane] = (x-m)*rs;
    }
    __syncthreads();
    #pragma unroll 1
    for (int sl=0; sl<6; sl++){
        int s_ = sl/LL, l_ = sl%LL;
        int ksrc = (s_==0)?1:2, vsrc = (s_==0)?2:1;
        int pb = sl*DD;
        if (lane<DD){
            float g = n1g[pb+lane], be = n1b[pb+lane];
            if (w==0) axk[lane] = xn[ksrc][lane]*g + be;
            else if (w==1) axv[lane] = xn[vsrc][lane]*g + be;
            else if (l_==0) axq[lane] = xn[0][lane]*g + be;
        }
        __syncthreads();
        if (lane<DD){
            const float* iw = in_w + sl*3*DD*DD;
            const float* ib = in_b + sl*3*DD;
            int i = b*HH + lane/HDD, e = lane%HDD;
            int o = (i*TT + t)*HDD + e;
            if (w==0){
                float acc = ib[DD+lane];
                const float* wr = iw + (DD+lane)*DD;
                #pragma unroll
                for (int j=0;j<DD;j++) acc = fmaf(axk[j], wr[j], acc);
                g_K[s_][l_][o] = acc;
            } else if (w==1){
                float acc = ib[2*DD+lane];
                const float* wr = iw + (2*DD+lane)*DD;
                #pragma unroll
                for (int j=0;j<DD;j++) acc = fmaf(axv[j], wr[j], acc);
                g_V[s_][l_][o] = acc;
            } else if (l_==0){
                float acc = ib[lane];
                const float* wr = iw + lane*DD;
                #pragma unroll
                for (int j=0;j<DD;j++) acc = fmaf(axq[j], wr[j], acc);
                g_Q[s_][o] = acc * 0.4082482904638631f;
            }
        }
        __syncthreads();
    }
}

// ---------------- 2. attention core (fp16x2 HFMA2 scan, hot kernel) -------
// 600 blocks, each handles exactly 2 (s,i,a-group) items -> single wave.
// fused[a,b] = max_c (q_a o k_b) . (v_c + vbar)     [mean folded into max]
// then softmax over b and attn[a,:] = sum_b p_b * q_b
__global__ void __launch_bounds__(160) k_att(int l){
    int tid = threadIdx.x;
    int lane = tid & 31, w = tid >> 5;
    __shared__ __align__(16) __half2 sVh[TT][8];  // v' duplicated fp16 pairs
    __shared__ float sQa[AA*HDD];
    __shared__ float sP[5][8];
    __shared__ float sVbar[HDD];
    __shared__ float sMax[AA][5];
    __shared__ float sBMax[AA];
    __shared__ float sSum[AA][5][8];
    bool valid = tid < TT;
    int b = valid ? tid : 0;

    #pragma unroll 1
    for (int m = blockIdx.x; m < 2*NI*(TT/AA); m += ATTG){
        int s = m / (NI*(TT/AA));
        int rem = m % (NI*(TT/AA));
        int i = rem / (TT/AA);
        int a0 = (rem % (TT/AA)) * AA;
        const float* Kp = g_K[s][l] + i*TT*HDD;
        const float* Vp = g_V[s][l] + i*TT*HDD;
        const float* Qp = g_Q[s]    + i*TT*HDD;

        float kb[HDD], vv[HDD];
        #pragma unroll
        for (int e=0;e<HDD;e++){
            kb[e] = Kp[b*HDD+e];
            vv[e] = valid ? Vp[b*HDD+e] : 0.f;
        }
        {   // vbar partials
            float p[HDD];
            #pragma unroll
            for (int e=0;e<HDD;e++) p[e] = warpsum(vv[e]);
            if (lane==0){
                #pragma unroll
                for (int e=0;e<HDD;e++) sP[w][e] = p[e];
            }
        }
        if (tid < AA*HDD) sQa[tid] = Qp[a0*HDD + tid];
        __syncthreads();
        if (tid < HDD){
            float acc = 0.f;
            #pragma unroll
            for (int ww=0;ww<5;ww++) acc += sP[ww][tid];
            sVbar[tid] = acc * (1.f/TT);
        }
        __syncthreads();
        if (valid){
            #pragma unroll
            for (int e=0;e<HDD;e++)
                sVh[tid][e] = __float2half2_rn(vv[e] + sVbar[e]);
        }
        __syncthreads();

        // kq in fp16x2 (a-pairs)
        __half2 kq[5][HDD];
        #pragma unroll
        for (int p=0;p<5;p++)
            #pragma unroll
            for (int e=0;e<HDD;e++)
                kq[p][e] = __floats2half2_rn(sQa[(2*p)*HDD+e]*kb[e],
                                             sQa[(2*p+1)*HDD+e]*kb[e]);

        __half2 mx2[5];
        #pragma unroll
        for (int p=0;p<5;p++) mx2[p] = __floats2half2_rn(-60000.f, -60000.f);

        #pragma unroll 2
        for (int c=0;c<TT;c++){
            uint4 u0 = *reinterpret_cast<const uint4*>(&sVh[c][0]);
            uint2 u1 = *reinterpret_cast<const uint2*>(&sVh[c][4]);
            __half2 v0 = *(__half2*)&u0.x, v1 = *(__half2*)&u0.y;
            __half2 v2 = *(__half2*)&u0.z, v3 = *(__half2*)&u0.w;
            __half2 v4 = *(__half2*)&u1.x, v5 = *(__half2*)&u1.y;
            #pragma unroll
            for (int p=0;p<5;p++){
                __half2 acc = __hmul2(kq[p][0], v0);
                acc = __hfma2(kq[p][1], v1, acc);
                acc = __hfma2(kq[p][2], v2, acc);
                acc = __hfma2(kq[p][3], v3, acc);
                acc = __hfma2(kq[p][4], v4, acc);
                acc = __hfma2(kq[p][5], v5, acc);
                mx2[p] = __hmax2(mx2[p], acc);
            }
        }
        float fx[AA];
        #pragma unroll
        for (int p=0;p<5;p++){
            fx[2*p]   = __low2float(mx2[p]);
            fx[2*p+1] = __high2float(mx2[p]);
        }

        // ---- batched epilogue ----
        #pragma unroll
        for (int a=0;a<AA;a++){
            float mm = valid ? fx[a] : -INFINITY;
            #pragma unroll
            for (int o=16;o>0;o>>=1) mm = fmaxf(mm, __shfl_xor_sync(0xffffffffu, mm, o));
            if (lane==0) sMax[a][w] = mm;
        }
        __syncthreads();
        if (tid < AA){
            float mm = sMax[tid][0];
            #pragma unroll
            for (int ww=1;ww<5;ww++) mm = fmaxf(mm, sMax[tid][ww]);
            sBMax[tid] = mm;
        }
        __syncthreads();
        float qb[HDD];
        #pragma unroll
        for (int e=0;e<HDD;e++) qb[e] = Qp[b*HDD+e];
        #pragma unroll
        for (int a=0;a<AA;a++){
            float ex = valid ? __expf(fx[a] - sBMax[a]) : 0.f;
            float v7[7];
            #pragma unroll
            for (int e=0;e<HDD;e++) v7[e] = ex*qb[e];
            v7[6] = ex;
            #pragma unroll
            for (int j=0;j<7;j++){
                float v = v7[j];
                #pragma unroll
                for (int o=16;o>0;o>>=1) v += __shfl_xor_sync(0xffffffffu, v, o);
                if (lane==0) sSum[a][w][j] = v;
            }
        }
        __syncthreads();
        if (tid < AA*HDD){
            int a = tid / HDD, e = tid % HDD;
            float num=0.f, den=0.f;
            #pragma unroll
            for (int ww=0;ww<5;ww++){ num += sSum[a][ww][e]; den += sSum[a][ww][6]; }
            int b_ = i/HH, h_ = i%HH;
            g_attn[s][((a0+a)*BB + b_)*DD + h_*HDD + e] = num/den;
        }
        __syncthreads();               // protect smem reuse for next item
    }
}

// ---------------- 3. out-proj + residual + LN + FFN + residual + Q(l+1) --
__global__ void k_ffnq(const float* __restrict__ out_w, const float* __restrict__ out_b,
                       const float* __restrict__ w1, const float* __restrict__ b1,
                       const float* __restrict__ w2, const float* __restrict__ b2,
                       const float* __restrict__ n2g, const float* __restrict__ n2b,
                       const float* __restrict__ in_w, const float* __restrict__ in_b,
                       const float* __restrict__ n1g, const float* __restrict__ n1b, int l){
    int w = threadIdx.x >> 5, lane = threadIdx.x & 31;
    int idx = blockIdx.x*4 + w;           // 2*T*B rows
    int b = idx % BB; idx /= BB;
    int t = idx % TT; int s = idx / TT;
    __shared__ float sA[4][DD], sXn[4][DD], sHid[4][4*DD];
    int ro = (t*BB+b)*DD;
    if (lane<DD) sA[w][lane] = g_attn[s][ro+lane];
    __syncwarp();
    int pl_ = s*LL+l;
    float x = 0.f;
    if (lane<DD){
        const float* wr = out_w + pl_*DD*DD + lane*DD;
        float acc = out_b[pl_*DD + lane];
        #pragma unroll
        for (int j=0;j<DD;j++) acc = fmaf(sA[w][j], wr[j], acc);
        x = g_h[s][ro+lane] + acc;        // residual
    }
    float sum = warpsum(x), sq = warpsum(x*x);
    float m = sum*(1.f/DD), var = sq*(1.f/DD)-m*m, r = rsqrtf(var+1e-5f);
    if (lane<DD) sXn[w][lane] = (x-m)*r*n2g[pl_*DD+lane] + n2b[pl_*DD+lane];
    __syncwarp();
    for (int j=lane; j<4*DD; j+=32){
        const float* wr = w1 + pl_*4*DD*DD + j*DD;
        float acc = b1[pl_*4*DD + j];
        #pragma unroll
        for (int q=0;q<DD;q++) acc = fmaf(sXn[w][q], wr[q], acc);
        sHid[w][j] = fmaxf(acc, 0.f);
    }
    __syncwarp();
    float hnew = 0.f;
    if (lane<DD){
        const float* wr = w2 + pl_*DD*4*DD + lane*4*DD;
        float acc = b2[pl_*DD + lane];
        #pragma unroll 4
        for (int j=0;j<4*DD;j++) acc = fmaf(sHid[w][j], wr[j], acc);
        hnew = x + acc;                   // residual 2
        g_h[s][ro+lane] = hnew;
    }
    if (l+1 < LL){
        // fused Q projection for next layer
        float sum2 = warpsum(hnew), sq2 = warpsum(hnew*hnew);
        float m2 = sum2*(1.f/DD), var2 = sq2*(1.f/DD)-m2*m2, r2 = rsqrtf(var2+1e-5f);
        int pb = (pl_+1)*DD;
        if (lane<DD) sA[w][lane] = (hnew-m2)*r2*n1g[pb+lane] + n1b[pb+lane];
        __syncwarp();
        if (lane<DD){
            const float* iw = in_w + (pl_+1)*3*DD*DD + lane*DD;
            float acc = in_b[(pl_+1)*3*DD + lane];
            #pragma unroll
            for (int j=0;j<DD;j++) acc = fmaf(sA[w][j], iw[j], acc);
            acc *= 0.4082482904638631f;
            int i = b*HH + lane/HDD, e = lane%HDD;
            g_Q[s][(i*TT+t)*HDD+e] = acc;
        }
    }
}

// ---------------- 4. head: concat last timestep, proj MLP, output --------
__global__ void k_head(const float* __restrict__ p1w, const float* __restrict__ p1b,
                       const float* __restrict__ p2w, const float* __restrict__ p2b,
                       const float* __restrict__ ow, const float* __restrict__ ob,
                       float* __restrict__ out){
    int tid = threadIdx.x;                // 64 threads
    __shared__ float sLast[BB*2*DD], sHid[2*DD], sC[2*DD];
    for (int idx=tid; idx<BB*2*DD; idx+=64){
        int b = idx/(2*DD), j = idx%(2*DD);
        float v = (j<DD) ? g_h[0][((TT-1)*BB+b)*DD + j]
                         : g_h[1][((TT-1)*BB+b)*DD + (j-DD)];
        sLast[idx] = v;
        out[BB + idx] = v;                // last_hs after out[0:8]
    }
    __syncthreads();
    for (int b=0;b<BB;b++){
        if (tid < 2*DD){
            float acc = p1b[tid];
            const float* wr = p1w + tid*2*DD;
            for (int j=0;j<2*DD;j++) acc = fmaf(sLast[b*2*DD+j], wr[j], acc);
            sHid[tid] = fmaxf(acc, 0.f);
        }
        __syncthreads();
        if (tid < 2*DD){
            float acc = p2b[tid];
            const float* wr = p2w + tid*2*DD;
            for (int j=0;j<2*DD;j++) acc = fmaf(sHid[j], wr[j], acc);
            acc += sLast[b*2*DD+tid];     // residual
            sC[tid] = acc * ow[tid];
        }
        __syncthreads();
        if (tid==0){
            float acc = ob[0];
            for (int j=0;j<2*DD;j++) acc += sC[j];
            out[b] = acc;
        }
        __syncthreads();
    }
}

// -------------------------------------------------------------------------
extern "C" void kernel_launch(void* const* d_in, const int* in_sizes, int n_in,
                              void* d_out, int out_size){
    const float* xl   = (const float*)d_in[0];
    const float* xa   = (const float*)d_in[1];
    const float* xv   = (const float*)d_in[2];
    const float* Wl   = (const float*)d_in[3];
    const float* Wa   = (const float*)d_in[4];
    const float* Wv   = (const float*)d_in[5];
    const float* in_w = (const float*)d_in[6];
    const float* in_b = (const float*)d_in[7];
    const float* outw = (const float*)d_in[8];
    const float* outb = (const float*)d_in[9];
    const float* l1w  = (const float*)d_in[10];
    const float* l1b  = (const float*)d_in[11];
    const float* l2w  = (const float*)d_in[12];
    const float* l2b  = (const float*)d_in[13];
    const float* n1g  = (const float*)d_in[14];
    const float* n1b  = (const float*)d_in[15];
    const float* n2g  = (const float*)d_in[16];
    const float* n2b  = (const float*)d_in[17];
    const float* p1w  = (const float*)d_in[18];
    const float* p1b  = (const float*)d_in[19];
    const float* p2w  = (const float*)d_in[20];
    const float* p2b  = (const float*)d_in[21];
    const float* ow   = (const float*)d_in[22];
    const float* ob   = (const float*)d_in[23];
    float* out = (float*)d_out;

    k_pre<<<TT*BB, 96>>>(xl, xa, xv, Wl, Wa, Wv, in_w, in_b, n1g, n1b);
    for (int l=0; l<LL; l++){
        k_att<<<ATTG, 160>>>(l);
        k_ffnq<<<2*TT*BB/4, 128>>>(outw, outb, l1w, l1b, l2w, l2b, n2g, n2b,
                                   in_w, in_b, n1g, n1b, l);
    }
    k_head<<<1, 64>>>(p1w, p1b, p2w, p2b, ow, ob, out);
}

// round 8
// speedup vs baseline: 1.0783x; 1.0783x over previous
#include <cuda_runtime.h>
#include <cuda_fp16.h>
#include <math.h>

#define BB   8
#define TT   150
#define DD   30
#define HH   5
#define HDD  6
#define LL   3
#define NI   40     // BB*HH
#define KL   300
#define KA   74
#define KV   35
#define AA   10     // a-values per attention block (5 fp16x2 pairs)

// ---------------- device scratch (no allocations allowed) ----------------
__device__ float g_h[2][TT*BB*DD];            // per-stream hidden state [T,B,D]
__device__ float g_K[2][LL][NI*TT*HDD];       // per (s,l): [i, t, e]
__device__ float g_V[2][LL][NI*TT*HDD];
__device__ float g_Q[2][NI*TT*HDD];           // current-layer Q
__device__ float g_attn[2][TT*BB*DD];         // attention output [T,B,D]

__device__ __forceinline__ float warpsum(float v){
    #pragma unroll
    for (int o=16;o>0;o>>=1) v += __shfl_xor_sync(0xffffffffu, v, o);
    return v;
}

// ---------------- 1. fused pre-stage: proj + all K/V + Q(l=0) -------------
// one block per (t,b); everything is row-local.
__global__ void __launch_bounds__(96) k_pre(
    const float* __restrict__ xl, const float* __restrict__ xa,
    const float* __restrict__ xv, const float* __restrict__ Wl,
    const float* __restrict__ Wa, const float* __restrict__ Wv,
    const float* __restrict__ in_w, const float* __restrict__ in_b,
    const float* __restrict__ n1g, const float* __restrict__ n1b){
    int r = blockIdx.x;                  // 0..T*B-1
    int t = r / BB, b = r % BB;
    int w = threadIdx.x >> 5, lane = threadIdx.x & 31;
    __shared__ float sx[KL+KA+KV];
    __shared__ float xn[3][DD];
    __shared__ float axk[DD], axv[DD], axq[DD];
    for (int k=threadIdx.x; k<KL; k+=96) sx[k]        = xl[(b*TT+t)*KL + k];
    for (int k=threadIdx.x; k<KA; k+=96) sx[KL+k]     = xa[(b*TT+t)*KA + k];
    for (int k=threadIdx.x; k<KV; k+=96) sx[KL+KA+k]  = xv[(b*TT+t)*KV + k];
    __syncthreads();
    // modality projection: warp w -> mod w
    float pv = 0.f;
    {
        const float* W  = (w==0)? Wl : (w==1)? Wa : Wv;
        int K           = (w==0)? KL : (w==1)? KA : KV;
        const float* xs = sx + ((w==0)? 0 : (w==1)? KL : KL+KA);
        if (lane < DD){
            const float* wr = W + lane*K;
            for (int k=0;k<K;k++) pv = fmaf(xs[k], wr[k], pv);
            if (w==0){ int o=(t*BB+b)*DD+lane; g_h[0][o]=pv; g_h[1][o]=pv; }
        }
    }
    // LN normalize (no affine yet)
    {
        float x = (lane<DD)? pv : 0.f;
        float sum = warpsum(x), sq = warpsum(x*x);
        float m = sum*(1.f/DD), var = sq*(1.f/DD)-m*m, rs = rsqrtf(var+1e-5f);
        if (lane<DD) xn[w][lane] = (x-m)*rs;
    }
    __syncthreads();
    #pragma unroll 1
    for (int sl=0; sl<6; sl++){
        int s_ = sl/LL, l_ = sl%LL;
        int ksrc = (s_==0)?1:2, vsrc = (s_==0)?2:1;
        int pb = sl*DD;
        if (lane<DD){
            float g = n1g[pb+lane], be = n1b[pb+lane];
            if (w==0) axk[lane] = xn[ksrc][lane]*g + be;
            else if (w==1) axv[lane] = xn[vsrc][lane]*g + be;
            else if (l_==0) axq[lane] = xn[0][lane]*g + be;
        }
        __syncthreads();
        if (lane<DD){
            const float* iw = in_w + sl*3*DD*DD;
            const float* ib = in_b + sl*3*DD;
            int i = b*HH + lane/HDD, e = lane%HDD;
            int o = (i*TT + t)*HDD + e;
            if (w==0){
                float acc = ib[DD+lane];
                const float* wr = iw + (DD+lane)*DD;
                #pragma unroll
                for (int j=0;j<DD;j++) acc = fmaf(axk[j], wr[j], acc);
                g_K[s_][l_][o] = acc;
            } else if (w==1){
                float acc = ib[2*DD+lane];
                const float* wr = iw + (2*DD+lane)*DD;
                #pragma unroll
                for (int j=0;j<DD;j++) acc = fmaf(axv[j], wr[j], acc);
                g_V[s_][l_][o] = acc;
            } else if (l_==0){
                float acc = ib[lane];
                const float* wr = iw + lane*DD;
                #pragma unroll
                for (int j=0;j<DD;j++) acc = fmaf(axq[j], wr[j], acc);
                g_Q[s_][o] = acc * 0.4082482904638631f;
            }
        }
        __syncthreads();
    }
}

// ---------------- 2. attention core (fp16x2 HFMA2 scan, hot kernel) -------
// One block per (s, i, 10-a group). 160 threads, thread = one b (key index).
// __launch_bounds__(160,8): cap regs at 51 -> 8 blocks/SM -> no tail wave.
// fused[a,b] = max_c (q_a o k_b) . (v_c + vbar)     [mean folded into max]
// then softmax over b and attn[a,:] = sum_b p_b * q_b
__global__ void __launch_bounds__(160, 8) k_att(int l){
    int s = blockIdx.z, i = blockIdx.y, a0 = blockIdx.x*AA;
    int tid = threadIdx.x;
    int lane = tid & 31, w = tid >> 5;
    __shared__ __align__(16) __half2 sVh[TT][8];  // v' duplicated fp16 pairs
    __shared__ float sQa[AA*HDD];
    __shared__ float sP[5][8];
    __shared__ float sVbar[HDD];
    __shared__ float sMax[AA][5];
    __shared__ float sBMax[AA];
    __shared__ float sSum[AA][5][8];
    const float* Kp = g_K[s][l] + i*TT*HDD;
    const float* Vp = g_V[s][l] + i*TT*HDD;
    const float* Qp = g_Q[s]    + i*TT*HDD;
    bool valid = tid < TT;
    int b = valid ? tid : 0;

    float kb[HDD], vv[HDD];
    #pragma unroll
    for (int e=0;e<HDD;e++){
        kb[e] = Kp[b*HDD+e];
        vv[e] = valid ? Vp[b*HDD+e] : 0.f;
    }
    {   // vbar partials
        float p[HDD];
        #pragma unroll
        for (int e=0;e<HDD;e++) p[e] = warpsum(vv[e]);
        if (lane==0){
            #pragma unroll
            for (int e=0;e<HDD;e++) sP[w][e] = p[e];
        }
    }
    if (tid < AA*HDD) sQa[tid] = Qp[a0*HDD + tid];
    __syncthreads();
    if (tid < HDD){
        float acc = 0.f;
        #pragma unroll
        for (int ww=0;ww<5;ww++) acc += sP[ww][tid];
        sVbar[tid] = acc * (1.f/TT);
    }
    __syncthreads();
    if (valid){
        #pragma unroll
        for (int e=0;e<HDD;e++)
            sVh[tid][e] = __float2half2_rn(vv[e] + sVbar[e]);
    }
    __syncthreads();

    // kq in fp16x2 (a-pairs)
    __half2 kq[5][HDD];
    #pragma unroll
    for (int p=0;p<5;p++)
        #pragma unroll
        for (int e=0;e<HDD;e++)
            kq[p][e] = __floats2half2_rn(sQa[(2*p)*HDD+e]*kb[e],
                                         sQa[(2*p+1)*HDD+e]*kb[e]);

    __half2 mx2[5];
    #pragma unroll
    for (int p=0;p<5;p++) mx2[p] = __floats2half2_rn(-60000.f, -60000.f);

    #pragma unroll 2
    for (int c=0;c<TT;c++){
        uint4 u0 = *reinterpret_cast<const uint4*>(&sVh[c][0]);
        uint2 u1 = *reinterpret_cast<const uint2*>(&sVh[c][4]);
        __half2 v0 = *(__half2*)&u0.x, v1 = *(__half2*)&u0.y;
        __half2 v2 = *(__half2*)&u0.z, v3 = *(__half2*)&u0.w;
        __half2 v4 = *(__half2*)&u1.x, v5 = *(__half2*)&u1.y;
        #pragma unroll
        for (int p=0;p<5;p++){
            __half2 acc = __hmul2(kq[p][0], v0);
            acc = __hfma2(kq[p][1], v1, acc);
            acc = __hfma2(kq[p][2], v2, acc);
            acc = __hfma2(kq[p][3], v3, acc);
            acc = __hfma2(kq[p][4], v4, acc);
            acc = __hfma2(kq[p][5], v5, acc);
            mx2[p] = __hmax2(mx2[p], acc);
        }
    }
    float fx[AA];
    #pragma unroll
    for (int p=0;p<5;p++){
        fx[2*p]   = __low2float(mx2[p]);
        fx[2*p+1] = __high2float(mx2[p]);
    }

    // ---- batched epilogue ----
    #pragma unroll
    for (int a=0;a<AA;a++){
        float mm = valid ? fx[a] : -INFINITY;
        #pragma unroll
        for (int o=16;o>0;o>>=1) mm = fmaxf(mm, __shfl_xor_sync(0xffffffffu, mm, o));
        if (lane==0) sMax[a][w] = mm;
    }
    __syncthreads();
    if (tid < AA){
        float mm = sMax[tid][0];
        #pragma unroll
        for (int ww=1;ww<5;ww++) mm = fmaxf(mm, sMax[tid][ww]);
        sBMax[tid] = mm;
    }
    __syncthreads();
    float qb[HDD];
    #pragma unroll
    for (int e=0;e<HDD;e++) qb[e] = Qp[b*HDD+e];
    #pragma unroll
    for (int a=0;a<AA;a++){
        float ex = valid ? __expf(fx[a] - sBMax[a]) : 0.f;
        float v7[7];
        #pragma unroll
        for (int e=0;e<HDD;e++) v7[e] = ex*qb[e];
        v7[6] = ex;
        #pragma unroll
        for (int j=0;j<7;j++){
            float v = v7[j];
            #pragma unroll
            for (int o=16;o>0;o>>=1) v += __shfl_xor_sync(0xffffffffu, v, o);
            if (lane==0) sSum[a][w][j] = v;
        }
    }
    __syncthreads();
    if (tid < AA*HDD){
        int a = tid / HDD, e = tid % HDD;
        float num=0.f, den=0.f;
        #pragma unroll
        for (int ww=0;ww<5;ww++){ num += sSum[a][ww][e]; den += sSum[a][ww][6]; }
        int b_ = i/HH, h_ = i%HH;
        g_attn[s][((a0+a)*BB + b_)*DD + h_*HDD + e] = num/den;
    }
}

// ---------------- 3. out-proj + residual + LN + FFN + residual + Q(l+1) --
__global__ void k_ffnq(const float* __restrict__ out_w, const float* __restrict__ out_b,
                       const float* __restrict__ w1, const float* __restrict__ b1,
                       const float* __restrict__ w2, const float* __restrict__ b2,
                       const float* __restrict__ n2g, const float* __restrict__ n2b,
                       const float* __restrict__ in_w, const float* __restrict__ in_b,
                       const float* __restrict__ n1g, const float* __restrict__ n1b, int l){
    int w = threadIdx.x >> 5, lane = threadIdx.x & 31;
    int idx = blockIdx.x*4 + w;           // 2*T*B rows
    int b = idx % BB; idx /= BB;
    int t = idx % TT; int s = idx / TT;
    __shared__ float sA[4][DD], sXn[4][DD], sHid[4][4*DD];
    int ro = (t*BB+b)*DD;
    if (lane<DD) sA[w][lane] = g_attn[s][ro+lane];
    __syncwarp();
    int pl_ = s*LL+l;
    float x = 0.f;
    if (lane<DD){
        const float* wr = out_w + pl_*DD*DD + lane*DD;
        float acc = out_b[pl_*DD + lane];
        #pragma unroll
        for (int j=0;j<DD;j++) acc = fmaf(sA[w][j], wr[j], acc);
        x = g_h[s][ro+lane] + acc;        // residual
    }
    float sum = warpsum(x), sq = warpsum(x*x);
    float m = sum*(1.f/DD), var = sq*(1.f/DD)-m*m, r = rsqrtf(var+1e-5f);
    if (lane<DD) sXn[w][lane] = (x-m)*r*n2g[pl_*DD+lane] + n2b[pl_*DD+lane];
    __syncwarp();
    for (int j=lane; j<4*DD; j+=32){
        const float* wr = w1 + pl_*4*DD*DD + j*DD;
        float acc = b1[pl_*4*DD + j];
        #pragma unroll
        for (int q=0;q<DD;q++) acc = fmaf(sXn[w][q], wr[q], acc);
        sHid[w][j] = fmaxf(acc, 0.f);
    }
    __syncwarp();
    float hnew = 0.f;
    if (lane<DD){
        const float* wr = w2 + pl_*DD*4*DD + lane*4*DD;
        float acc = b2[pl_*DD + lane];
        #pragma unroll 4
        for (int j=0;j<4*DD;j++) acc = fmaf(sHid[w][j], wr[j], acc);
        hnew = x + acc;                   // residual 2
        g_h[s][ro+lane] = hnew;
    }
    if (l+1 < LL){
        // fused Q projection for next layer
        float sum2 = warpsum(hnew), sq2 = warpsum(hnew*hnew);
        float m2 = sum2*(1.f/DD), var2 = sq2*(1.f/DD)-m2*m2, r2 = rsqrtf(var2+1e-5f);
        int pb = (pl_+1)*DD;
        if (lane<DD) sA[w][lane] = (hnew-m2)*r2*n1g[pb+lane] + n1b[pb+lane];
        __syncwarp();
        if (lane<DD){
            const float* iw = in_w + (pl_+1)*3*DD*DD + lane*DD;
            float acc = in_b[(pl_+1)*3*DD + lane];
            #pragma unroll
            for (int j=0;j<DD;j++) acc = fmaf(sA[w][j], iw[j], acc);
            acc *= 0.4082482904638631f;
            int i = b*HH + lane/HDD, e = lane%HDD;
            g_Q[s][(i*TT+t)*HDD+e] = acc;
        }
    }
}

// ---------------- 4. head: concat last timestep, proj MLP, output --------
__global__ void k_head(const float* __restrict__ p1w, const float* __restrict__ p1b,
                       const float* __restrict__ p2w, const float* __restrict__ p2b,
                       const float* __restrict__ ow, const float* __restrict__ ob,
                       float* __restrict__ out){
    int tid = threadIdx.x;                // 64 threads
    __shared__ float sLast[BB*2*DD], sHid[2*DD], sC[2*DD];
    for (int idx=tid; idx<BB*2*DD; idx+=64){
        int b = idx/(2*DD), j = idx%(2*DD);
        float v = (j<DD) ? g_h[0][((TT-1)*BB+b)*DD + j]
                         : g_h[1][((TT-1)*BB+b)*DD + (j-DD)];
        sLast[idx] = v;
        out[BB + idx] = v;                // last_hs after out[0:8]
    }
    __syncthreads();
    for (int b=0;b<BB;b++){
        if (tid < 2*DD){
            float acc = p1b[tid];
            const float* wr = p1w + tid*2*DD;
            for (int j=0;j<2*DD;j++) acc = fmaf(sLast[b*2*DD+j], wr[j], acc);
            sHid[tid] = fmaxf(acc, 0.f);
        }
        __syncthreads();
        if (tid < 2*DD){
            float acc = p2b[tid];
            const float* wr = p2w + tid*2*DD;
            for (int j=0;j<2*DD;j++) acc = fmaf(sHid[j], wr[j], acc);
            acc += sLast[b*2*DD+tid];     // residual
            sC[tid] = acc * ow[tid];
        }
        __syncthreads();
        if (tid==0){
            float acc = ob[0];
            for (int j=0;j<2*DD;j++) acc += sC[j];
            out[b] = acc;
        }
        __syncthreads();
    }
}

// -------------------------------------------------------------------------
extern "C" void kernel_launch(void* const* d_in, const int* in_sizes, int n_in,
                              void* d_out, int out_size){
    const float* xl   = (const float*)d_in[0];
    const float* xa   = (const float*)d_in[1];
    const float* xv   = (const float*)d_in[2];
    const float* Wl   = (const float*)d_in[3];
    const float* Wa   = (const float*)d_in[4];
    const float* Wv   = (const float*)d_in[5];
    const float* in_w = (const float*)d_in[6];
    const float* in_b = (const float*)d_in[7];
    const float* outw = (const float*)d_in[8];
    const float* outb = (const float*)d_in[9];
    const float* l1w  = (const float*)d_in[10];
    const float* l1b  = (const float*)d_in[11];
    const float* l2w  = (const float*)d_in[12];
    const float* l2b  = (const float*)d_in[13];
    const float* n1g  = (const float*)d_in[14];
    const float* n1b  = (const float*)d_in[15];
    const float* n2g  = (const float*)d_in[16];
    const float* n2b  = (const float*)d_in[17];
    const float* p1w  = (const float*)d_in[18];
    const float* p1b  = (const float*)d_in[19];
    const float* p2w  = (const float*)d_in[20];
    const float* p2b  = (const float*)d_in[21];
    const float* ow   = (const float*)d_in[22];
    const float* ob   = (const float*)d_in[23];
    float* out = (float*)d_out;

    k_pre<<<TT*BB, 96>>>(xl, xa, xv, Wl, Wa, Wv, in_w, in_b, n1g, n1b);
    for (int l=0; l<LL; l++){
        k_att<<<dim3(TT/AA, NI, 2), 160>>>(l);
        k_ffnq<<<2*TT*BB/4, 128>>>(outw, outb, l1w, l1b, l2w, l2b, n2g, n2b,
                                   in_w, in_b, n1g, n1b, l);
    }
    k_head<<<1, 64>>>(p1w, p1b, p2w, p2b, ow, ob, out);
}

// round 9
// speedup vs baseline: 1.1300x; 1.0479x over previous
#include <cuda_runtime.h>
#include <cuda_fp16.h>
#include <math.h>

#define BB   8
#define TT   150
#define DD   30
#define HH   5
#define HDD  6
#define LL   3
#define NI   40     // BB*HH
#define KL   300
#define KA   74
#define KV   35
#define AA   10     // a-values per attention block (5 fp16x2 pairs)
#define EPAD 164    // padded epilogue row length (bank-conflict-free float4)

// ---------------- device scratch (no allocations allowed) ----------------
__device__ float g_h[2][TT*BB*DD];            // per-stream hidden state [T,B,D]
__device__ float g_K[2][LL][NI*TT*HDD];       // per (s,l): [i, t, e]
__device__ float g_V[2][LL][NI*TT*HDD];
__device__ float g_Q[2][NI*TT*HDD];           // current-layer Q
__device__ float g_attn[2][TT*BB*DD];         // attention output [T,B,D]

__device__ __forceinline__ float warpsum(float v){
    #pragma unroll
    for (int o=16;o>0;o>>=1) v += __shfl_xor_sync(0xffffffffu, v, o);
    return v;
}

// ---------------- 1. fused pre-stage: proj + all K/V + Q(l=0) -------------
// one block per (t,b); everything is row-local.
__global__ void __launch_bounds__(96) k_pre(
    const float* __restrict__ xl, const float* __restrict__ xa,
    const float* __restrict__ xv, const float* __restrict__ Wl,
    const float* __restrict__ Wa, const float* __restrict__ Wv,
    const float* __restrict__ in_w, const float* __restrict__ in_b,
    const float* __restrict__ n1g, const float* __restrict__ n1b){
    int r = blockIdx.x;                  // 0..T*B-1
    int t = r / BB, b = r % BB;
    int w = threadIdx.x >> 5, lane = threadIdx.x & 31;
    __shared__ float sx[KL+KA+KV];
    __shared__ float xn[3][DD];
    __shared__ float axk[DD], axv[DD], axq[DD];
    for (int k=threadIdx.x; k<KL; k+=96) sx[k]        = xl[(b*TT+t)*KL + k];
    for (int k=threadIdx.x; k<KA; k+=96) sx[KL+k]     = xa[(b*TT+t)*KA + k];
    for (int k=threadIdx.x; k<KV; k+=96) sx[KL+KA+k]  = xv[(b*TT+t)*KV + k];
    __syncthreads();
    // modality projection: warp w -> mod w
    float pv = 0.f;
    {
        const float* W  = (w==0)? Wl : (w==1)? Wa : Wv;
        int K           = (w==0)? KL : (w==1)? KA : KV;
        const float* xs = sx + ((w==0)? 0 : (w==1)? KL : KL+KA);
        if (lane < DD){
            const float* wr = W + lane*K;
            for (int k=0;k<K;k++) pv = fmaf(xs[k], wr[k], pv);
            if (w==0){ int o=(t*BB+b)*DD+lane; g_h[0][o]=pv; g_h[1][o]=pv; }
        }
    }
    // LN normalize (no affine yet)
    {
        float x = (lane<DD)? pv : 0.f;
        float sum = warpsum(x), sq = warpsum(x*x);
        float m = sum*(1.f/DD), var = sq*(1.f/DD)-m*m, rs = rsqrtf(var+1e-5f);
        if (lane<DD) xn[w][lane] = (x-m)*rs;
    }
    __syncthreads();
    #pragma unroll 1
    for (int sl=0; sl<6; sl++){
        int s_ = sl/LL, l_ = sl%LL;
        int ksrc = (s_==0)?1:2, vsrc = (s_==0)?2:1;
        int pb = sl*DD;
        if (lane<DD){
            float g = n1g[pb+lane], be = n1b[pb+lane];
            if (w==0) axk[lane] = xn[ksrc][lane]*g + be;
            else if (w==1) axv[lane] = xn[vsrc][lane]*g + be;
            else if (l_==0) axq[lane] = xn[0][lane]*g + be;
        }
        __syncthreads();
        if (lane<DD){
            const float* iw = in_w + sl*3*DD*DD;
            const float* ib = in_b + sl*3*DD;
            int i = b*HH + lane/HDD, e = lane%HDD;
            int o = (i*TT + t)*HDD + e;
            if (w==0){
                float acc = ib[DD+lane];
                const float* wr = iw + (DD+lane)*DD;
                #pragma unroll
                for (int j=0;j<DD;j++) acc = fmaf(axk[j], wr[j], acc);
                g_K[s_][l_][o] = acc;
            } else if (w==1){
                float acc = ib[2*DD+lane];
                const float* wr = iw + (2*DD+lane)*DD;
                #pragma unroll
                for (int j=0;j<DD;j++) acc = fmaf(axv[j], wr[j], acc);
                g_V[s_][l_][o] = acc;
            } else if (l_==0){
                float acc = ib[lane];
                const float* wr = iw + lane*DD;
                #pragma unroll
                for (int j=0;j<DD;j++) acc = fmaf(axq[j], wr[j], acc);
                g_Q[s_][o] = acc * 0.4082482904638631f;
            }
        }
        __syncthreads();
    }
}

// ---------------- 2. attention core (fp16x2 HFMA2 scan, hot kernel) -------
// One block per (s, i, 10-a group). 160 threads, thread = one b (key index).
// fused[a,b] = max_c (q_a o k_b) . (v_c + vbar)     [mean folded into max]
// softmax over b; attn[a,:] = sum_b p_b q_b via smem float4 mini-GEMM.
__global__ void __launch_bounds__(160) k_att(int l){
    int s = blockIdx.z, i = blockIdx.y, a0 = blockIdx.x*AA;
    int tid = threadIdx.x;
    int lane = tid & 31, w = tid >> 5;
    __shared__ __align__(16) __half2 sVh[TT][8];  // v' duplicated fp16 pairs
    __shared__ float sQa[AA*HDD];
    __shared__ float sP[5][8];
    __shared__ float sVbar[HDD];
    __shared__ float sMax[AA][5];
    __shared__ float sBMax[AA];
    __shared__ __align__(16) float sEx[AA][EPAD]; // ex[a][b]
    __shared__ __align__(16) float sQt[7][EPAD];  // q^T[e][b], row 6 = ones
    __shared__ float sDot[AA][8];
    const float* Kp = g_K[s][l] + i*TT*HDD;
    const float* Vp = g_V[s][l] + i*TT*HDD;
    const float* Qp = g_Q[s]    + i*TT*HDD;
    bool valid = tid < TT;
    int b = valid ? tid : 0;

    float kb[HDD], vv[HDD];
    #pragma unroll
    for (int e=0;e<HDD;e++){
        kb[e] = Kp[b*HDD+e];
        vv[e] = valid ? Vp[b*HDD+e] : 0.f;
    }
    {   // vbar partials
        float p[HDD];
        #pragma unroll
        for (int e=0;e<HDD;e++) p[e] = warpsum(vv[e]);
        if (lane==0){
            #pragma unroll
            for (int e=0;e<HDD;e++) sP[w][e] = p[e];
        }
    }
    if (tid < AA*HDD) sQa[tid] = Qp[a0*HDD + tid];
    __syncthreads();
    if (tid < HDD){
        float acc = 0.f;
        #pragma unroll
        for (int ww=0;ww<5;ww++) acc += sP[ww][tid];
        sVbar[tid] = acc * (1.f/TT);
    }
    __syncthreads();
    if (valid){
        #pragma unroll
        for (int e=0;e<HDD;e++)
            sVh[tid][e] = __float2half2_rn(vv[e] + sVbar[e]);
    }
    __syncthreads();

    // kq in fp16x2 (a-pairs)
    __half2 kq[5][HDD];
    #pragma unroll
    for (int p=0;p<5;p++)
        #pragma unroll
        for (int e=0;e<HDD;e++)
            kq[p][e] = __floats2half2_rn(sQa[(2*p)*HDD+e]*kb[e],
                                         sQa[(2*p+1)*HDD+e]*kb[e]);

    __half2 mx2[5];
    #pragma unroll
    for (int p=0;p<5;p++) mx2[p] = __floats2half2_rn(-60000.f, -60000.f);

    #pragma unroll 2
    for (int c=0;c<TT;c++){
        uint4 u0 = *reinterpret_cast<const uint4*>(&sVh[c][0]);
        uint2 u1 = *reinterpret_cast<const uint2*>(&sVh[c][4]);
        __half2 v0 = *(__half2*)&u0.x, v1 = *(__half2*)&u0.y;
        __half2 v2 = *(__half2*)&u0.z, v3 = *(__half2*)&u0.w;
        __half2 v4 = *(__half2*)&u1.x, v5 = *(__half2*)&u1.y;
        #pragma unroll
        for (int p=0;p<5;p++){
            __half2 acc = __hmul2(kq[p][0], v0);
            acc = __hfma2(kq[p][1], v1, acc);
            acc = __hfma2(kq[p][2], v2, acc);
            acc = __hfma2(kq[p][3], v3, acc);
            acc = __hfma2(kq[p][4], v4, acc);
            acc = __hfma2(kq[p][5], v5, acc);
            mx2[p] = __hmax2(mx2[p], acc);
        }
    }
    float fx[AA];
    #pragma unroll
    for (int p=0;p<5;p++){
        fx[2*p]   = __low2float(mx2[p]);
        fx[2*p+1] = __high2float(mx2[p]);
    }

    // ---- max over b (warp shuffles + smem combine) ----
    #pragma unroll
    for (int a=0;a<AA;a++){
        float mm = valid ? fx[a] : -INFINITY;
        #pragma unroll
        for (int o=16;o>0;o>>=1) mm = fmaxf(mm, __shfl_xor_sync(0xffffffffu, mm, o));
        if (lane==0) sMax[a][w] = mm;
    }
    __syncthreads();
    if (tid < AA){
        float mm = sMax[tid][0];
        #pragma unroll
        for (int ww=1;ww<5;ww++) mm = fmaxf(mm, sMax[tid][ww]);
        sBMax[tid] = mm;
    }
    __syncthreads();

    // ---- ex + q^T to smem ----
    if (valid){
        float qb[HDD];
        #pragma unroll
        for (int e=0;e<HDD;e++) qb[e] = Qp[b*HDD+e];
        #pragma unroll
        for (int a=0;a<AA;a++) sEx[a][tid] = __expf(fx[a] - sBMax[a]);
        #pragma unroll
        for (int e=0;e<HDD;e++) sQt[e][tid] = qb[e];
        sQt[6][tid] = 1.f;
    } else {
        #pragma unroll
        for (int a=0;a<AA;a++) sEx[a][tid] = 0.f;
        #pragma unroll
        for (int e=0;e<7;e++) sQt[e][tid] = 0.f;
    }
    __syncthreads();

    // ---- mini-GEMM: dot[a][j] = sum_b ex[a][b] * qt[j][b] ----
    if (tid < AA*7){
        int a = tid / 7, j = tid % 7;
        const float4* ex4 = (const float4*)&sEx[a][0];
        const float4* q4  = (const float4*)&sQt[j][0];
        float acc = 0.f;
        #pragma unroll 5
        for (int b4=0;b4<40;b4++){
            float4 e4 = ex4[b4], qq = q4[b4];
            acc = fmaf(e4.x, qq.x, acc);
            acc = fmaf(e4.y, qq.y, acc);
            acc = fmaf(e4.z, qq.z, acc);
            acc = fmaf(e4.w, qq.w, acc);
        }
        sDot[a][j] = acc;
    }
    __syncthreads();
    if (tid < AA*7){
        int a = tid / 7, j = tid % 7;
        if (j < 6){
            int b_ = i/HH, h_ = i%HH;
            g_attn[s][((a0+a)*BB + b_)*DD + h_*HDD + j] = sDot[a][j]/sDot[a][6];
        }
    }
}

// ---------------- 3. out-proj + residual + LN + FFN + residual + Q(l+1) --
__global__ void k_ffnq(const float* __restrict__ out_w, const float* __restrict__ out_b,
                       const float* __restrict__ w1, const float* __restrict__ b1,
                       const float* __restrict__ w2, const float* __restrict__ b2,
                       const float* __restrict__ n2g, const float* __restrict__ n2b,
                       const float* __restrict__ in_w, const float* __restrict__ in_b,
                       const float* __restrict__ n1g, const float* __restrict__ n1b, int l){
    int w = threadIdx.x >> 5, lane = threadIdx.x & 31;
    int idx = blockIdx.x*4 + w;           // 2*T*B rows
    int b = idx % BB; idx /= BB;
    int t = idx % TT; int s = idx / TT;
    __shared__ float sA[4][DD], sXn[4][DD], sHid[4][4*DD];
    int ro = (t*BB+b)*DD;
    if (lane<DD) sA[w][lane] = g_attn[s][ro+lane];
    __syncwarp();
    int pl_ = s*LL+l;
    float x = 0.f;
    if (lane<DD){
        const float* wr = out_w + pl_*DD*DD + lane*DD;
        float acc = out_b[pl_*DD + lane];
        #pragma unroll
        for (int j=0;j<DD;j++) acc = fmaf(sA[w][j], wr[j], acc);
        x = g_h[s][ro+lane] + acc;        // residual
    }
    float sum = warpsum(x), sq = warpsum(x*x);
    float m = sum*(1.f/DD), var = sq*(1.f/DD)-m*m, r = rsqrtf(var+1e-5f);
    if (lane<DD) sXn[w][lane] = (x-m)*r*n2g[pl_*DD+lane] + n2b[pl_*DD+lane];
    __syncwarp();
    for (int j=lane; j<4*DD; j+=32){
        const float* wr = w1 + pl_*4*DD*DD + j*DD;
        float acc = b1[pl_*4*DD + j];
        #pragma unroll
        for (int q=0;q<DD;q++) acc = fmaf(sXn[w][q], wr[q], acc);
        sHid[w][j] = fmaxf(acc, 0.f);
    }
    __syncwarp();
    float hnew = 0.f;
    if (lane<DD){
        const float* wr = w2 + pl_*DD*4*DD + lane*4*DD;
        float acc = b2[pl_*DD + lane];
        #pragma unroll 4
        for (int j=0;j<4*DD;j++) acc = fmaf(sHid[w][j], wr[j], acc);
        hnew = x + acc;                   // residual 2
        g_h[s][ro+lane] = hnew;
    }
    if (l+1 < LL){
        // fused Q projection for next layer
        float sum2 = warpsum(hnew), sq2 = warpsum(hnew*hnew);
        float m2 = sum2*(1.f/DD), var2 = sq2*(1.f/DD)-m2*m2, r2 = rsqrtf(var2+1e-5f);
        int pb = (pl_+1)*DD;
        if (lane<DD) sA[w][lane] = (hnew-m2)*r2*n1g[pb+lane] + n1b[pb+lane];
        __syncwarp();
        if (lane<DD){
            const float* iw = in_w + (pl_+1)*3*DD*DD + lane*DD;
            float acc = in_b[(pl_+1)*3*DD + lane];
            #pragma unroll
            for (int j=0;j<DD;j++) acc = fmaf(sA[w][j], iw[j], acc);
            acc *= 0.4082482904638631f;
            int i = b*HH + lane/HDD, e = lane%HDD;
            g_Q[s][(i*TT+t)*HDD+e] = acc;
        }
    }
}

// ---------------- 4. head: concat last timestep, proj MLP, output --------
__global__ void k_head(const float* __restrict__ p1w, const float* __restrict__ p1b,
                       const float* __restrict__ p2w, const float* __restrict__ p2b,
                       const float* __restrict__ ow, const float* __restrict__ ob,
                       float* __restrict__ out){
    int tid = threadIdx.x;                // 64 threads
    __shared__ float sLast[BB*2*DD], sHid[2*DD], sC[2*DD];
    for (int idx=tid; idx<BB*2*DD; idx+=64){
        int b = idx/(2*DD), j = idx%(2*DD);
        float v = (j<DD) ? g_h[0][((TT-1)*BB+b)*DD + j]
                         : g_h[1][((TT-1)*BB+b)*DD + (j-DD)];
        sLast[idx] = v;
        out[BB + idx] = v;                // last_hs after out[0:8]
    }
    __syncthreads();
    for (int b=0;b<BB;b++){
        if (tid < 2*DD){
            float acc = p1b[tid];
            const float* wr = p1w + tid*2*DD;
            for (int j=0;j<2*DD;j++) acc = fmaf(sLast[b*2*DD+j], wr[j], acc);
            sHid[tid] = fmaxf(acc, 0.f);
        }
        __syncthreads();
        if (tid < 2*DD){
            float acc = p2b[tid];
            const float* wr = p2w + tid*2*DD;
            for (int j=0;j<2*DD;j++) acc = fmaf(sHid[j], wr[j], acc);
            acc += sLast[b*2*DD+tid];     // residual
            sC[tid] = acc * ow[tid];
        }
        __syncthreads();
        if (tid==0){
            float acc = ob[0];
            for (int j=0;j<2*DD;j++) acc += sC[j];
            out[b] = acc;
        }
        __syncthreads();
    }
}

// -------------------------------------------------------------------------
extern "C" void kernel_launch(void* const* d_in, const int* in_sizes, int n_in,
                              void* d_out, int out_size){
    const float* xl   = (const float*)d_in[0];
    const float* xa   = (const float*)d_in[1];
    const float* xv   = (const float*)d_in[2];
    const float* Wl   = (const float*)d_in[3];
    const float* Wa   = (const float*)d_in[4];
    const float* Wv   = (const float*)d_in[5];
    const float* in_w = (const float*)d_in[6];
    const float* in_b = (const float*)d_in[7];
    const float* outw = (const float*)d_in[8];
    const float* outb = (const float*)d_in[9];
    const float* l1w  = (const float*)d_in[10];
    const float* l1b  = (const float*)d_in[11];
    const float* l2w  = (const float*)d_in[12];
    const float* l2b  = (const float*)d_in[13];
    const float* n1g  = (const float*)d_in[14];
    const float* n1b  = (const float*)d_in[15];
    const float* n2g  = (const float*)d_in[16];
    const float* n2b  = (const float*)d_in[17];
    const float* p1w  = (const float*)d_in[18];
    const float* p1b  = (const float*)d_in[19];
    const float* p2w  = (const float*)d_in[20];
    const float* p2b  = (const float*)d_in[21];
    const float* ow   = (const float*)d_in[22];
    const float* ob   = (const float*)d_in[23];
    float* out = (float*)d_out;

    k_pre<<<TT*BB, 96>>>(xl, xa, xv, Wl, Wa, Wv, in_w, in_b, n1g, n1b);
    for (int l=0; l<LL; l++){
        k_att<<<dim3(TT/AA, NI, 2), 160>>>(l);
        k_ffnq<<<2*TT*BB/4, 128>>>(outw, outb, l1w, l1b, l2w, l2b, n2g, n2b,
                                   in_w, in_b, n1g, n1b, l);
    }
    k_head<<<1, 64>>>(p1w, p1b, p2w, p2b, ow, ob, out);
}

// round 10
// speedup vs baseline: 1.1603x; 1.0268x over previous
#include <cuda_runtime.h>
#include <cuda_fp16.h>
#include <math.h>

#define BB   8
#define TT   150
#define DD   30
#define HH   5
#define HDD  6
#define LL   3
#define NI   40     // BB*HH
#define KL   300
#define KA   74
#define KV   35
#define AA   10     // a-values per attention block (5 fp16x2 pairs)
#define EPAD 164    // padded epilogue row length (bank-conflict-free float4)

// ---------------- device scratch (no allocations allowed) ----------------
__device__ float g_h[2][TT*BB*DD];            // per-stream hidden state [T,B,D]
__device__ float g_K[2][LL][NI*TT*HDD];       // per (s,l): [i, t, e]
__device__ float g_V[2][LL][NI*TT*HDD];
__device__ float g_Q[2][NI*TT*HDD];           // current-layer Q
__device__ float g_attn[2][TT*BB*DD];         // attention output [T,B,D]

__device__ __forceinline__ float warpsum(float v){
    #pragma unroll
    for (int o=16;o>0;o>>=1) v += __shfl_xor_sync(0xffffffffu, v, o);
    return v;
}

// ---------------- 1. fused pre-stage: proj + all K/V + Q(l=0) -------------
// one block per (t,b); everything is row-local.
__global__ void __launch_bounds__(96) k_pre(
    const float* __restrict__ xl, const float* __restrict__ xa,
    const float* __restrict__ xv, const float* __restrict__ Wl,
    const float* __restrict__ Wa, const float* __restrict__ Wv,
    const float* __restrict__ in_w, const float* __restrict__ in_b,
    const float* __restrict__ n1g, const float* __restrict__ n1b){
    int r = blockIdx.x;                  // 0..T*B-1
    int t = r / BB, b = r % BB;
    int w = threadIdx.x >> 5, lane = threadIdx.x & 31;
    __shared__ float sx[KL+KA+KV];
    __shared__ float xn[3][DD];
    __shared__ float axk[DD], axv[DD], axq[DD];
    for (int k=threadIdx.x; k<KL; k+=96) sx[k]        = xl[(b*TT+t)*KL + k];
    for (int k=threadIdx.x; k<KA; k+=96) sx[KL+k]     = xa[(b*TT+t)*KA + k];
    for (int k=threadIdx.x; k<KV; k+=96) sx[KL+KA+k]  = xv[(b*TT+t)*KV + k];
    __syncthreads();
    // modality projection: warp w -> mod w
    float pv = 0.f;
    {
        const float* W  = (w==0)? Wl : (w==1)? Wa : Wv;
        int K           = (w==0)? KL : (w==1)? KA : KV;
        const float* xs = sx + ((w==0)? 0 : (w==1)? KL : KL+KA);
        if (lane < DD){
            const float* wr = W + lane*K;
            for (int k=0;k<K;k++) pv = fmaf(xs[k], wr[k], pv);
            if (w==0){ int o=(t*BB+b)*DD+lane; g_h[0][o]=pv; g_h[1][o]=pv; }
        }
    }
    // LN normalize (no affine yet)
    {
        float x = (lane<DD)? pv : 0.f;
        float sum = warpsum(x), sq = warpsum(x*x);
        float m = sum*(1.f/DD), var = sq*(1.f/DD)-m*m, rs = rsqrtf(var+1e-5f);
        if (lane<DD) xn[w][lane] = (x-m)*rs;
    }
    __syncthreads();
    #pragma unroll 1
    for (int sl=0; sl<6; sl++){
        int s_ = sl/LL, l_ = sl%LL;
        int ksrc = (s_==0)?1:2, vsrc = (s_==0)?2:1;
        int pb = sl*DD;
        if (lane<DD){
            float g = n1g[pb+lane], be = n1b[pb+lane];
            if (w==0) axk[lane] = xn[ksrc][lane]*g + be;
            else if (w==1) axv[lane] = xn[vsrc][lane]*g + be;
            else if (l_==0) axq[lane] = xn[0][lane]*g + be;
        }
        __syncthreads();
        if (lane<DD){
            const float* iw = in_w + sl*3*DD*DD;
            const float* ib = in_b + sl*3*DD;
            int i = b*HH + lane/HDD, e = lane%HDD;
            int o = (i*TT + t)*HDD + e;
            if (w==0){
                float acc = ib[DD+lane];
                const float* wr = iw + (DD+lane)*DD;
                #pragma unroll
                for (int j=0;j<DD;j++) acc = fmaf(axk[j], wr[j], acc);
                g_K[s_][l_][o] = acc;
            } else if (w==1){
                float acc = ib[2*DD+lane];
                const float* wr = iw + (2*DD+lane)*DD;
                #pragma unroll
                for (int j=0;j<DD;j++) acc = fmaf(axv[j], wr[j], acc);
                g_V[s_][l_][o] = acc;
            } else if (l_==0){
                float acc = ib[lane];
                const float* wr = iw + lane*DD;
                #pragma unroll
                for (int j=0;j<DD;j++) acc = fmaf(axq[j], wr[j], acc);
                g_Q[s_][o] = acc * 0.4082482904638631f;
            }
        }
        __syncthreads();
    }
}

// ---------------- 2. attention core (fp16x2 HFMA2 scan, hot kernel) -------
// One block per (s, i, 10-a group). 160 threads, thread = one b (key index).
// fused[a,b] = max_c (q_a o k_b) . (v_c + vbar)     [mean folded into max]
// softmax over b; attn[a,:] = sum_b p_b q_b via smem float4 mini-GEMM.
__global__ void __launch_bounds__(160) k_att(int l){
    int s = blockIdx.z, i = blockIdx.y, a0 = blockIdx.x*AA;
    int tid = threadIdx.x;
    int lane = tid & 31, w = tid >> 5;
    __shared__ __align__(16) __half2 sVh[TT][8];  // v' duplicated fp16 pairs
    __shared__ float sQa[AA*HDD];
    __shared__ float sP[5][8];
    __shared__ float sVbar[HDD];
    __shared__ float sMax[AA][5];
    __shared__ float sBMax[AA];
    __shared__ __align__(16) float sEx[AA][EPAD]; // ex[a][b]
    __shared__ __align__(16) float sQt[7][EPAD];  // q^T[e][b], row 6 = ones
    __shared__ float sDot[AA][8];
    const float* Kp = g_K[s][l] + i*TT*HDD;
    const float* Vp = g_V[s][l] + i*TT*HDD;
    const float* Qp = g_Q[s]    + i*TT*HDD;
    bool valid = tid < TT;
    int b = valid ? tid : 0;

    float kb[HDD], vv[HDD];
    #pragma unroll
    for (int e=0;e<HDD;e++){
        kb[e] = Kp[b*HDD+e];
        vv[e] = valid ? Vp[b*HDD+e] : 0.f;
    }
    {   // vbar partials
        float p[HDD];
        #pragma unroll
        for (int e=0;e<HDD;e++) p[e] = warpsum(vv[e]);
        if (lane==0){
            #pragma unroll
            for (int e=0;e<HDD;e++) sP[w][e] = p[e];
        }
    }
    if (tid < AA*HDD) sQa[tid] = Qp[a0*HDD + tid];
    __syncthreads();
    if (tid < HDD){
        float acc = 0.f;
        #pragma unroll
        for (int ww=0;ww<5;ww++) acc += sP[ww][tid];
        sVbar[tid] = acc * (1.f/TT);
    }
    __syncthreads();
    if (valid){
        #pragma unroll
        for (int e=0;e<HDD;e++)
            sVh[tid][e] = __float2half2_rn(vv[e] + sVbar[e]);
    }
    __syncthreads();

    // kq in fp16x2 (a-pairs)
    __half2 kq[5][HDD];
    #pragma unroll
    for (int p=0;p<5;p++)
        #pragma unroll
        for (int e=0;e<HDD;e++)
            kq[p][e] = __floats2half2_rn(sQa[(2*p)*HDD+e]*kb[e],
                                         sQa[(2*p+1)*HDD+e]*kb[e]);

    __half2 mx2[5];
    #pragma unroll
    for (int p=0;p<5;p++) mx2[p] = __floats2half2_rn(-60000.f, -60000.f);

    #pragma unroll 2
    for (int c=0;c<TT;c++){
        uint4 u0 = *reinterpret_cast<const uint4*>(&sVh[c][0]);
        uint2 u1 = *reinterpret_cast<const uint2*>(&sVh[c][4]);
        __half2 v0 = *(__half2*)&u0.x, v1 = *(__half2*)&u0.y;
        __half2 v2 = *(__half2*)&u0.z, v3 = *(__half2*)&u0.w;
        __half2 v4 = *(__half2*)&u1.x, v5 = *(__half2*)&u1.y;
        #pragma unroll
        for (int p=0;p<5;p++){
            __half2 acc = __hmul2(kq[p][0], v0);
            acc = __hfma2(kq[p][1], v1, acc);
            acc = __hfma2(kq[p][2], v2, acc);
            acc = __hfma2(kq[p][3], v3, acc);
            acc = __hfma2(kq[p][4], v4, acc);
            acc = __hfma2(kq[p][5], v5, acc);
            mx2[p] = __hmax2(mx2[p], acc);
        }
    }
    float fx[AA];
    #pragma unroll
    for (int p=0;p<5;p++){
        fx[2*p]   = __low2float(mx2[p]);
        fx[2*p+1] = __high2float(mx2[p]);
    }

    // ---- max over b (warp shuffles + smem combine) ----
    #pragma unroll
    for (int a=0;a<AA;a++){
        float mm = valid ? fx[a] : -INFINITY;
        #pragma unroll
        for (int o=16;o>0;o>>=1) mm = fmaxf(mm, __shfl_xor_sync(0xffffffffu, mm, o));
        if (lane==0) sMax[a][w] = mm;
    }
    __syncthreads();
    if (tid < AA){
        float mm = sMax[tid][0];
        #pragma unroll
        for (int ww=1;ww<5;ww++) mm = fmaxf(mm, sMax[tid][ww]);
        sBMax[tid] = mm;
    }
    __syncthreads();

    // ---- ex + q^T to smem ----
    if (valid){
        float qb[HDD];
        #pragma unroll
        for (int e=0;e<HDD;e++) qb[e] = Qp[b*HDD+e];
        #pragma unroll
        for (int a=0;a<AA;a++) sEx[a][tid] = __expf(fx[a] - sBMax[a]);
        #pragma unroll
        for (int e=0;e<HDD;e++) sQt[e][tid] = qb[e];
        sQt[6][tid] = 1.f;
    } else {
        #pragma unroll
        for (int a=0;a<AA;a++) sEx[a][tid] = 0.f;
        #pragma unroll
        for (int e=0;e<7;e++) sQt[e][tid] = 0.f;
    }
    __syncthreads();

    // ---- mini-GEMM: dot[a][j] = sum_b ex[a][b] * qt[j][b] ----
    if (tid < AA*7){
        int a = tid / 7, j = tid % 7;
        const float4* ex4 = (const float4*)&sEx[a][0];
        const float4* q4  = (const float4*)&sQt[j][0];
        float acc = 0.f;
        #pragma unroll 5
        for (int b4=0;b4<40;b4++){
            float4 e4 = ex4[b4], qq = q4[b4];
            acc = fmaf(e4.x, qq.x, acc);
            acc = fmaf(e4.y, qq.y, acc);
            acc = fmaf(e4.z, qq.z, acc);
            acc = fmaf(e4.w, qq.w, acc);
        }
        sDot[a][j] = acc;
    }
    __syncthreads();
    if (tid < AA*7){
        int a = tid / 7, j = tid % 7;
        if (j < 6){
            int b_ = i/HH, h_ = i%HH;
            g_attn[s][((a0+a)*BB + b_)*DD + h_*HDD + j] = sDot[a][j]/sDot[a][6];
        }
    }
}

// ---------------- 3. ffn (+ next-layer Q; + head fused in block 149, l=2) -
// 512 threads = 16 warps = 16 rows; row = t*16 + s*8 + b  (t-major!)
// block 149 owns all (s,b) rows at t=149 -> runs the output head for l==2.
__global__ void __launch_bounds__(512) k_ffnq(
                       const float* __restrict__ out_w, const float* __restrict__ out_b,
                       const float* __restrict__ w1, const float* __restrict__ b1,
                       const float* __restrict__ w2, const float* __restrict__ b2,
                       const float* __restrict__ n2g, const float* __restrict__ n2b,
                       const float* __restrict__ in_w, const float* __restrict__ in_b,
                       const float* __restrict__ n1g, const float* __restrict__ n1b,
                       const float* __restrict__ p1w, const float* __restrict__ p1b,
                       const float* __restrict__ p2w, const float* __restrict__ p2b,
                       const float* __restrict__ ow, const float* __restrict__ ob,
                       float* __restrict__ out, int l){
    int tid = threadIdx.x;
    int w = tid >> 5, lane = tid & 31;
    int gw = blockIdx.x*16 + w;           // row index, t-major
    int t = gw >> 4;
    int r16 = gw & 15;
    int s = r16 >> 3, b = r16 & 7;
    __shared__ float sA[16][DD], sXn[16][DD], sHid[16][4*DD];
    __shared__ float sLast[BB*2*DD];      // head scratch (block 149 only)
    __shared__ float sC[BB][2*DD];
    int ro = (t*BB+b)*DD;
    if (lane<DD) sA[w][lane] = g_attn[s][ro+lane];
    __syncwarp();
    int pl_ = s*LL+l;
    float x = 0.f;
    if (lane<DD){
        const float* wr = out_w + pl_*DD*DD + lane*DD;
        float acc = out_b[pl_*DD + lane];
        #pragma unroll
        for (int j=0;j<DD;j++) acc = fmaf(sA[w][j], wr[j], acc);
        x = g_h[s][ro+lane] + acc;        // residual
    }
    float sum = warpsum(x), sq = warpsum(x*x);
    float m = sum*(1.f/DD), var = sq*(1.f/DD)-m*m, rr = rsqrtf(var+1e-5f);
    if (lane<DD) sXn[w][lane] = (x-m)*rr*n2g[pl_*DD+lane] + n2b[pl_*DD+lane];
    __syncwarp();
    for (int j=lane; j<4*DD; j+=32){
        const float* wr = w1 + pl_*4*DD*DD + j*DD;
        float acc = b1[pl_*4*DD + j];
        #pragma unroll
        for (int q=0;q<DD;q++) acc = fmaf(sXn[w][q], wr[q], acc);
        sHid[w][j] = fmaxf(acc, 0.f);
    }
    __syncwarp();
    float hnew = 0.f;
    if (lane<DD){
        const float* wr = w2 + pl_*DD*4*DD + lane*4*DD;
        float acc = b2[pl_*DD + lane];
        #pragma unroll 4
        for (int j=0;j<4*DD;j++) acc = fmaf(sHid[w][j], wr[j], acc);
        hnew = x + acc;                   // residual 2
        g_h[s][ro+lane] = hnew;
    }
    if (l+1 < LL){
        // fused Q projection for next layer
        float sum2 = warpsum(hnew), sq2 = warpsum(hnew*hnew);
        float m2 = sum2*(1.f/DD), var2 = sq2*(1.f/DD)-m2*m2, r2 = rsqrtf(var2+1e-5f);
        int pb = (pl_+1)*DD;
        if (lane<DD) sA[w][lane] = (hnew-m2)*r2*n1g[pb+lane] + n1b[pb+lane];
        __syncwarp();
        if (lane<DD){
            const float* iw = in_w + (pl_+1)*3*DD*DD + lane*DD;
            float acc = in_b[(pl_+1)*3*DD + lane];
            #pragma unroll
            for (int j=0;j<DD;j++) acc = fmaf(sA[w][j], iw[j], acc);
            acc *= 0.4082482904638631f;
            int i = b*HH + lane/HDD, e = lane%HDD;
            g_Q[s][(i*TT+t)*HDD+e] = acc;
        }
    } else if (blockIdx.x == 149){
        // ---- fused head: this block owns all 16 rows at t = TT-1 ----
        if (lane < DD){
            sLast[b*2*DD + s*DD + lane] = hnew;
            out[BB + b*2*DD + s*DD + lane] = hnew;   // last_hs output
        }
        __syncthreads();
        int bb = tid >> 6, j = tid & 63;             // bb<8, j<64
        if (j < 2*DD){
            float acc = p1b[j];
            const float* wr = p1w + j*2*DD;
            for (int q=0;q<2*DD;q++) acc = fmaf(sLast[bb*2*DD+q], wr[q], acc);
            sC[bb][j] = fmaxf(acc, 0.f);
        }
        __syncthreads();
        float a2 = 0.f;
        if (j < 2*DD){
            a2 = p2b[j];
            const float* wr = p2w + j*2*DD;
            for (int q=0;q<2*DD;q++) a2 = fmaf(sC[bb][q], wr[q], a2);
            a2 = (a2 + sLast[bb*2*DD+j]) * ow[j];
        }
        __syncthreads();
        if (j < 2*DD) sC[bb][j] = a2;
        __syncthreads();
        if (tid < BB){
            float a3 = ob[0];
            for (int q=0;q<2*DD;q++) a3 += sC[tid][q];
            out[tid] = a3;
        }
    }
}

// -------------------------------------------------------------------------
extern "C" void kernel_launch(void* const* d_in, const int* in_sizes, int n_in,
                              void* d_out, int out_size){
    const float* xl   = (const float*)d_in[0];
    const float* xa   = (const float*)d_in[1];
    const float* xv   = (const float*)d_in[2];
    const float* Wl   = (const float*)d_in[3];
    const float* Wa   = (const float*)d_in[4];
    const float* Wv   = (const float*)d_in[5];
    const float* in_w = (const float*)d_in[6];
    const float* in_b = (const float*)d_in[7];
    const float* outw = (const float*)d_in[8];
    const float* outb = (const float*)d_in[9];
    const float* l1w  = (const float*)d_in[10];
    const float* l1b  = (const float*)d_in[11];
    const float* l2w  = (const float*)d_in[12];
    const float* l2b  = (const float*)d_in[13];
    const float* n1g  = (const float*)d_in[14];
    const float* n1b  = (const float*)d_in[15];
    const float* n2g  = (const float*)d_in[16];
    const float* n2b  = (const float*)d_in[17];
    const float* p1w  = (const float*)d_in[18];
    const float* p1b  = (const float*)d_in[19];
    const float* p2w  = (const float*)d_in[20];
    const float* p2b  = (const float*)d_in[21];
    const float* ow   = (const float*)d_in[22];
    const float* ob   = (const float*)d_in[23];
    float* out = (float*)d_out;

    k_pre<<<TT*BB, 96>>>(xl, xa, xv, Wl, Wa, Wv, in_w, in_b, n1g, n1b);
    for (int l=0; l<LL; l++){
        k_att<<<dim3(TT/AA, NI, 2), 160>>>(l);
        k_ffnq<<<(2*TT*BB)/16, 512>>>(outw, outb, l1w, l1b, l2w, l2b, n2g, n2b,
                                      in_w, in_b, n1g, n1b,
                                      p1w, p1b, p2w, p2b, ow, ob, out, l);
    }
}

// round 11
// speedup vs baseline: 1.4997x; 1.2925x over previous
#include <cuda_runtime.h>
#include <cuda_fp16.h>
#include <math.h>

#define BB   8
#define TT   150
#define DD   30
#define HH   5
#define HDD  6
#define LL   3
#define NI   40     // BB*HH
#define KL   300
#define KA   74
#define KV   35
#define ACH  30     // a-values per attention block
#define NCH  5      // a-chunks (ACH*NCH = TT)
#define EPAD 164    // padded row length (bank-friendly float4)

// ---------------- device scratch (no allocations allowed) ----------------
__device__ float g_h[2][TT*BB*DD];            // per-stream hidden state [T,B,D]
__device__ float g_K[2][LL][NI*TT*HDD];       // per (s,l): [i, t, e]
__device__ float g_V[2][LL][NI*TT*HDD];
__device__ float g_Q[2][NI*TT*HDD];           // current-layer Q
__device__ float g_attn[2][TT*BB*DD];         // attention output [T,B,D]

__device__ __forceinline__ float warpsum(float v){
    #pragma unroll
    for (int o=16;o>0;o>>=1) v += __shfl_xor_sync(0xffffffffu, v, o);
    return v;
}
__device__ __forceinline__ void mma8(float4& d, unsigned a0, unsigned a1, unsigned b0){
    asm volatile("mma.sync.aligned.m16n8k8.row.col.f32.f16.f16.f32 "
        "{%0,%1,%2,%3}, {%4,%5}, {%6}, {%7,%8,%9,%10};"
        : "=f"(d.x),"=f"(d.y),"=f"(d.z),"=f"(d.w)
        : "r"(a0),"r"(a1),"r"(b0),
          "f"(0.f),"f"(0.f),"f"(0.f),"f"(0.f));
}
__device__ __forceinline__ unsigned h2u(__half2 h){
    unsigned u; 
    asm("mov.b32 %0, %1;" : "=r"(u) : "r"(*reinterpret_cast<unsigned*>(&h)));
    return u;
}

// ---------------- 1. fused pre-stage: proj + all K/V + Q(l=0) -------------
__global__ void __launch_bounds__(96) k_pre(
    const float* __restrict__ xl, const float* __restrict__ xa,
    const float* __restrict__ xv, const float* __restrict__ Wl,
    const float* __restrict__ Wa, const float* __restrict__ Wv,
    const float* __restrict__ in_w, const float* __restrict__ in_b,
    const float* __restrict__ n1g, const float* __restrict__ n1b){
    int r = blockIdx.x;                  // 0..T*B-1
    int t = r / BB, b = r % BB;
    int w = threadIdx.x >> 5, lane = threadIdx.x & 31;
    __shared__ float sx[KL+KA+KV];
    __shared__ float xn[3][DD];
    __shared__ float axk[DD], axv[DD], axq[DD];
    for (int k=threadIdx.x; k<KL; k+=96) sx[k]        = xl[(b*TT+t)*KL + k];
    for (int k=threadIdx.x; k<KA; k+=96) sx[KL+k]     = xa[(b*TT+t)*KA + k];
    for (int k=threadIdx.x; k<KV; k+=96) sx[KL+KA+k]  = xv[(b*TT+t)*KV + k];
    __syncthreads();
    float pv = 0.f;
    {
        const float* W  = (w==0)? Wl : (w==1)? Wa : Wv;
        int K           = (w==0)? KL : (w==1)? KA : KV;
        const float* xs = sx + ((w==0)? 0 : (w==1)? KL : KL+KA);
        if (lane < DD){
            const float* wr = W + lane*K;
            for (int k=0;k<K;k++) pv = fmaf(xs[k], wr[k], pv);
            if (w==0){ int o=(t*BB+b)*DD+lane; g_h[0][o]=pv; g_h[1][o]=pv; }
        }
    }
    {
        float x = (lane<DD)? pv : 0.f;
        float sum = warpsum(x), sq = warpsum(x*x);
        float m = sum*(1.f/DD), var = sq*(1.f/DD)-m*m, rs = rsqrtf(var+1e-5f);
        if (lane<DD) xn[w][lane] = (x-m)*rs;
    }
    __syncthreads();
    #pragma unroll 1
    for (int sl=0; sl<6; sl++){
        int s_ = sl/LL, l_ = sl%LL;
        int ksrc = (s_==0)?1:2, vsrc = (s_==0)?2:1;
        int pb = sl*DD;
        if (lane<DD){
            float g = n1g[pb+lane], be = n1b[pb+lane];
            if (w==0) axk[lane] = xn[ksrc][lane]*g + be;
            else if (w==1) axv[lane] = xn[vsrc][lane]*g + be;
            else if (l_==0) axq[lane] = xn[0][lane]*g + be;
        }
        __syncthreads();
        if (lane<DD){
            const float* iw = in_w + sl*3*DD*DD;
            const float* ib = in_b + sl*3*DD;
            int i = b*HH + lane/HDD, e = lane%HDD;
            int o = (i*TT + t)*HDD + e;
            if (w==0){
                float acc = ib[DD+lane];
                const float* wr = iw + (DD+lane)*DD;
                #pragma unroll
                for (int j=0;j<DD;j++) acc = fmaf(axk[j], wr[j], acc);
                g_K[s_][l_][o] = acc;
            } else if (w==1){
                float acc = ib[2*DD+lane];
                const float* wr = iw + (2*DD+lane)*DD;
                #pragma unroll
                for (int j=0;j<DD;j++) acc = fmaf(axv[j], wr[j], acc);
                g_V[s_][l_][o] = acc;
            } else if (l_==0){
                float acc = ib[lane];
                const float* wr = iw + lane*DD;
                #pragma unroll
                for (int j=0;j<DD;j++) acc = fmaf(axq[j], wr[j], acc);
                g_Q[s_][o] = acc * 0.4082482904638631f;
            }
        }
        __syncthreads();
    }
}

// ---------------- 2. attention core: tensor-core (HMMA) scan --------------
// Block = (a-chunk, i, s). 160 threads = 5 warps, warp w owns b-rows [32w,32w+32).
// S_a = (K o q_a) V'^T via m16n8k8; running fp32 max over c in regs.
// Then batched softmax-over-b + attn dot (mini-GEMM) for the 30 a's.
__global__ void __launch_bounds__(160) k_att(int l){
    int s = blockIdx.z, i = blockIdx.y, ch = blockIdx.x;
    int tid = threadIdx.x;
    int lane = tid & 31, w = tid >> 5;
    int g = lane >> 2, qd = lane & 3;
    int e0 = qd*2;
    __shared__ __align__(16) __half sKh[160][8];
    __shared__ __align__(4)  __half sVt[8][152];
    __shared__ __align__(16) __half sQh[ACH][8];
    __shared__ __align__(16) float sQt[7][EPAD];
    __shared__ __align__(16) float sFused[ACH][EPAD];
    __shared__ float sP[5][8];
    __shared__ float sVbar[8];
    __shared__ float sMaxP[ACH][8];
    __shared__ float sBMax[ACH];
    __shared__ float sDot[ACH][8];
    const float* Kp = g_K[s][l] + i*TT*HDD;
    const float* Vp = g_V[s][l] + i*TT*HDD;
    const float* Qp = g_Q[s]    + i*TT*HDD;

    // ---- prologue: K rows (fp16, padded), V + vbar partials ----
    float vv[HDD];
    if (tid < 150){
        #pragma unroll
        for (int e=0;e<HDD;e++){
            sKh[tid][e] = __float2half_rn(Kp[tid*HDD+e]);
            vv[e] = Vp[tid*HDD+e];
        }
        sKh[tid][6] = __float2half_rn(0.f);
        sKh[tid][7] = __float2half_rn(0.f);
    } else {
        #pragma unroll
        for (int e=0;e<8;e++) sKh[tid][e] = __float2half_rn(0.f);
        #pragma unroll
        for (int e=0;e<HDD;e++) vv[e] = 0.f;
    }
    {
        float p[HDD];
        #pragma unroll
        for (int e=0;e<HDD;e++) p[e] = warpsum(vv[e]);
        if (lane==0){
            #pragma unroll
            for (int e=0;e<HDD;e++) sP[w][e] = p[e];
        }
    }
    // q^T (fp32) for final dot, ones row; padded cols 0
    for (int idx=tid; idx<7*152; idx+=160){
        int j = idx / 152, b = idx - j*152;
        float val = 0.f;
        if (b < 150) val = (j<6) ? Qp[b*HDD+j] : 1.f;
        sQt[j][b] = val;
    }
    // a-chunk q (fp16) for A scaling
    for (int idx=tid; idx<ACH*8; idx+=160){
        int a = idx >> 3, e = idx & 7;
        sQh[a][e] = (e<HDD) ? __float2half_rn(Qp[(ch*ACH+a)*HDD+e]) : __float2half_rn(0.f);
    }
    // pad fused cols 150,151 with -inf surrogate
    if (tid < ACH*2){
        int a = tid >> 1;
        sFused[a][150 + (tid&1)] = -1e30f;
    }
    __syncthreads();
    if (tid < HDD){
        float acc = 0.f;
        #pragma unroll
        for (int ww=0;ww<5;ww++) acc += sP[ww][tid];
        sVbar[tid] = acc * (1.f/TT);
    }
    __syncthreads();
    // V'^T fp16: sVt[e][c] = v_c[e] + vbar[e]
    if (tid < 150){
        #pragma unroll
        for (int e=0;e<HDD;e++) sVt[e][tid] = __float2half_rn(vv[e] + sVbar[e]);
        #pragma unroll
        for (int e=HDD;e<8;e++) sVt[e][tid] = __float2half_rn(0.f);
    } else if (tid < 152){
        #pragma unroll
        for (int e=0;e<8;e++) sVt[e][tid] = __float2half_rn(0.f);
    }
    __syncthreads();

    // ---- fragments (held in regs across the a-loop) ----
    int r0 = w*32 + g;                     // rows r0, r0+8, r0+16, r0+24
    __half2 kA0 = *(const __half2*)&sKh[r0][e0];
    __half2 kA1 = *(const __half2*)&sKh[r0+8][e0];
    __half2 kA2 = *(const __half2*)&sKh[r0+16][e0];
    __half2 kA3 = *(const __half2*)&sKh[r0+24][e0];
    unsigned bfu[19];
    #pragma unroll
    for (int j=0;j<19;j++){
        int c = j*8 + g;
        __half2 bb = __halves2half2(sVt[e0][c], sVt[e0+1][c]);
        bfu[j] = h2u(bb);
    }

    // ---- a loop: 30 GEMM+max ----
    #pragma unroll 1
    for (int a=0;a<ACH;a++){
        __half2 q2 = *(const __half2*)&sQh[a][e0];
        unsigned a0 = h2u(__hmul2(kA0, q2));
        unsigned a1 = h2u(__hmul2(kA1, q2));
        unsigned a2 = h2u(__hmul2(kA2, q2));
        unsigned a3 = h2u(__hmul2(kA3, q2));
        float rm0=-INFINITY, rm1=-INFINITY, rm2=-INFINITY, rm3=-INFINITY;
        #pragma unroll
        for (int j=0;j<19;j++){
            float4 d;
            mma8(d, a0, a1, bfu[j]);
            bool ok = (j<18) || (qd!=3);   // exclude padded c=150,151
            if (ok){ rm0 = fmaxf(rm0, fmaxf(d.x,d.y)); rm1 = fmaxf(rm1, fmaxf(d.z,d.w)); }
            mma8(d, a2, a3, bfu[j]);
            if (ok){ rm2 = fmaxf(rm2, fmaxf(d.x,d.y)); rm3 = fmaxf(rm3, fmaxf(d.z,d.w)); }
        }
        // quad reduce (full max over all 8 cols of each tile-row)
        #pragma unroll
        for (int o=1;o<=2;o<<=1){
            rm0 = fmaxf(rm0, __shfl_xor_sync(0xffffffffu, rm0, o));
            rm1 = fmaxf(rm1, __shfl_xor_sync(0xffffffffu, rm1, o));
            rm2 = fmaxf(rm2, __shfl_xor_sync(0xffffffffu, rm2, o));
            rm3 = fmaxf(rm3, __shfl_xor_sync(0xffffffffu, rm3, o));
        }
        // warp max over valid rows
        float wm = -INFINITY;
        if (r0      < 150) wm = rm0;
        if (r0 + 8  < 150) wm = fmaxf(wm, rm1);
        if (r0 + 16 < 150) wm = fmaxf(wm, rm2);
        if (r0 + 24 < 150) wm = fmaxf(wm, rm3);
        #pragma unroll
        for (int o=4;o<=16;o<<=1) wm = fmaxf(wm, __shfl_xor_sync(0xffffffffu, wm, o));
        if (lane==0) sMaxP[a][w] = wm;
        if (qd==0){
            if (r0      < 150) sFused[a][r0]      = rm0;
            if (r0 + 8  < 150) sFused[a][r0 + 8]  = rm1;
            if (r0 + 16 < 150) sFused[a][r0 + 16] = rm2;
            if (r0 + 24 < 150) sFused[a][r0 + 24] = rm3;
        }
    }
    __syncthreads();

    // ---- pass 2: batched softmax + dot ----
    if (tid < ACH){
        float mm = sMaxP[tid][0];
        #pragma unroll
        for (int ww=1;ww<5;ww++) mm = fmaxf(mm, sMaxP[tid][ww]);
        sBMax[tid] = mm;
    }
    __syncthreads();
    for (int idx=tid; idx<ACH*152; idx+=160){
        int a = idx / 152, b = idx - a*152;
        sFused[a][b] = __expf(sFused[a][b] - sBMax[a]);
    }
    __syncthreads();
    for (int idx=tid; idx<ACH*7; idx+=160){
        int a = idx / 7, j = idx % 7;
        const float4* ex4 = (const float4*)&sFused[a][0];
        const float4* q4  = (const float4*)&sQt[j][0];
        float acc = 0.f;
        #pragma unroll 5
        for (int b4=0;b4<38;b4++){
            float4 e4 = ex4[b4], qq = q4[b4];
            acc = fmaf(e4.x, qq.x, acc);
            acc = fmaf(e4.y, qq.y, acc);
            acc = fmaf(e4.z, qq.z, acc);
            acc = fmaf(e4.w, qq.w, acc);
        }
        sDot[a][j] = acc;
    }
    __syncthreads();
    int b_ = i/HH, h_ = i%HH;
    for (int idx=tid; idx<ACH*HDD; idx+=160){
        int a = idx / HDD, e = idx % HDD;
        g_attn[s][((ch*ACH+a)*BB + b_)*DD + h_*HDD + e] = sDot[a][e]/sDot[a][6];
    }
}

// ---------------- 3. ffn (+ next-layer Q; + head fused in block 149, l=2) -
__global__ void __launch_bounds__(512) k_ffnq(
                       const float* __restrict__ out_w, const float* __restrict__ out_b,
                       const float* __restrict__ w1, const float* __restrict__ b1,
                       const float* __restrict__ w2, const float* __restrict__ b2,
                       const float* __restrict__ n2g, const float* __restrict__ n2b,
                       const float* __restrict__ in_w, const float* __restrict__ in_b,
                       const float* __restrict__ n1g, const float* __restrict__ n1b,
                       const float* __restrict__ p1w, const float* __restrict__ p1b,
                       const float* __restrict__ p2w, const float* __restrict__ p2b,
                       const float* __restrict__ ow, const float* __restrict__ ob,
                       float* __restrict__ out, int l){
    int tid = threadIdx.x;
    int w = tid >> 5, lane = tid & 31;
    int gw = blockIdx.x*16 + w;           // row index, t-major
    int t = gw >> 4;
    int r16 = gw & 15;
    int s = r16 >> 3, b = r16 & 7;
    __shared__ float sA[16][DD], sXn[16][DD], sHid[16][4*DD];
    __shared__ float sLast[BB*2*DD];      // head scratch (block 149 only)
    __shared__ float sC[BB][2*DD];
    int ro = (t*BB+b)*DD;
    if (lane<DD) sA[w][lane] = g_attn[s][ro+lane];
    __syncwarp();
    int pl_ = s*LL+l;
    float x = 0.f;
    if (lane<DD){
        const float* wr = out_w + pl_*DD*DD + lane*DD;
        float acc = out_b[pl_*DD + lane];
        #pragma unroll
        for (int j=0;j<DD;j++) acc = fmaf(sA[w][j], wr[j], acc);
        x = g_h[s][ro+lane] + acc;        // residual
    }
    float sum = warpsum(x), sq = warpsum(x*x);
    float m = sum*(1.f/DD), var = sq*(1.f/DD)-m*m, rr = rsqrtf(var+1e-5f);
    if (lane<DD) sXn[w][lane] = (x-m)*rr*n2g[pl_*DD+lane] + n2b[pl_*DD+lane];
    __syncwarp();
    for (int j=lane; j<4*DD; j+=32){
        const float* wr = w1 + pl_*4*DD*DD + j*DD;
        float acc = b1[pl_*4*DD + j];
        #pragma unroll
        for (int q=0;q<DD;q++) acc = fmaf(sXn[w][q], wr[q], acc);
        sHid[w][j] = fmaxf(acc, 0.f);
    }
    __syncwarp();
    float hnew = 0.f;
    if (lane<DD){
        const float* wr = w2 + pl_*DD*4*DD + lane*4*DD;
        float acc = b2[pl_*DD + lane];
        #pragma unroll 4
        for (int j=0;j<4*DD;j++) acc = fmaf(sHid[w][j], wr[j], acc);
        hnew = x + acc;                   // residual 2
        g_h[s][ro+lane] = hnew;
    }
    if (l+1 < LL){
        float sum2 = warpsum(hnew), sq2 = warpsum(hnew*hnew);
        float m2 = sum2*(1.f/DD), var2 = sq2*(1.f/DD)-m2*m2, r2 = rsqrtf(var2+1e-5f);
        int pb = (pl_+1)*DD;
        if (lane<DD) sA[w][lane] = (hnew-m2)*r2*n1g[pb+lane] + n1b[pb+lane];
        __syncwarp();
        if (lane<DD){
            const float* iw = in_w + (pl_+1)*3*DD*DD + lane*DD;
            float acc = in_b[(pl_+1)*3*DD + lane];
            #pragma unroll
            for (int j=0;j<DD;j++) acc = fmaf(sA[w][j], iw[j], acc);
            acc *= 0.4082482904638631f;
            int i = b*HH + lane/HDD, e = lane%HDD;
            g_Q[s][(i*TT+t)*HDD+e] = acc;
        }
    } else if (blockIdx.x == 149){
        if (lane < DD){
            sLast[b*2*DD + s*DD + lane] = hnew;
            out[BB + b*2*DD + s*DD + lane] = hnew;   // last_hs output
        }
        __syncthreads();
        int bb = tid >> 6, j = tid & 63;
        if (j < 2*DD){
            float acc = p1b[j];
            const float* wr = p1w + j*2*DD;
            for (int q=0;q<2*DD;q++) acc = fmaf(sLast[bb*2*DD+q], wr[q], acc);
            sC[bb][j] = fmaxf(acc, 0.f);
        }
        __syncthreads();
        float a2 = 0.f;
        if (j < 2*DD){
            a2 = p2b[j];
            const float* wr = p2w + j*2*DD;
            for (int q=0;q<2*DD;q++) a2 = fmaf(sC[bb][q], wr[q], a2);
            a2 = (a2 + sLast[bb*2*DD+j]) * ow[j];
        }
        __syncthreads();
        if (j < 2*DD) sC[bb][j] = a2;
        __syncthreads();
        if (tid < BB){
            float a3 = ob[0];
            for (int q=0;q<2*DD;q++) a3 += sC[tid][q];
            out[tid] = a3;
        }
    }
}

// -------------------------------------------------------------------------
extern "C" void kernel_launch(void* const* d_in, const int* in_sizes, int n_in,
                              void* d_out, int out_size){
    const float* xl   = (const float*)d_in[0];
    const float* xa   = (const float*)d_in[1];
    const float* xv   = (const float*)d_in[2];
    const float* Wl   = (const float*)d_in[3];
    const float* Wa   = (const float*)d_in[4];
    const float* Wv   = (const float*)d_in[5];
    const float* in_w = (const float*)d_in[6];
    const float* in_b = (const float*)d_in[7];
    const float* outw = (const float*)d_in[8];
    const float* outb = (const float*)d_in[9];
    const float* l1w  = (const float*)d_in[10];
    const float* l1b  = (const float*)d_in[11];
    const float* l2w  = (const float*)d_in[12];
    const float* l2b  = (const float*)d_in[13];
    const float* n1g  = (const float*)d_in[14];
    const float* n1b  = (const float*)d_in[15];
    const float* n2g  = (const float*)d_in[16];
    const float* n2b  = (const float*)d_in[17];
    const float* p1w  = (const float*)d_in[18];
    const float* p1b  = (const float*)d_in[19];
    const float* p2w  = (const float*)d_in[20];
    const float* p2b  = (const float*)d_in[21];
    const float* ow   = (const float*)d_in[22];
    const float* ob   = (const float*)d_in[23];
    float* out = (float*)d_out;

    k_pre<<<TT*BB, 96>>>(xl, xa, xv, Wl, Wa, Wv, in_w, in_b, n1g, n1b);
    for (int l=0; l<LL; l++){
        k_att<<<dim3(NCH, NI, 2), 160>>>(l);
        k_ffnq<<<(2*TT*BB)/16, 512>>>(outw, outb, l1w, l1b, l2w, l2b, n2g, n2b,
                                      in_w, in_b, n1g, n1b,
                                      p1w, p1b, p2w, p2b, ow, ob, out, l);
    }
}

// round 12
// speedup vs baseline: 1.5242x; 1.0163x over previous
#include <cuda_runtime.h>
#include <cuda_fp16.h>
#include <math.h>

#define BB   8
#define TT   150
#define DD   30
#define HH   5
#define HDD  6
#define LL   3
#define NI   40     // BB*HH
#define KL   300
#define KA   74
#define KV   35
#define ACH  15     // a-values per attention block
#define NCH  10     // a-chunks (ACH*NCH = TT)
#define EPAD 164    // padded row length (bank-friendly float4)

// ---------------- device scratch (no allocations allowed) ----------------
__device__ float g_h[2][TT*BB*DD];            // per-stream hidden state [T,B,D]
__device__ float g_K[2][LL][NI*TT*HDD];       // per (s,l): [i, t, e]
__device__ float g_V[2][LL][NI*TT*HDD];
__device__ float g_Q[2][NI*TT*HDD];           // current-layer Q
__device__ float g_attn[2][TT*BB*DD];         // attention output [T,B,D]

__device__ __forceinline__ float warpsum(float v){
    #pragma unroll
    for (int o=16;o>0;o>>=1) v += __shfl_xor_sync(0xffffffffu, v, o);
    return v;
}
__device__ __forceinline__ void mma8(float4& d, unsigned a0, unsigned a1, unsigned b0){
    asm volatile("mma.sync.aligned.m16n8k8.row.col.f32.f16.f16.f32 "
        "{%0,%1,%2,%3}, {%4,%5}, {%6}, {%7,%8,%9,%10};"
        : "=f"(d.x),"=f"(d.y),"=f"(d.z),"=f"(d.w)
        : "r"(a0),"r"(a1),"r"(b0),
          "f"(0.f),"f"(0.f),"f"(0.f),"f"(0.f));
}
__device__ __forceinline__ unsigned h2u(__half2 h){
    unsigned u; 
    asm("mov.b32 %0, %1;" : "=r"(u) : "r"(*reinterpret_cast<unsigned*>(&h)));
    return u;
}

// ---------------- 1. fused pre-stage: proj + all K/V + Q(l=0) -------------
__global__ void __launch_bounds__(96) k_pre(
    const float* __restrict__ xl, const float* __restrict__ xa,
    const float* __restrict__ xv, const float* __restrict__ Wl,
    const float* __restrict__ Wa, const float* __restrict__ Wv,
    const float* __restrict__ in_w, const float* __restrict__ in_b,
    const float* __restrict__ n1g, const float* __restrict__ n1b){
    int r = blockIdx.x;                  // 0..T*B-1
    int t = r / BB, b = r % BB;
    int w = threadIdx.x >> 5, lane = threadIdx.x & 31;
    __shared__ float sx[KL+KA+KV];
    __shared__ float xn[3][DD];
    __shared__ float axk[DD], axv[DD], axq[DD];
    for (int k=threadIdx.x; k<KL; k+=96) sx[k]        = xl[(b*TT+t)*KL + k];
    for (int k=threadIdx.x; k<KA; k+=96) sx[KL+k]     = xa[(b*TT+t)*KA + k];
    for (int k=threadIdx.x; k<KV; k+=96) sx[KL+KA+k]  = xv[(b*TT+t)*KV + k];
    __syncthreads();
    float pv = 0.f;
    {
        const float* W  = (w==0)? Wl : (w==1)? Wa : Wv;
        int K           = (w==0)? KL : (w==1)? KA : KV;
        const float* xs = sx + ((w==0)? 0 : (w==1)? KL : KL+KA);
        if (lane < DD){
            const float* wr = W + lane*K;
            for (int k=0;k<K;k++) pv = fmaf(xs[k], wr[k], pv);
            if (w==0){ int o=(t*BB+b)*DD+lane; g_h[0][o]=pv; g_h[1][o]=pv; }
        }
    }
    {
        float x = (lane<DD)? pv : 0.f;
        float sum = warpsum(x), sq = warpsum(x*x);
        float m = sum*(1.f/DD), var = sq*(1.f/DD)-m*m, rs = rsqrtf(var+1e-5f);
        if (lane<DD) xn[w][lane] = (x-m)*rs;
    }
    __syncthreads();
    #pragma unroll 1
    for (int sl=0; sl<6; sl++){
        int s_ = sl/LL, l_ = sl%LL;
        int ksrc = (s_==0)?1:2, vsrc = (s_==0)?2:1;
        int pb = sl*DD;
        if (lane<DD){
            float g = n1g[pb+lane], be = n1b[pb+lane];
            if (w==0) axk[lane] = xn[ksrc][lane]*g + be;
            else if (w==1) axv[lane] = xn[vsrc][lane]*g + be;
            else if (l_==0) axq[lane] = xn[0][lane]*g + be;
        }
        __syncthreads();
        if (lane<DD){
            const float* iw = in_w + sl*3*DD*DD;
            const float* ib = in_b + sl*3*DD;
            int i = b*HH + lane/HDD, e = lane%HDD;
            int o = (i*TT + t)*HDD + e;
            if (w==0){
                float acc = ib[DD+lane];
                const float* wr = iw + (DD+lane)*DD;
                #pragma unroll
                for (int j=0;j<DD;j++) acc = fmaf(axk[j], wr[j], acc);
                g_K[s_][l_][o] = acc;
            } else if (w==1){
                float acc = ib[2*DD+lane];
                const float* wr = iw + (2*DD+lane)*DD;
                #pragma unroll
                for (int j=0;j<DD;j++) acc = fmaf(axv[j], wr[j], acc);
                g_V[s_][l_][o] = acc;
            } else if (l_==0){
                float acc = ib[lane];
                const float* wr = iw + lane*DD;
                #pragma unroll
                for (int j=0;j<DD;j++) acc = fmaf(axq[j], wr[j], acc);
                g_Q[s_][o] = acc * 0.4082482904638631f;
            }
        }
        __syncthreads();
    }
}

// ---------------- 2. attention core: tensor-core (HMMA) scan --------------
// Block = (a-chunk, i, s). 160 threads = 5 warps, warp w owns b-rows [32w,32w+32).
// S_a = (K o q_a) V'^T via m16n8k8; running fp32 max over c in regs.
// Then batched softmax-over-b + attn dot (mini-GEMM) for the ACH a's.
__global__ void __launch_bounds__(160) k_att(int l){
    int s = blockIdx.z, i = blockIdx.y, ch = blockIdx.x;
    int tid = threadIdx.x;
    int lane = tid & 31, w = tid >> 5;
    int g = lane >> 2, qd = lane & 3;
    int e0 = qd*2;
    __shared__ __align__(16) __half sKh[160][8];
    __shared__ __align__(4)  __half sVt[8][152];
    __shared__ __align__(16) __half sQh[ACH][8];
    __shared__ __align__(16) float sQt[7][EPAD];
    __shared__ __align__(16) float sFused[ACH][EPAD];
    __shared__ float sP[5][8];
    __shared__ float sVbar[8];
    __shared__ float sMaxP[ACH][8];
    __shared__ float sBMax[ACH];
    __shared__ float sDot[ACH][8];
    const float* Kp = g_K[s][l] + i*TT*HDD;
    const float* Vp = g_V[s][l] + i*TT*HDD;
    const float* Qp = g_Q[s]    + i*TT*HDD;

    // ---- prologue: K rows (fp16, padded), V + vbar partials ----
    float vv[HDD];
    if (tid < 150){
        #pragma unroll
        for (int e=0;e<HDD;e++){
            sKh[tid][e] = __float2half_rn(Kp[tid*HDD+e]);
            vv[e] = Vp[tid*HDD+e];
        }
        sKh[tid][6] = __float2half_rn(0.f);
        sKh[tid][7] = __float2half_rn(0.f);
    } else {
        #pragma unroll
        for (int e=0;e<8;e++) sKh[tid][e] = __float2half_rn(0.f);
        #pragma unroll
        for (int e=0;e<HDD;e++) vv[e] = 0.f;
    }
    {
        float p[HDD];
        #pragma unroll
        for (int e=0;e<HDD;e++) p[e] = warpsum(vv[e]);
        if (lane==0){
            #pragma unroll
            for (int e=0;e<HDD;e++) sP[w][e] = p[e];
        }
    }
    // q^T (fp32) for final dot, ones row; padded cols 0
    for (int idx=tid; idx<7*152; idx+=160){
        int j = idx / 152, b = idx - j*152;
        float val = 0.f;
        if (b < 150) val = (j<6) ? Qp[b*HDD+j] : 1.f;
        sQt[j][b] = val;
    }
    // a-chunk q (fp16) for A scaling
    for (int idx=tid; idx<ACH*8; idx+=160){
        int a = idx >> 3, e = idx & 7;
        sQh[a][e] = (e<HDD) ? __float2half_rn(Qp[(ch*ACH+a)*HDD+e]) : __float2half_rn(0.f);
    }
    // pad fused cols 150,151 with -inf surrogate
    if (tid < ACH*2){
        int a = tid >> 1;
        sFused[a][150 + (tid&1)] = -1e30f;
    }
    __syncthreads();
    if (tid < HDD){
        float acc = 0.f;
        #pragma unroll
        for (int ww=0;ww<5;ww++) acc += sP[ww][tid];
        sVbar[tid] = acc * (1.f/TT);
    }
    __syncthreads();
    // V'^T fp16: sVt[e][c] = v_c[e] + vbar[e]
    if (tid < 150){
        #pragma unroll
        for (int e=0;e<HDD;e++) sVt[e][tid] = __float2half_rn(vv[e] + sVbar[e]);
        #pragma unroll
        for (int e=HDD;e<8;e++) sVt[e][tid] = __float2half_rn(0.f);
    } else if (tid < 152){
        #pragma unroll
        for (int e=0;e<8;e++) sVt[e][tid] = __float2half_rn(0.f);
    }
    __syncthreads();

    // ---- fragments (held in regs across the a-loop) ----
    int r0 = w*32 + g;                     // rows r0, r0+8, r0+16, r0+24
    __half2 kA0 = *(const __half2*)&sKh[r0][e0];
    __half2 kA1 = *(const __half2*)&sKh[r0+8][e0];
    __half2 kA2 = *(const __half2*)&sKh[r0+16][e0];
    __half2 kA3 = *(const __half2*)&sKh[r0+24][e0];
    unsigned bfu[19];
    #pragma unroll
    for (int j=0;j<19;j++){
        int c = j*8 + g;
        __half2 bb = __halves2half2(sVt[e0][c], sVt[e0+1][c]);
        bfu[j] = h2u(bb);
    }

    // ---- a loop: ACH GEMM+max ----
    #pragma unroll 1
    for (int a=0;a<ACH;a++){
        __half2 q2 = *(const __half2*)&sQh[a][e0];
        unsigned a0 = h2u(__hmul2(kA0, q2));
        unsigned a1 = h2u(__hmul2(kA1, q2));
        unsigned a2 = h2u(__hmul2(kA2, q2));
        unsigned a3 = h2u(__hmul2(kA3, q2));
        float rm0=-INFINITY, rm1=-INFINITY, rm2=-INFINITY, rm3=-INFINITY;
        #pragma unroll
        for (int j=0;j<19;j++){
            float4 d;
            mma8(d, a0, a1, bfu[j]);
            bool ok = (j<18) || (qd!=3);   // exclude padded c=150,151
            if (ok){ rm0 = fmaxf(rm0, fmaxf(d.x,d.y)); rm1 = fmaxf(rm1, fmaxf(d.z,d.w)); }
            mma8(d, a2, a3, bfu[j]);
            if (ok){ rm2 = fmaxf(rm2, fmaxf(d.x,d.y)); rm3 = fmaxf(rm3, fmaxf(d.z,d.w)); }
        }
        // quad reduce (full max over all 8 cols of each tile-row)
        #pragma unroll
        for (int o=1;o<=2;o<<=1){
            rm0 = fmaxf(rm0, __shfl_xor_sync(0xffffffffu, rm0, o));
            rm1 = fmaxf(rm1, __shfl_xor_sync(0xffffffffu, rm1, o));
            rm2 = fmaxf(rm2, __shfl_xor_sync(0xffffffffu, rm2, o));
            rm3 = fmaxf(rm3, __shfl_xor_sync(0xffffffffu, rm3, o));
        }
        // warp max over valid rows
        float wm = -INFINITY;
        if (r0      < 150) wm = rm0;
        if (r0 + 8  < 150) wm = fmaxf(wm, rm1);
        if (r0 + 16 < 150) wm = fmaxf(wm, rm2);
        if (r0 + 24 < 150) wm = fmaxf(wm, rm3);
        #pragma unroll
        for (int o=4;o<=16;o<<=1) wm = fmaxf(wm, __shfl_xor_sync(0xffffffffu, wm, o));
        if (lane==0) sMaxP[a][w] = wm;
        if (qd==0){
            if (r0      < 150) sFused[a][r0]      = rm0;
            if (r0 + 8  < 150) sFused[a][r0 + 8]  = rm1;
            if (r0 + 16 < 150) sFused[a][r0 + 16] = rm2;
            if (r0 + 24 < 150) sFused[a][r0 + 24] = rm3;
        }
    }
    __syncthreads();

    // ---- pass 2: batched softmax + dot ----
    if (tid < ACH){
        float mm = sMaxP[tid][0];
        #pragma unroll
        for (int ww=1;ww<5;ww++) mm = fmaxf(mm, sMaxP[tid][ww]);
        sBMax[tid] = mm;
    }
    __syncthreads();
    for (int idx=tid; idx<ACH*152; idx+=160){
        int a = idx / 152, b = idx - a*152;
        sFused[a][b] = __expf(sFused[a][b] - sBMax[a]);
    }
    __syncthreads();
    for (int idx=tid; idx<ACH*7; idx+=160){
        int a = idx / 7, j = idx % 7;
        const float4* ex4 = (const float4*)&sFused[a][0];
        const float4* q4  = (const float4*)&sQt[j][0];
        float acc = 0.f;
        #pragma unroll 5
        for (int b4=0;b4<38;b4++){
            float4 e4 = ex4[b4], qq = q4[b4];
            acc = fmaf(e4.x, qq.x, acc);
            acc = fmaf(e4.y, qq.y, acc);
            acc = fmaf(e4.z, qq.z, acc);
            acc = fmaf(e4.w, qq.w, acc);
        }
        sDot[a][j] = acc;
    }
    __syncthreads();
    int b_ = i/HH, h_ = i%HH;
    for (int idx=tid; idx<ACH*HDD; idx+=160){
        int a = idx / HDD, e = idx % HDD;
        g_attn[s][((ch*ACH+a)*BB + b_)*DD + h_*HDD + e] = sDot[a][e]/sDot[a][6];
    }
}

// ---------------- 3. ffn (+ next-layer Q; + head fused in block 149, l=2) -
__global__ void __launch_bounds__(512) k_ffnq(
                       const float* __restrict__ out_w, const float* __restrict__ out_b,
                       const float* __restrict__ w1, const float* __restrict__ b1,
                       const float* __restrict__ w2, const float* __restrict__ b2,
                       const float* __restrict__ n2g, const float* __restrict__ n2b,
                       const float* __restrict__ in_w, const float* __restrict__ in_b,
                       const float* __restrict__ n1g, const float* __restrict__ n1b,
                       const float* __restrict__ p1w, const float* __restrict__ p1b,
                       const float* __restrict__ p2w, const float* __restrict__ p2b,
                       const float* __restrict__ ow, const float* __restrict__ ob,
                       float* __restrict__ out, int l){
    int tid = threadIdx.x;
    int w = tid >> 5, lane = tid & 31;
    int gw = blockIdx.x*16 + w;           // row index, t-major
    int t = gw >> 4;
    int r16 = gw & 15;
    int s = r16 >> 3, b = r16 & 7;
    __shared__ float sA[16][DD], sXn[16][DD], sHid[16][4*DD];
    __shared__ float sLast[BB*2*DD];      // head scratch (block 149 only)
    __shared__ float sC[BB][2*DD];
    int ro = (t*BB+b)*DD;
    if (lane<DD) sA[w][lane] = g_attn[s][ro+lane];
    __syncwarp();
    int pl_ = s*LL+l;
    float x = 0.f;
    if (lane<DD){
        const float* wr = out_w + pl_*DD*DD + lane*DD;
        float acc = out_b[pl_*DD + lane];
        #pragma unroll
        for (int j=0;j<DD;j++) acc = fmaf(sA[w][j], wr[j], acc);
        x = g_h[s][ro+lane] + acc;        // residual
    }
    float sum = warpsum(x), sq = warpsum(x*x);
    float m = sum*(1.f/DD), var = sq*(1.f/DD)-m*m, rr = rsqrtf(var+1e-5f);
    if (lane<DD) sXn[w][lane] = (x-m)*rr*n2g[pl_*DD+lane] + n2b[pl_*DD+lane];
    __syncwarp();
    for (int j=lane; j<4*DD; j+=32){
        const float* wr = w1 + pl_*4*DD*DD + j*DD;
        float acc = b1[pl_*4*DD + j];
        #pragma unroll
        for (int q=0;q<DD;q++) acc = fmaf(sXn[w][q], wr[q], acc);
        sHid[w][j] = fmaxf(acc, 0.f);
    }
    __syncwarp();
    float hnew = 0.f;
    if (lane<DD){
        const float* wr = w2 + pl_*DD*4*DD + lane*4*DD;
        float acc = b2[pl_*DD + lane];
        #pragma unroll 4
        for (int j=0;j<4*DD;j++) acc = fmaf(sHid[w][j], wr[j], acc);
        hnew = x + acc;                   // residual 2
        g_h[s][ro+lane] = hnew;
    }
    if (l+1 < LL){
        float sum2 = warpsum(hnew), sq2 = warpsum(hnew*hnew);
        float m2 = sum2*(1.f/DD), var2 = sq2*(1.f/DD)-m2*m2, r2 = rsqrtf(var2+1e-5f);
        int pb = (pl_+1)*DD;
        if (lane<DD) sA[w][lane] = (hnew-m2)*r2*n1g[pb+lane] + n1b[pb+lane];
        __syncwarp();
        if (lane<DD){
            const float* iw = in_w + (pl_+1)*3*DD*DD + lane*DD;
            float acc = in_b[(pl_+1)*3*DD + lane];
            #pragma unroll
            for (int j=0;j<DD;j++) acc = fmaf(sA[w][j], iw[j], acc);
            acc *= 0.4082482904638631f;
            int i = b*HH + lane/HDD, e = lane%HDD;
            g_Q[s][(i*TT+t)*HDD+e] = acc;
        }
    } else if (blockIdx.x == 149){
        if (lane < DD){
            sLast[b*2*DD + s*DD + lane] = hnew;
            out[BB + b*2*DD + s*DD + lane] = hnew;   // last_hs output
        }
        __syncthreads();
        int bb = tid >> 6, j = tid & 63;
        if (j < 2*DD){
            float acc = p1b[j];
            const float* wr = p1w + j*2*DD;
            for (int q=0;q<2*DD;q++) acc = fmaf(sLast[bb*2*DD+q], wr[q], acc);
            sC[bb][j] = fmaxf(acc, 0.f);
        }
        __syncthreads();
        float a2 = 0.f;
        if (j < 2*DD){
            a2 = p2b[j];
            const float* wr = p2w + j*2*DD;
            for (int q=0;q<2*DD;q++) a2 = fmaf(sC[bb][q], wr[q], a2);
            a2 = (a2 + sLast[bb*2*DD+j]) * ow[j];
        }
        __syncthreads();
        if (j < 2*DD) sC[bb][j] = a2;
        __syncthreads();
        if (tid < BB){
            float a3 = ob[0];
            for (int q=0;q<2*DD;q++) a3 += sC[tid][q];
            out[tid] = a3;
        }
    }
}

// -------------------------------------------------------------------------
extern "C" void kernel_launch(void* const* d_in, const int* in_sizes, int n_in,
                              void* d_out, int out_size){
    const float* xl   = (const float*)d_in[0];
    const float* xa   = (const float*)d_in[1];
    const float* xv   = (const float*)d_in[2];
    const float* Wl   = (const float*)d_in[3];
    const float* Wa   = (const float*)d_in[4];
    const float* Wv   = (const float*)d_in[5];
    const float* in_w = (const float*)d_in[6];
    const float* in_b = (const float*)d_in[7];
    const float* outw = (const float*)d_in[8];
    const float* outb = (const float*)d_in[9];
    const float* l1w  = (const float*)d_in[10];
    const float* l1b  = (const float*)d_in[11];
    const float* l2w  = (const float*)d_in[12];
    const float* l2b  = (const float*)d_in[13];
    const float* n1g  = (const float*)d_in[14];
    const float* n1b  = (const float*)d_in[15];
    const float* n2g  = (const float*)d_in[16];
    const float* n2b  = (const float*)d_in[17];
    const float* p1w  = (const float*)d_in[18];
    const float* p1b  = (const float*)d_in[19];
    const float* p2w  = (const float*)d_in[20];
    const float* p2b  = (const float*)d_in[21];
    const float* ow   = (const float*)d_in[22];
    const float* ob   = (const float*)d_in[23];
    float* out = (float*)d_out;

    k_pre<<<TT*BB, 96>>>(xl, xa, xv, Wl, Wa, Wv, in_w, in_b, n1g, n1b);
    for (int l=0; l<LL; l++){
        k_att<<<dim3(NCH, NI, 2), 160>>>(l);
        k_ffnq<<<(2*TT*BB)/16, 512>>>(outw, outb, l1w, l1b, l2w, l2b, n2g, n2b,
                                      in_w, in_b, n1g, n1b,
                                      p1w, p1b, p2w, p2b, ow, ob, out, l);
    }
}

// round 13
// speedup vs baseline: 1.7672x; 1.1595x over previous
#include <cuda_runtime.h>
#include <cuda_fp16.h>
#include <math.h>

#define BB   8
#define TT   150
#define DD   30
#define HH   5
#define HDD  6
#define LL   3
#define NI   40     // BB*HH
#define KL   300
#define KA   74
#define KV   35
#define ACH  15     // a-values per attention block
#define NCH  10     // a-chunks (ACH*NCH = TT)
#define EPAD 164    // padded row length (bank-friendly float4)

// dynamic smem layout for k_ffnq (floats)
#define W1T_OFF 0          // [2][30][128]  w1^T : (s,q,j)
#define W2T_OFF 7680       // [2][120][32]  w2^T : (s,j,d)
#define OWT_OFF 15360      // [2][30][32]   out_w^T : (s,j,o)
#define IWT_OFF 17280      // [2][30][32]   in_w(q)^T : (s,j,d)
#define DYN_FLOATS 19200   // 76.8 KB

// ---------------- device scratch (no allocations allowed) ----------------
__device__ float g_h[2][TT*BB*DD];            // per-stream hidden state [T,B,D]
__device__ float g_K[2][LL][NI*TT*HDD];       // per (s,l): [i, t, e]
__device__ float g_V[2][LL][NI*TT*HDD];
__device__ float g_Q[2][NI*TT*HDD];           // current-layer Q
__device__ float g_attn[2][TT*BB*DD];         // attention output [T,B,D]

__device__ __forceinline__ float warpsum(float v){
    #pragma unroll
    for (int o=16;o>0;o>>=1) v += __shfl_xor_sync(0xffffffffu, v, o);
    return v;
}
__device__ __forceinline__ void mma8(float4& d, unsigned a0, unsigned a1, unsigned b0){
    asm volatile("mma.sync.aligned.m16n8k8.row.col.f32.f16.f16.f32 "
        "{%0,%1,%2,%3}, {%4,%5}, {%6}, {%7,%8,%9,%10};"
        : "=f"(d.x),"=f"(d.y),"=f"(d.z),"=f"(d.w)
        : "r"(a0),"r"(a1),"r"(b0),
          "f"(0.f),"f"(0.f),"f"(0.f),"f"(0.f));
}
__device__ __forceinline__ unsigned h2u(__half2 h){
    unsigned u; 
    asm("mov.b32 %0, %1;" : "=r"(u) : "r"(*reinterpret_cast<unsigned*>(&h)));
    return u;
}

// ---------------- 1. fused pre-stage: proj + all K/V + Q(l=0) -------------
__global__ void __launch_bounds__(96) k_pre(
    const float* __restrict__ xl, const float* __restrict__ xa,
    const float* __restrict__ xv, const float* __restrict__ Wl,
    const float* __restrict__ Wa, const float* __restrict__ Wv,
    const float* __restrict__ in_w, const float* __restrict__ in_b,
    const float* __restrict__ n1g, const float* __restrict__ n1b){
    int r = blockIdx.x;                  // 0..T*B-1
    int t = r / BB, b = r % BB;
    int w = threadIdx.x >> 5, lane = threadIdx.x & 31;
    __shared__ float sx[KL+KA+KV];
    __shared__ float xn[3][DD];
    __shared__ float axk[DD], axv[DD], axq[DD];
    for (int k=threadIdx.x; k<KL; k+=96) sx[k]        = xl[(b*TT+t)*KL + k];
    for (int k=threadIdx.x; k<KA; k+=96) sx[KL+k]     = xa[(b*TT+t)*KA + k];
    for (int k=threadIdx.x; k<KV; k+=96) sx[KL+KA+k]  = xv[(b*TT+t)*KV + k];
    __syncthreads();
    float pv = 0.f;
    {
        const float* W  = (w==0)? Wl : (w==1)? Wa : Wv;
        int K           = (w==0)? KL : (w==1)? KA : KV;
        const float* xs = sx + ((w==0)? 0 : (w==1)? KL : KL+KA);
        if (lane < DD){
            const float* wr = W + lane*K;
            for (int k=0;k<K;k++) pv = fmaf(xs[k], wr[k], pv);
            if (w==0){ int o=(t*BB+b)*DD+lane; g_h[0][o]=pv; g_h[1][o]=pv; }
        }
    }
    {
        float x = (lane<DD)? pv : 0.f;
        float sum = warpsum(x), sq = warpsum(x*x);
        float m = sum*(1.f/DD), var = sq*(1.f/DD)-m*m, rs = rsqrtf(var+1e-5f);
        if (lane<DD) xn[w][lane] = (x-m)*rs;
    }
    __syncthreads();
    #pragma unroll 1
    for (int sl=0; sl<6; sl++){
        int s_ = sl/LL, l_ = sl%LL;
        int ksrc = (s_==0)?1:2, vsrc = (s_==0)?2:1;
        int pb = sl*DD;
        if (lane<DD){
            float g = n1g[pb+lane], be = n1b[pb+lane];
            if (w==0) axk[lane] = xn[ksrc][lane]*g + be;
            else if (w==1) axv[lane] = xn[vsrc][lane]*g + be;
            else if (l_==0) axq[lane] = xn[0][lane]*g + be;
        }
        __syncthreads();
        if (lane<DD){
            const float* iw = in_w + sl*3*DD*DD;
            const float* ib = in_b + sl*3*DD;
            int i = b*HH + lane/HDD, e = lane%HDD;
            int o = (i*TT + t)*HDD + e;
            if (w==0){
                float acc = ib[DD+lane];
                const float* wr = iw + (DD+lane)*DD;
                #pragma unroll
                for (int j=0;j<DD;j++) acc = fmaf(axk[j], wr[j], acc);
                g_K[s_][l_][o] = acc;
            } else if (w==1){
                float acc = ib[2*DD+lane];
                const float* wr = iw + (2*DD+lane)*DD;
                #pragma unroll
                for (int j=0;j<DD;j++) acc = fmaf(axv[j], wr[j], acc);
                g_V[s_][l_][o] = acc;
            } else if (l_==0){
                float acc = ib[lane];
                const float* wr = iw + lane*DD;
                #pragma unroll
                for (int j=0;j<DD;j++) acc = fmaf(axq[j], wr[j], acc);
                g_Q[s_][o] = acc * 0.4082482904638631f;
            }
        }
        __syncthreads();
    }
}

// ---------------- 2. attention core: tensor-core (HMMA) scan --------------
__global__ void __launch_bounds__(160) k_att(int l){
    int s = blockIdx.z, i = blockIdx.y, ch = blockIdx.x;
    int tid = threadIdx.x;
    int lane = tid & 31, w = tid >> 5;
    int g = lane >> 2, qd = lane & 3;
    int e0 = qd*2;
    __shared__ __align__(16) __half sKh[160][8];
    __shared__ __align__(4)  __half sVt[8][152];
    __shared__ __align__(16) __half sQh[ACH][8];
    __shared__ __align__(16) float sQt[7][EPAD];
    __shared__ __align__(16) float sFused[ACH][EPAD];
    __shared__ float sP[5][8];
    __shared__ float sVbar[8];
    __shared__ float sMaxP[ACH][8];
    __shared__ float sBMax[ACH];
    __shared__ float sDot[ACH][8];
    const float* Kp = g_K[s][l] + i*TT*HDD;
    const float* Vp = g_V[s][l] + i*TT*HDD;
    const float* Qp = g_Q[s]    + i*TT*HDD;

    float vv[HDD];
    if (tid < 150){
        #pragma unroll
        for (int e=0;e<HDD;e++){
            sKh[tid][e] = __float2half_rn(Kp[tid*HDD+e]);
            vv[e] = Vp[tid*HDD+e];
        }
        sKh[tid][6] = __float2half_rn(0.f);
        sKh[tid][7] = __float2half_rn(0.f);
    } else {
        #pragma unroll
        for (int e=0;e<8;e++) sKh[tid][e] = __float2half_rn(0.f);
        #pragma unroll
        for (int e=0;e<HDD;e++) vv[e] = 0.f;
    }
    {
        float p[HDD];
        #pragma unroll
        for (int e=0;e<HDD;e++) p[e] = warpsum(vv[e]);
        if (lane==0){
            #pragma unroll
            for (int e=0;e<HDD;e++) sP[w][e] = p[e];
        }
    }
    for (int idx=tid; idx<7*152; idx+=160){
        int j = idx / 152, b = idx - j*152;
        float val = 0.f;
        if (b < 150) val = (j<6) ? Qp[b*HDD+j] : 1.f;
        sQt[j][b] = val;
    }
    for (int idx=tid; idx<ACH*8; idx+=160){
        int a = idx >> 3, e = idx & 7;
        sQh[a][e] = (e<HDD) ? __float2half_rn(Qp[(ch*ACH+a)*HDD+e]) : __float2half_rn(0.f);
    }
    if (tid < ACH*2){
        int a = tid >> 1;
        sFused[a][150 + (tid&1)] = -1e30f;
    }
    __syncthreads();
    if (tid < HDD){
        float acc = 0.f;
        #pragma unroll
        for (int ww=0;ww<5;ww++) acc += sP[ww][tid];
        sVbar[tid] = acc * (1.f/TT);
    }
    __syncthreads();
    if (tid < 150){
        #pragma unroll
        for (int e=0;e<HDD;e++) sVt[e][tid] = __float2half_rn(vv[e] + sVbar[e]);
        #pragma unroll
        for (int e=HDD;e<8;e++) sVt[e][tid] = __float2half_rn(0.f);
    } else if (tid < 152){
        #pragma unroll
        for (int e=0;e<8;e++) sVt[e][tid] = __float2half_rn(0.f);
    }
    __syncthreads();

    int r0 = w*32 + g;                     // rows r0, r0+8, r0+16, r0+24
    __half2 kA0 = *(const __half2*)&sKh[r0][e0];
    __half2 kA1 = *(const __half2*)&sKh[r0+8][e0];
    __half2 kA2 = *(const __half2*)&sKh[r0+16][e0];
    __half2 kA3 = *(const __half2*)&sKh[r0+24][e0];
    unsigned bfu[19];
    #pragma unroll
    for (int j=0;j<19;j++){
        int c = j*8 + g;
        __half2 bb = __halves2half2(sVt[e0][c], sVt[e0+1][c]);
        bfu[j] = h2u(bb);
    }

    #pragma unroll 1
    for (int a=0;a<ACH;a++){
        __half2 q2 = *(const __half2*)&sQh[a][e0];
        unsigned a0 = h2u(__hmul2(kA0, q2));
        unsigned a1 = h2u(__hmul2(kA1, q2));
        unsigned a2 = h2u(__hmul2(kA2, q2));
        unsigned a3 = h2u(__hmul2(kA3, q2));
        float rm0=-INFINITY, rm1=-INFINITY, rm2=-INFINITY, rm3=-INFINITY;
        #pragma unroll
        for (int j=0;j<19;j++){
            float4 d;
            mma8(d, a0, a1, bfu[j]);
            bool ok = (j<18) || (qd!=3);   // exclude padded c=150,151
            if (ok){ rm0 = fmaxf(rm0, fmaxf(d.x,d.y)); rm1 = fmaxf(rm1, fmaxf(d.z,d.w)); }
            mma8(d, a2, a3, bfu[j]);
            if (ok){ rm2 = fmaxf(rm2, fmaxf(d.x,d.y)); rm3 = fmaxf(rm3, fmaxf(d.z,d.w)); }
        }
        #pragma unroll
        for (int o=1;o<=2;o<<=1){
            rm0 = fmaxf(rm0, __shfl_xor_sync(0xffffffffu, rm0, o));
            rm1 = fmaxf(rm1, __shfl_xor_sync(0xffffffffu, rm1, o));
            rm2 = fmaxf(rm2, __shfl_xor_sync(0xffffffffu, rm2, o));
            rm3 = fmaxf(rm3, __shfl_xor_sync(0xffffffffu, rm3, o));
        }
        float wm = -INFINITY;
        if (r0      < 150) wm = rm0;
        if (r0 + 8  < 150) wm = fmaxf(wm, rm1);
        if (r0 + 16 < 150) wm = fmaxf(wm, rm2);
        if (r0 + 24 < 150) wm = fmaxf(wm, rm3);
        #pragma unroll
        for (int o=4;o<=16;o<<=1) wm = fmaxf(wm, __shfl_xor_sync(0xffffffffu, wm, o));
        if (lane==0) sMaxP[a][w] = wm;
        if (qd==0){
            if (r0      < 150) sFused[a][r0]      = rm0;
            if (r0 + 8  < 150) sFused[a][r0 + 8]  = rm1;
            if (r0 + 16 < 150) sFused[a][r0 + 16] = rm2;
            if (r0 + 24 < 150) sFused[a][r0 + 24] = rm3;
        }
    }
    __syncthreads();

    if (tid < ACH){
        float mm = sMaxP[tid][0];
        #pragma unroll
        for (int ww=1;ww<5;ww++) mm = fmaxf(mm, sMaxP[tid][ww]);
        sBMax[tid] = mm;
    }
    __syncthreads();
    for (int idx=tid; idx<ACH*152; idx+=160){
        int a = idx / 152, b = idx - a*152;
        sFused[a][b] = __expf(sFused[a][b] - sBMax[a]);
    }
    __syncthreads();
    for (int idx=tid; idx<ACH*7; idx+=160){
        int a = idx / 7, j = idx % 7;
        const float4* ex4 = (const float4*)&sFused[a][0];
        const float4* q4  = (const float4*)&sQt[j][0];
        float acc = 0.f;
        #pragma unroll 5
        for (int b4=0;b4<38;b4++){
            float4 e4 = ex4[b4], qq = q4[b4];
            acc = fmaf(e4.x, qq.x, acc);
            acc = fmaf(e4.y, qq.y, acc);
            acc = fmaf(e4.z, qq.z, acc);
            acc = fmaf(e4.w, qq.w, acc);
        }
        sDot[a][j] = acc;
    }
    __syncthreads();
    int b_ = i/HH, h_ = i%HH;
    for (int idx=tid; idx<ACH*HDD; idx+=160){
        int a = idx / HDD, e = idx % HDD;
        g_attn[s][((ch*ACH+a)*BB + b_)*DD + h_*HDD + e] = sDot[a][e]/sDot[a][6];
    }
}

// ---------------- 3. ffn (+ next-layer Q; + head fused in block 149, l=2) -
// 512 threads = 16 warps = 16 rows; row = t*16 + s*8 + b  (t-major).
// Weights staged to smem TRANSPOSED so compute LDS is coalesced/conflict-free.
__global__ void __launch_bounds__(512) k_ffnq(
                       const float* __restrict__ out_w, const float* __restrict__ out_b,
                       const float* __restrict__ w1, const float* __restrict__ b1,
                       const float* __restrict__ w2, const float* __restrict__ b2,
                       const float* __restrict__ n2g, const float* __restrict__ n2b,
                       const float* __restrict__ in_w, const float* __restrict__ in_b,
                       const float* __restrict__ n1g, const float* __restrict__ n1b,
                       const float* __restrict__ p1w, const float* __restrict__ p1b,
                       const float* __restrict__ p2w, const float* __restrict__ p2b,
                       const float* __restrict__ ow, const float* __restrict__ ob,
                       float* __restrict__ out, int l){
    extern __shared__ float dyn[];
    int tid = threadIdx.x;
    int w = tid >> 5, lane = tid & 31;
    int gw = blockIdx.x*16 + w;           // row index, t-major
    int t = gw >> 4;
    int r16 = gw & 15;
    int s = r16 >> 3, b = r16 & 7;
    __shared__ float sA[16][DD], sXn[16][DD], sHid[16][4*DD];
    __shared__ float sLast[BB*2*DD];      // head scratch (block 149 only)
    __shared__ float sC[BB][2*DD];

    // ---- stage weights (both streams) transposed into smem, coalesced ----
    #pragma unroll 1
    for (int s2=0; s2<2; s2++){
        int pl2 = s2*LL + l;
        const float* gw1 = w1 + pl2*4*DD*DD;        // [120][30]
        for (int g2=tid; g2<4*DD*DD; g2+=512){
            int j = g2 / DD, q = g2 - j*DD;
            dyn[W1T_OFF + s2*3840 + q*128 + j] = gw1[g2];
        }
        const float* gw2 = w2 + pl2*DD*4*DD;        // [30][120]
        for (int g2=tid; g2<4*DD*DD; g2+=512){
            int d = g2 / (4*DD), j = g2 - d*4*DD;
            dyn[W2T_OFF + s2*3840 + j*32 + d] = gw2[g2];
        }
        const float* go = out_w + pl2*DD*DD;        // [30][30]
        for (int g2=tid; g2<DD*DD; g2+=512){
            int o = g2 / DD, j = g2 - o*DD;
            dyn[OWT_OFF + s2*960 + j*32 + o] = go[g2];
        }
        if (l+1 < LL){
            const float* gi = in_w + (pl2+1)*3*DD*DD;   // q rows [30][30]
            for (int g2=tid; g2<DD*DD; g2+=512){
                int d = g2 / DD, j = g2 - d*DD;
                dyn[IWT_OFF + s2*960 + j*32 + d] = gi[g2];
            }
        }
    }
    int ro = (t*BB+b)*DD;
    if (lane<DD) sA[w][lane] = g_attn[s][ro+lane];
    __syncthreads();

    int pl_ = s*LL+l;
    const float* W1t = dyn + W1T_OFF + s*3840;
    const float* W2t = dyn + W2T_OFF + s*3840;
    const float* OWt = dyn + OWT_OFF + s*960;
    const float* IWt = dyn + IWT_OFF + s*960;

    float x = 0.f;
    if (lane<DD){
        float acc = out_b[pl_*DD + lane];
        #pragma unroll
        for (int j=0;j<DD;j++) acc = fmaf(sA[w][j], OWt[j*32+lane], acc);
        x = g_h[s][ro+lane] + acc;        // residual
    }
    float sum = warpsum(x), sq = warpsum(x*x);
    float m = sum*(1.f/DD), var = sq*(1.f/DD)-m*m, rr = rsqrtf(var+1e-5f);
    if (lane<DD) sXn[w][lane] = (x-m)*rr*n2g[pl_*DD+lane] + n2b[pl_*DD+lane];
    __syncwarp();
    #pragma unroll
    for (int mo=0; mo<4; mo++){
        int j = mo*32 + lane;
        if (j < 4*DD){
            float acc = b1[pl_*4*DD + j];
            #pragma unroll
            for (int q=0;q<DD;q++) acc = fmaf(sXn[w][q], W1t[q*128+j], acc);
            sHid[w][j] = fmaxf(acc, 0.f);
        }
    }
    __syncwarp();
    float hnew = 0.f;
    if (lane<DD){
        float acc = b2[pl_*DD + lane];
        #pragma unroll 4
        for (int j=0;j<4*DD;j++) acc = fmaf(sHid[w][j], W2t[j*32+lane], acc);
        hnew = x + acc;                   // residual 2
        g_h[s][ro+lane] = hnew;
    }
    if (l+1 < LL){
        float sum2 = warpsum(hnew), sq2 = warpsum(hnew*hnew);
        float m2 = sum2*(1.f/DD), var2 = sq2*(1.f/DD)-m2*m2, r2 = rsqrtf(var2+1e-5f);
        int pb = (pl_+1)*DD;
        if (lane<DD) sA[w][lane] = (hnew-m2)*r2*n1g[pb+lane] + n1b[pb+lane];
        __syncwarp();
        if (lane<DD){
            float acc = in_b[(pl_+1)*3*DD + lane];
            #pragma unroll
            for (int j=0;j<DD;j++) acc = fmaf(sA[w][j], IWt[j*32+lane], acc);
            acc *= 0.4082482904638631f;
            int i = b*HH + lane/HDD, e = lane%HDD;
            g_Q[s][(i*TT+t)*HDD+e] = acc;
        }
    } else if (blockIdx.x == 149){
        if (lane < DD){
            sLast[b*2*DD + s*DD + lane] = hnew;
            out[BB + b*2*DD + s*DD + lane] = hnew;   // last_hs output
        }
        __syncthreads();
        int bb = tid >> 6, j = tid & 63;
        if (j < 2*DD){
            float acc = p1b[j];
            const float* wr = p1w + j*2*DD;
            for (int q=0;q<2*DD;q++) acc = fmaf(sLast[bb*2*DD+q], wr[q], acc);
            sC[bb][j] = fmaxf(acc, 0.f);
        }
        __syncthreads();
        float a2 = 0.f;
        if (j < 2*DD){
            a2 = p2b[j];
            const float* wr = p2w + j*2*DD;
            for (int q=0;q<2*DD;q++) a2 = fmaf(sC[bb][q], wr[q], a2);
            a2 = (a2 + sLast[bb*2*DD+j]) * ow[j];
        }
        __syncthreads();
        if (j < 2*DD) sC[bb][j] = a2;
        __syncthreads();
        if (tid < BB){
            float a3 = ob[0];
            for (int q=0;q<2*DD;q++) a3 += sC[tid][q];
            out[tid] = a3;
        }
    }
}

// -------------------------------------------------------------------------
extern "C" void kernel_launch(void* const* d_in, const int* in_sizes, int n_in,
                              void* d_out, int out_size){
    const float* xl   = (const float*)d_in[0];
    const float* xa   = (const float*)d_in[1];
    const float* xv   = (const float*)d_in[2];
    const float* Wl   = (const float*)d_in[3];
    const float* Wa   = (const float*)d_in[4];
    const float* Wv   = (const float*)d_in[5];
    const float* in_w = (const float*)d_in[6];
    const float* in_b = (const float*)d_in[7];
    const float* outw = (const float*)d_in[8];
    const float* outb = (const float*)d_in[9];
    const float* l1w  = (const float*)d_in[10];
    const float* l1b  = (const float*)d_in[11];
    const float* l2w  = (const float*)d_in[12];
    const float* l2b  = (const float*)d_in[13];
    const float* n1g  = (const float*)d_in[14];
    const float* n1b  = (const float*)d_in[15];
    const float* n2g  = (const float*)d_in[16];
    const float* n2b  = (const float*)d_in[17];
    const float* p1w  = (const float*)d_in[18];
    const float* p1b  = (const float*)d_in[19];
    const float* p2w  = (const float*)d_in[20];
    const float* p2b  = (const float*)d_in[21];
    const float* ow   = (const float*)d_in[22];
    const float* ob   = (const float*)d_in[23];
    float* out = (float*)d_out;

    static_assert(DYN_FLOATS*4 == 76800, "dyn smem size");
    cudaFuncSetAttribute(k_ffnq, cudaFuncAttributeMaxDynamicSharedMemorySize,
                         DYN_FLOATS*4);

    k_pre<<<TT*BB, 96>>>(xl, xa, xv, Wl, Wa, Wv, in_w, in_b, n1g, n1b);
    for (int l=0; l<LL; l++){
        k_att<<<dim3(NCH, NI, 2), 160>>>(l);
        k_ffnq<<<(2*TT*BB)/16, 512, DYN_FLOATS*4>>>(
                                      outw, outb, l1w, l1b, l2w, l2b, n2g, n2b,
                                      in_w, in_b, n1g, n1b,
                                      p1w, p1b, p2w, p2b, ow, ob, out, l);
    }
}

// round 15
// speedup vs baseline: 1.8515x; 1.0477x over previous
#include <cuda_runtime.h>
#include <cuda_fp16.h>
#include <math.h>

#define BB   8
#define TT   150
#define DD   30
#define HH   5
#define HDD  6
#define LL   3
#define NI   40     // BB*HH
#define KL   300
#define KA   74
#define KV   35
#define ACH  15     // a-values per attention block
#define NCH  10     // a-chunks (ACH*NCH = TT)
#define EPAD 164    // padded row length (bank-friendly float4)

// dynamic smem layout for k_ffnq (floats)
#define W1T_OFF 0          // [2][30][128]  w1^T : (s,q,j)
#define W2T_OFF 7680       // [2][120][32]  w2^T : (s,j,d)
#define OWT_OFF 15360      // [2][30][32]   out_w^T : (s,j,o)
#define IWT_OFF 17280      // [2][30][32]   in_w(q)^T : (s,j,d)
#define DYN_FLOATS 19200   // 76.8 KB

// dynamic smem layout for k_pre (floats)
#define PW_OFF  0          // [409][30] transposed modality weights
#define PX_OFF  12270      // [8][409]  x rows per b
#define PAX_OFF 15542      // [8][3][30] ax per warp (k,v,q)
#define PIW_OFF 16262      // [30][90]  in_w^T per sl
#define PRE_FLOATS 18962   // ~75.8 KB

// ---------------- device scratch (no allocations allowed) ----------------
__device__ float g_h[2][TT*BB*DD];            // per-stream hidden state [T,B,D]
__device__ float g_K[2][LL][NI*TT*HDD];       // per (s,l): [i, t, e]
__device__ float g_V[2][LL][NI*TT*HDD];
__device__ float g_Q[2][NI*TT*HDD];           // current-layer Q
__device__ float g_attn[2][TT*BB*DD];         // attention output [T,B,D]

__device__ __forceinline__ float warpsum(float v){
    #pragma unroll
    for (int o=16;o>0;o>>=1) v += __shfl_xor_sync(0xffffffffu, v, o);
    return v;
}
__device__ __forceinline__ void mma8(float4& d, unsigned a0, unsigned a1, unsigned b0){
    asm volatile("mma.sync.aligned.m16n8k8.row.col.f32.f16.f16.f32 "
        "{%0,%1,%2,%3}, {%4,%5}, {%6}, {%7,%8,%9,%10};"
        : "=f"(d.x),"=f"(d.y),"=f"(d.z),"=f"(d.w)
        : "r"(a0),"r"(a1),"r"(b0),
          "f"(0.f),"f"(0.f),"f"(0.f),"f"(0.f));
}
__device__ __forceinline__ unsigned h2u(__half2 h){
    unsigned u; 
    asm("mov.b32 %0, %1;" : "=r"(u) : "r"(*reinterpret_cast<unsigned*>(&h)));
    return u;
}

// ---------------- 1. fused pre-stage: proj + all K/V + Q(l=0) -------------
// one block per t (256 threads, warp = b). Weights staged transposed in smem.
__global__ void __launch_bounds__(256) k_pre(
    const float* __restrict__ xl, const float* __restrict__ xa,
    const float* __restrict__ xv, const float* __restrict__ Wl,
    const float* __restrict__ Wa, const float* __restrict__ Wv,
    const float* __restrict__ in_w, const float* __restrict__ in_b,
    const float* __restrict__ n1g, const float* __restrict__ n1b){
    extern __shared__ float dyn[];
    int t = blockIdx.x;
    int tid = threadIdx.x;
    int b = tid >> 5, lane = tid & 31;
    float* sW  = dyn + PW_OFF;     // [k_global][30], k_global<409
    float* sx  = dyn + PX_OFF;     // [8][409]
    float* sAx = dyn + PAX_OFF;    // [8][3][30]
    float* sIw = dyn + PIW_OFF;    // [j][90]

    // stage x rows (coalesced per b)
    #pragma unroll 1
    for (int bb=0; bb<BB; bb++){
        const float* xr = xl + (bb*TT+t)*KL;
        for (int k=tid;k<KL;k+=256) sx[bb*409+k] = xr[k];
        const float* xar = xa + (bb*TT+t)*KA;
        for (int k=tid;k<KA;k+=256) sx[bb*409+300+k] = xar[k];
        const float* xvr = xv + (bb*TT+t)*KV;
        for (int k=tid;k<KV;k+=256) sx[bb*409+374+k] = xvr[k];
    }
    // stage modality weights transposed (coalesced global reads)
    for (int g=tid; g<DD*KL; g+=256){ int d=g/KL, k=g-d*KL; sW[k*30+d] = Wl[g]; }
    for (int g=tid; g<DD*KA; g+=256){ int d=g/KA, k=g-d*KA; sW[(300+k)*30+d] = Wa[g]; }
    for (int g=tid; g<DD*KV; g+=256){ int d=g/KV, k=g-d*KV; sW[(374+k)*30+d] = Wv[g]; }
    __syncthreads();

    // modality projections (warp = b, lane = d); same accumulation order as before
    float p0=0.f, p1=0.f, p2=0.f;
    if (lane < DD){
        const float* xb = sx + b*409;
        for (int k=0;k<KL;k++) p0 = fmaf(xb[k],     sW[k*30+lane],       p0);
        for (int k=0;k<KA;k++) p1 = fmaf(xb[300+k], sW[(300+k)*30+lane], p1);
        for (int k=0;k<KV;k++) p2 = fmaf(xb[374+k], sW[(374+k)*30+lane], p2);
        int o=(t*BB+b)*DD+lane; g_h[0][o]=p0; g_h[1][o]=p0;
    }
    // LN normalize (no affine yet)
    float xn0, xn1, xn2;
    {
        float s0=warpsum(p0), q0=warpsum(p0*p0);
        float m=s0*(1.f/DD), v=q0*(1.f/DD)-m*m; xn0=(p0-m)*rsqrtf(v+1e-5f);
        float s1=warpsum(p1), q1=warpsum(p1*p1);
        m=s1*(1.f/DD); v=q1*(1.f/DD)-m*m; xn1=(p1-m)*rsqrtf(v+1e-5f);
        float s2=warpsum(p2), q2=warpsum(p2*p2);
        m=s2*(1.f/DD); v=q2*(1.f/DD)-m*m; xn2=(p2-m)*rsqrtf(v+1e-5f);
    }
    __syncthreads();

    #pragma unroll 1
    for (int sl=0; sl<6; sl++){
        int s_ = sl/LL, l_ = sl%LL;
        // stage in_w rows 0..89 transposed: sIw[j][r] = in_w[sl][r][j]
        const float* iw = in_w + sl*3*DD*DD;
        for (int g=tid; g<3*DD*DD; g+=256){ int r=g/DD, j=g-r*DD; sIw[j*90+r] = iw[g]; }
        int pb = sl*DD;
        if (lane<DD){
            float gg = n1g[pb+lane], be = n1b[pb+lane];
            float xk = (s_==0)? xn1 : xn2;
            float xv_= (s_==0)? xn2 : xn1;
            sAx[(b*3+0)*30+lane] = xk *gg + be;
            sAx[(b*3+1)*30+lane] = xv_*gg + be;
            sAx[(b*3+2)*30+lane] = xn0*gg + be;
        }
        __syncthreads();
        if (lane<DD){
            const float* ib  = in_b + sl*3*DD;
            const float* axk = sAx + (b*3+0)*30;
            const float* axv = sAx + (b*3+1)*30;
            const float* axq = sAx + (b*3+2)*30;
            int i = b*HH + lane/HDD, e = lane%HDD;
            int o = (i*TT + t)*HDD + e;
            float ka = ib[DD+lane], va = ib[2*DD+lane];
            #pragma unroll
            for (int j=0;j<DD;j++){
                ka = fmaf(axk[j], sIw[j*90 + DD+lane],   ka);
                va = fmaf(axv[j], sIw[j*90 + 2*DD+lane], va);
            }
            g_K[s_][l_][o] = ka;
            g_V[s_][l_][o] = va;
            if (l_==0){
                float qa = ib[lane];
                #pragma unroll
                for (int j=0;j<DD;j++) qa = fmaf(axq[j], sIw[j*90 + lane], qa);
                g_Q[s_][o] = qa * 0.4082482904638631f;
            }
        }
        __syncthreads();
    }
}

// ---------------- 2. attention core: tensor-core (HMMA) scan --------------
__global__ void __launch_bounds__(160) k_att(int l){
    int s = blockIdx.z, i = blockIdx.y, ch = blockIdx.x;
    int tid = threadIdx.x;
    int lane = tid & 31, w = tid >> 5;
    int g = lane >> 2, qd = lane & 3;
    int e0 = qd*2;
    __shared__ __align__(16) __half sKh[160][8];
    __shared__ __align__(4)  __half sVt[8][152];
    __shared__ __align__(16) __half sQh[ACH][8];
    __shared__ __align__(16) float sQt[7][EPAD];
    __shared__ __align__(16) float sFused[ACH][EPAD];
    __shared__ float sP[5][8];
    __shared__ float sVbar[8];
    __shared__ float sMaxP[ACH][8];
    __shared__ float sBMax[ACH];
    __shared__ float sDot[ACH][8];
    const float* Kp = g_K[s][l] + i*TT*HDD;
    const float* Vp = g_V[s][l] + i*TT*HDD;
    const float* Qp = g_Q[s]    + i*TT*HDD;

    float vv[HDD];
    if (tid < 150){
        #pragma unroll
        for (int e=0;e<HDD;e++){
            sKh[tid][e] = __float2half_rn(Kp[tid*HDD+e]);
            vv[e] = Vp[tid*HDD+e];
        }
        sKh[tid][6] = __float2half_rn(0.f);
        sKh[tid][7] = __float2half_rn(0.f);
    } else {
        #pragma unroll
        for (int e=0;e<8;e++) sKh[tid][e] = __float2half_rn(0.f);
        #pragma unroll
        for (int e=0;e<HDD;e++) vv[e] = 0.f;
    }
    {
        float p[HDD];
        #pragma unroll
        for (int e=0;e<HDD;e++) p[e] = warpsum(vv[e]);
        if (lane==0){
            #pragma unroll
            for (int e=0;e<HDD;e++) sP[w][e] = p[e];
        }
    }
    for (int idx=tid; idx<7*152; idx+=160){
        int j = idx / 152, b = idx - j*152;
        float val = 0.f;
        if (b < 150) val = (j<6) ? Qp[b*HDD+j] : 1.f;
        sQt[j][b] = val;
    }
    for (int idx=tid; idx<ACH*8; idx+=160){
        int a = idx >> 3, e = idx & 7;
        sQh[a][e] = (e<HDD) ? __float2half_rn(Qp[(ch*ACH+a)*HDD+e]) : __float2half_rn(0.f);
    }
    if (tid < ACH*2){
        int a = tid >> 1;
        sFused[a][150 + (tid&1)] = -1e30f;
    }
    __syncthreads();
    if (tid < HDD){
        float acc = 0.f;
        #pragma unroll
        for (int ww=0;ww<5;ww++) acc += sP[ww][tid];
        sVbar[tid] = acc * (1.f/TT);
    }
    __syncthreads();
    if (tid < 150){
        #pragma unroll
        for (int e=0;e<HDD;e++) sVt[e][tid] = __float2half_rn(vv[e] + sVbar[e]);
        #pragma unroll
        for (int e=HDD;e<8;e++) sVt[e][tid] = __float2half_rn(0.f);
    } else if (tid < 152){
        #pragma unroll
        for (int e=0;e<8;e++) sVt[e][tid] = __float2half_rn(0.f);
    }
    __syncthreads();

    int r0 = w*32 + g;                     // rows r0, r0+8, r0+16, r0+24
    __half2 kA0 = *(const __half2*)&sKh[r0][e0];
    __half2 kA1 = *(const __half2*)&sKh[r0+8][e0];
    __half2 kA2 = *(const __half2*)&sKh[r0+16][e0];
    __half2 kA3 = *(const __half2*)&sKh[r0+24][e0];
    unsigned bfu[19];
    #pragma unroll
    for (int j=0;j<19;j++){
        int c = j*8 + g;
        __half2 bb = __halves2half2(sVt[e0][c], sVt[e0+1][c]);
        bfu[j] = h2u(bb);
    }

    #pragma unroll 1
    for (int a=0;a<ACH;a++){
        __half2 q2 = *(const __half2*)&sQh[a][e0];
        unsigned a0 = h2u(__hmul2(kA0, q2));
        unsigned a1 = h2u(__hmul2(kA1, q2));
        unsigned a2 = h2u(__hmul2(kA2, q2));
        unsigned a3 = h2u(__hmul2(kA3, q2));
        float rm0=-INFINITY, rm1=-INFINITY, rm2=-INFINITY, rm3=-INFINITY;
        #pragma unroll
        for (int j=0;j<19;j++){
            float4 d;
            mma8(d, a0, a1, bfu[j]);
            bool ok = (j<18) || (qd!=3);   // exclude padded c=150,151
            if (ok){ rm0 = fmaxf(rm0, fmaxf(d.x,d.y)); rm1 = fmaxf(rm1, fmaxf(d.z,d.w)); }
            mma8(d, a2, a3, bfu[j]);
            if (ok){ rm2 = fmaxf(rm2, fmaxf(d.x,d.y)); rm3 = fmaxf(rm3, fmaxf(d.z,d.w)); }
        }
        #pragma unroll
        for (int o=1;o<=2;o<<=1){
            rm0 = fmaxf(rm0, __shfl_xor_sync(0xffffffffu, rm0, o));
            rm1 = fmaxf(rm1, __shfl_xor_sync(0xffffffffu, rm1, o));
            rm2 = fmaxf(rm2, __shfl_xor_sync(0xffffffffu, rm2, o));
            rm3 = fmaxf(rm3, __shfl_xor_sync(0xffffffffu, rm3, o));
        }
        float wm = -INFINITY;
        if (r0      < 150) wm = rm0;
        if (r0 + 8  < 150) wm = fmaxf(wm, rm1);
        if (r0 + 16 < 150) wm = fmaxf(wm, rm2);
        if (r0 + 24 < 150) wm = fmaxf(wm, rm3);
        #pragma unroll
        for (int o=4;o<=16;o<<=1) wm = fmaxf(wm, __shfl_xor_sync(0xffffffffu, wm, o));
        if (lane==0) sMaxP[a][w] = wm;
        if (qd==0){
            if (r0      < 150) sFused[a][r0]      = rm0;
            if (r0 + 8  < 150) sFused[a][r0 + 8]  = rm1;
            if (r0 + 16 < 150) sFused[a][r0 + 16] = rm2;
            if (r0 + 24 < 150) sFused[a][r0 + 24] = rm3;
        }
    }
    __syncthreads();

    if (tid < ACH){
        float mm = sMaxP[tid][0];
        #pragma unroll
        for (int ww=1;ww<5;ww++) mm = fmaxf(mm, sMaxP[tid][ww]);
        sBMax[tid] = mm;
    }
    __syncthreads();
    for (int idx=tid; idx<ACH*152; idx+=160){
        int a = idx / 152, b = idx - a*152;
        sFused[a][b] = __expf(sFused[a][b] - sBMax[a]);
    }
    __syncthreads();
    for (int idx=tid; idx<ACH*7; idx+=160){
        int a = idx / 7, j = idx % 7;
        const float4* ex4 = (const float4*)&sFused[a][0];
        const float4* q4  = (const float4*)&sQt[j][0];
        float acc = 0.f;
        #pragma unroll 5
        for (int b4=0;b4<38;b4++){
            float4 e4 = ex4[b4], qq = q4[b4];
            acc = fmaf(e4.x, qq.x, acc);
            acc = fmaf(e4.y, qq.y, acc);
            acc = fmaf(e4.z, qq.z, acc);
            acc = fmaf(e4.w, qq.w, acc);
        }
        sDot[a][j] = acc;
    }
    __syncthreads();
    int b_ = i/HH, h_ = i%HH;
    for (int idx=tid; idx<ACH*HDD; idx+=160){
        int a = idx / HDD, e = idx % HDD;
        g_attn[s][((ch*ACH+a)*BB + b_)*DD + h_*HDD + e] = sDot[a][e]/sDot[a][6];
    }
}

// ---------------- 3. ffn (+ next-layer Q; + head fused in block 149, l=2) -
// 512 threads = 16 warps = 16 rows; row = t*16 + s*8 + b  (t-major).
// Weights staged to smem TRANSPOSED so compute LDS is coalesced/conflict-free.
__global__ void __launch_bounds__(512) k_ffnq(
                       const float* __restrict__ out_w, const float* __restrict__ out_b,
                       const float* __restrict__ w1, const float* __restrict__ b1,
                       const float* __restrict__ w2, const float* __restrict__ b2,
                       const float* __restrict__ n2g, const float* __restrict__ n2b,
                       const float* __restrict__ in_w, const float* __restrict__ in_b,
                       const float* __restrict__ n1g, const float* __restrict__ n1b,
                       const float* __restrict__ p1w, const float* __restrict__ p1b,
                       const float* __restrict__ p2w, const float* __restrict__ p2b,
                       const float* __restrict__ ow, const float* __restrict__ ob,
                       float* __restrict__ out, int l){
    extern __shared__ float dyn[];
    int tid = threadIdx.x;
    int w = tid >> 5, lane = tid & 31;
    int gw = blockIdx.x*16 + w;           // row index, t-major
    int t = gw >> 4;
    int r16 = gw & 15;
    int s = r16 >> 3, b = r16 & 7;
    __shared__ float sA[16][DD], sXn[16][DD], sHid[16][4*DD];
    __shared__ float sLast[BB*2*DD];      // head scratch (block 149 only)
    __shared__ float sC[BB][2*DD];

    // ---- stage weights (both streams) transposed into smem, coalesced ----
    #pragma unroll 1
    for (int s2=0; s2<2; s2++){
        int pl2 = s2*LL + l;
        const float* gw1 = w1 + pl2*4*DD*DD;        // [120][30]
        for (int g2=tid; g2<4*DD*DD; g2+=512){
            int j = g2 / DD, q = g2 - j*DD;
            dyn[W1T_OFF + s2*3840 + q*128 + j] = gw1[g2];
        }
        const float* gw2 = w2 + pl2*DD*4*DD;        // [30][120]
        for (int g2=tid; g2<4*DD*DD; g2+=512){
            int d = g2 / (4*DD), j = g2 - d*4*DD;
            dyn[W2T_OFF + s2*3840 + j*32 + d] = gw2[g2];
        }
        const float* go = out_w + pl2*DD*DD;        // [30][30]
        for (int g2=tid; g2<DD*DD; g2+=512){
            int o = g2 / DD, j = g2 - o*DD;
            dyn[OWT_OFF + s2*960 + j*32 + o] = go[g2];
        }
        if (l+1 < LL){
            const float* gi = in_w + (pl2+1)*3*DD*DD;   // q rows [30][30]
            for (int g2=tid; g2<DD*DD; g2+=512){
                int d = g2 / DD, j = g2 - d*DD;
                dyn[IWT_OFF + s2*960 + j*32 + d] = gi[g2];
            }
        }
    }
    int ro = (t*BB+b)*DD;
    if (lane<DD) sA[w][lane] = g_attn[s][ro+lane];
    __syncthreads();

    int pl_ = s*LL+l;
    const float* W1t = dyn + W1T_OFF + s*3840;
    const float* W2t = dyn + W2T_OFF + s*3840;
    const float* OWt = dyn + OWT_OFF + s*960;
    const float* IWt = dyn + IWT_OFF + s*960;

    float x = 0.f;
    if (lane<DD){
        float acc = out_b[pl_*DD + lane];
        #pragma unroll
        for (int j=0;j<DD;j++) acc = fmaf(sA[w][j], OWt[j*32+lane], acc);
        x = g_h[s][ro+lane] + acc;        // residual
    }
    float sum = warpsum(x), sq = warpsum(x*x);
    float m = sum*(1.f/DD), var = sq*(1.f/DD)-m*m, rr = rsqrtf(var+1e-5f);
    if (lane<DD) sXn[w][lane] = (x-m)*rr*n2g[pl_*DD+lane] + n2b[pl_*DD+lane];
    __syncwarp();
    #pragma unroll
    for (int mo=0; mo<4; mo++){
        int j = mo*32 + lane;
        if (j < 4*DD){
            float acc = b1[pl_*4*DD + j];
            #pragma unroll
            for (int q=0;q<DD;q++) acc = fmaf(sXn[w][q], W1t[q*128+j], acc);
            sHid[w][j] = fmaxf(acc, 0.f);
        }
    }
    __syncwarp();
    float hnew = 0.f;
    if (lane<DD){
        float acc = b2[pl_*DD + lane];
        #pragma unroll 4
        for (int j=0;j<4*DD;j++) acc = fmaf(sHid[w][j], W2t[j*32+lane], acc);
        hnew = x + acc;                   // residual 2
        g_h[s][ro+lane] = hnew;
    }
    if (l+1 < LL){
        float sum2 = warpsum(hnew), sq2 = warpsum(hnew*hnew);
        float m2 = sum2*(1.f/DD), var2 = sq2*(1.f/DD)-m2*m2, r2 = rsqrtf(var2+1e-5f);
        int pb = (pl_+1)*DD;
        if (lane<DD) sA[w][lane] = (hnew-m2)*r2*n1g[pb+lane] + n1b[pb+lane];
        __syncwarp();
        if (lane<DD){
            float acc = in_b[(pl_+1)*3*DD + lane];
            #pragma unroll
            for (int j=0;j<DD;j++) acc = fmaf(sA[w][j], IWt[j*32+lane], acc);
            acc *= 0.4082482904638631f;
            int i = b*HH + lane/HDD, e = lane%HDD;
            g_Q[s][(i*TT+t)*HDD+e] = acc;
        }
    } else if (blockIdx.x == 149){
        if (lane < DD){
            sLast[b*2*DD + s*DD + lane] = hnew;
            out[BB + b*2*DD + s*DD + lane] = hnew;   // last_hs output
        }
        __syncthreads();
        int bb = tid >> 6, j = tid & 63;
        if (j < 2*DD){
            float acc = p1b[j];
            const float* wr = p1w + j*2*DD;
            for (int q=0;q<2*DD;q++) acc = fmaf(sLast[bb*2*DD+q], wr[q], acc);
            sC[bb][j] = fmaxf(acc, 0.f);
        }
        __syncthreads();
        float a2 = 0.f;
        if (j < 2*DD){
            a2 = p2b[j];
            const float* wr = p2w + j*2*DD;
            for (int q=0;q<2*DD;q++) a2 = fmaf(sC[bb][q], wr[q], a2);
            a2 = (a2 + sLast[bb*2*DD+j]) * ow[j];
        }
        __syncthreads();
        if (j < 2*DD) sC[bb][j] = a2;
        __syncthreads();
        if (tid < BB){
            float a3 = ob[0];
            for (int q=0;q<2*DD;q++) a3 += sC[tid][q];
            out[tid] = a3;
        }
    }
}

// -------------------------------------------------------------------------
extern "C" void kernel_launch(void* const* d_in, const int* in_sizes, int n_in,
                              void* d_out, int out_size){
    const float* xl   = (const float*)d_in[0];
    const float* xa   = (const float*)d_in[1];
    const float* xv   = (const float*)d_in[2];
    const float* Wl   = (const float*)d_in[3];
    const float* Wa   = (const float*)d_in[4];
    const float* Wv   = (const float*)d_in[5];
    const float* in_w = (const float*)d_in[6];
    const float* in_b = (const float*)d_in[7];
    const float* outw = (const float*)d_in[8];
    const float* outb = (const float*)d_in[9];
    const float* l1w  = (const float*)d_in[10];
    const float* l1b  = (const float*)d_in[11];
    const float* l2w  = (const float*)d_in[12];
    const float* l2b  = (const float*)d_in[13];
    const float* n1g  = (const float*)d_in[14];
    const float* n1b  = (const float*)d_in[15];
    const float* n2g  = (const float*)d_in[16];
    const float* n2b  = (const float*)d_in[17];
    const float* p1w  = (const float*)d_in[18];
    const float* p1b  = (const float*)d_in[19];
    const float* p2w  = (const float*)d_in[20];
    const float* p2b  = (const float*)d_in[21];
    const float* ow   = (const float*)d_in[22];
    const float* ob   = (const float*)d_in[23];
    float* out = (float*)d_out;

    cudaFuncSetAttribute(k_ffnq, cudaFuncAttributeMaxDynamicSharedMemorySize,
                         DYN_FLOATS*4);
    cudaFuncSetAttribute(k_pre, cudaFuncAttributeMaxDynamicSharedMemorySize,
                         PRE_FLOATS*4);

    k_pre<<<TT, 256, PRE_FLOATS*4>>>(xl, xa, xv, Wl, Wa, Wv, in_w, in_b, n1g, n1b);
    for (int l=0; l<LL; l++){
        k_att<<<dim3(NCH, NI, 2), 160>>>(l);
        k_ffnq<<<(2*TT*BB)/16, 512, DYN_FLOATS*4>>>(
                                      outw, outb, l1w, l1b, l2w, l2b, n2g, n2b,
                                      in_w, in_b, n1g, n1b,
                                      p1w, p1b, p2w, p2b, ow, ob, out, l);
    }
}

// round 16
// speedup vs baseline: 1.8889x; 1.0202x over previous
#include <cuda_runtime.h>
#include <cuda_fp16.h>
#include <math.h>

#define BB   8
#define TT   150
#define DD   30
#define HH   5
#define HDD  6
#define LL   3
#define NI   40     // BB*HH
#define KL   300
#define KA   74
#define KV   35
#define ACH  15     // a-values per attention block
#define NCH  10     // a-chunks (ACH*NCH = TT)
#define EPAD 164    // padded row length (bank-friendly float4)

// dynamic smem layout for k_ffnq (floats)
#define W1T_OFF 0          // [2][30][128]  w1^T : (s,q,j)
#define W2T_OFF 7680       // [2][120][32]  w2^T : (s,j,d)
#define OWT_OFF 15360      // [2][30][32]   out_w^T : (s,j,o)
#define IWT_OFF 17280      // [2][30][32]   in_w(q)^T : (s,j,d)
#define DYN_FLOATS 19200   // 76.8 KB

// dynamic smem layout for k_pre (floats)
#define PW_OFF  0          // [409][30] transposed modality weights
#define PX_OFF  12270      // [8][409]  x rows per b
#define PAX_OFF 15542      // [8][3][30] ax per warp (k,v,q)
#define PIW_OFF 16262      // [30][90]  in_w^T per sl
#define PRE_FLOATS 18962   // ~75.8 KB

// ---------------- device scratch (no allocations allowed) ----------------
__device__ float g_h[2][TT*BB*DD];            // per-stream hidden state [T,B,D]
__device__ float g_K[2][LL][NI*TT*HDD];       // per (s,l): [i, t, e]
__device__ float g_V[2][LL][NI*TT*HDD];
__device__ float g_Q[2][NI*TT*HDD];           // current-layer Q
__device__ float g_attn[2][TT*BB*DD];         // attention output [T,B,D]

__device__ __forceinline__ float warpsum(float v){
    #pragma unroll
    for (int o=16;o>0;o>>=1) v += __shfl_xor_sync(0xffffffffu, v, o);
    return v;
}
// f16-accumulate MMA: D(половина2 x2) = A(16x8) * B(8x8) + 0
__device__ __forceinline__ void mma8h(unsigned& d0, unsigned& d1,
                                      unsigned a0, unsigned a1, unsigned b0){
    asm volatile("mma.sync.aligned.m16n8k8.row.col.f16.f16.f16.f16 "
        "{%0,%1}, {%2,%3}, {%4}, {%5,%6};"
        : "=r"(d0),"=r"(d1)
        : "r"(a0),"r"(a1),"r"(b0),"r"(0u),"r"(0u));
}
__device__ __forceinline__ unsigned h2u(__half2 h){
    unsigned u; 
    asm("mov.b32 %0, %1;" : "=r"(u) : "r"(*reinterpret_cast<unsigned*>(&h)));
    return u;
}

// ---------------- 1. fused pre-stage: proj + all K/V + Q(l=0) -------------
// one block per t (256 threads, warp = b). Weights staged transposed in smem.
__global__ void __launch_bounds__(256) k_pre(
    const float* __restrict__ xl, const float* __restrict__ xa,
    const float* __restrict__ xv, const float* __restrict__ Wl,
    const float* __restrict__ Wa, const float* __restrict__ Wv,
    const float* __restrict__ in_w, const float* __restrict__ in_b,
    const float* __restrict__ n1g, const float* __restrict__ n1b){
    extern __shared__ float dyn[];
    int t = blockIdx.x;
    int tid = threadIdx.x;
    int b = tid >> 5, lane = tid & 31;
    float* sW  = dyn + PW_OFF;     // [k_global][30], k_global<409
    float* sx  = dyn + PX_OFF;     // [8][409]
    float* sAx = dyn + PAX_OFF;    // [8][3][30]
    float* sIw = dyn + PIW_OFF;    // [j][90]

    #pragma unroll 1
    for (int bb=0; bb<BB; bb++){
        const float* xr = xl + (bb*TT+t)*KL;
        for (int k=tid;k<KL;k+=256) sx[bb*409+k] = xr[k];
        const float* xar = xa + (bb*TT+t)*KA;
        for (int k=tid;k<KA;k+=256) sx[bb*409+300+k] = xar[k];
        const float* xvr = xv + (bb*TT+t)*KV;
        for (int k=tid;k<KV;k+=256) sx[bb*409+374+k] = xvr[k];
    }
    for (int g=tid; g<DD*KL; g+=256){ int d=g/KL, k=g-d*KL; sW[k*30+d] = Wl[g]; }
    for (int g=tid; g<DD*KA; g+=256){ int d=g/KA, k=g-d*KA; sW[(300+k)*30+d] = Wa[g]; }
    for (int g=tid; g<DD*KV; g+=256){ int d=g/KV, k=g-d*KV; sW[(374+k)*30+d] = Wv[g]; }
    __syncthreads();

    float p0=0.f, p1=0.f, p2=0.f;
    if (lane < DD){
        const float* xb = sx + b*409;
        for (int k=0;k<KL;k++) p0 = fmaf(xb[k],     sW[k*30+lane],       p0);
        for (int k=0;k<KA;k++) p1 = fmaf(xb[300+k], sW[(300+k)*30+lane], p1);
        for (int k=0;k<KV;k++) p2 = fmaf(xb[374+k], sW[(374+k)*30+lane], p2);
        int o=(t*BB+b)*DD+lane; g_h[0][o]=p0; g_h[1][o]=p0;
    }
    float xn0, xn1, xn2;
    {
        float s0=warpsum(p0), q0=warpsum(p0*p0);
        float m=s0*(1.f/DD), v=q0*(1.f/DD)-m*m; xn0=(p0-m)*rsqrtf(v+1e-5f);
        float s1=warpsum(p1), q1=warpsum(p1*p1);
        m=s1*(1.f/DD); v=q1*(1.f/DD)-m*m; xn1=(p1-m)*rsqrtf(v+1e-5f);
        float s2=warpsum(p2), q2=warpsum(p2*p2);
        m=s2*(1.f/DD); v=q2*(1.f/DD)-m*m; xn2=(p2-m)*rsqrtf(v+1e-5f);
    }
    __syncthreads();

    #pragma unroll 1
    for (int sl=0; sl<6; sl++){
        int s_ = sl/LL, l_ = sl%LL;
        const float* iw = in_w + sl*3*DD*DD;
        for (int g=tid; g<3*DD*DD; g+=256){ int r=g/DD, j=g-r*DD; sIw[j*90+r] = iw[g]; }
        int pb = sl*DD;
        if (lane<DD){
            float gg = n1g[pb+lane], be = n1b[pb+lane];
            float xk = (s_==0)? xn1 : xn2;
            float xv_= (s_==0)? xn2 : xn1;
            sAx[(b*3+0)*30+lane] = xk *gg + be;
            sAx[(b*3+1)*30+lane] = xv_*gg + be;
            sAx[(b*3+2)*30+lane] = xn0*gg + be;
        }
        __syncthreads();
        if (lane<DD){
            const float* ib  = in_b + sl*3*DD;
            const float* axk = sAx + (b*3+0)*30;
            const float* axv = sAx + (b*3+1)*30;
            const float* axq = sAx + (b*3+2)*30;
            int i = b*HH + lane/HDD, e = lane%HDD;
            int o = (i*TT + t)*HDD + e;
            float ka = ib[DD+lane], va = ib[2*DD+lane];
            #pragma unroll
            for (int j=0;j<DD;j++){
                ka = fmaf(axk[j], sIw[j*90 + DD+lane],   ka);
                va = fmaf(axv[j], sIw[j*90 + 2*DD+lane], va);
            }
            g_K[s_][l_][o] = ka;
            g_V[s_][l_][o] = va;
            if (l_==0){
                float qa = ib[lane];
                #pragma unroll
                for (int j=0;j<DD;j++) qa = fmaf(axq[j], sIw[j*90 + lane], qa);
                g_Q[s_][o] = qa * 0.4082482904638631f;
            }
        }
        __syncthreads();
    }
}

// ---------------- 2. attention core: tensor-core HMMA (f16 accum) ---------
__global__ void __launch_bounds__(160) k_att(int l){
    int s = blockIdx.z, i = blockIdx.y, ch = blockIdx.x;
    int tid = threadIdx.x;
    int lane = tid & 31, w = tid >> 5;
    int g = lane >> 2, qd = lane & 3;
    int e0 = qd*2;
    __shared__ __align__(16) __half sKh[160][8];
    __shared__ __align__(4)  __half sVt[8][152];
    __shared__ __align__(16) __half sQh[ACH][8];
    __shared__ __align__(16) float sQt[7][EPAD];
    __shared__ __align__(16) float sFused[ACH][EPAD];
    __shared__ float sP[5][8];
    __shared__ float sVbar[8];
    __shared__ float sMaxP[ACH][8];
    __shared__ float sBMax[ACH];
    __shared__ float sDot[ACH][8];
    const float* Kp = g_K[s][l] + i*TT*HDD;
    const float* Vp = g_V[s][l] + i*TT*HDD;
    const float* Qp = g_Q[s]    + i*TT*HDD;

    float vv[HDD];
    if (tid < 150){
        #pragma unroll
        for (int e=0;e<HDD;e++){
            sKh[tid][e] = __float2half_rn(Kp[tid*HDD+e]);
            vv[e] = Vp[tid*HDD+e];
        }
        sKh[tid][6] = __float2half_rn(0.f);
        sKh[tid][7] = __float2half_rn(0.f);
    } else {
        #pragma unroll
        for (int e=0;e<8;e++) sKh[tid][e] = __float2half_rn(0.f);
        #pragma unroll
        for (int e=0;e<HDD;e++) vv[e] = 0.f;
    }
    {
        float p[HDD];
        #pragma unroll
        for (int e=0;e<HDD;e++) p[e] = warpsum(vv[e]);
        if (lane==0){
            #pragma unroll
            for (int e=0;e<HDD;e++) sP[w][e] = p[e];
        }
    }
    for (int idx=tid; idx<7*152; idx+=160){
        int j = idx / 152, b = idx - j*152;
        float val = 0.f;
        if (b < 150) val = (j<6) ? Qp[b*HDD+j] : 1.f;
        sQt[j][b] = val;
    }
    for (int idx=tid; idx<ACH*8; idx+=160){
        int a = idx >> 3, e = idx & 7;
        sQh[a][e] = (e<HDD) ? __float2half_rn(Qp[(ch*ACH+a)*HDD+e]) : __float2half_rn(0.f);
    }
    if (tid < ACH*2){
        int a = tid >> 1;
        sFused[a][150 + (tid&1)] = -1e30f;
    }
    __syncthreads();
    if (tid < HDD){
        float acc = 0.f;
        #pragma unroll
        for (int ww=0;ww<5;ww++) acc += sP[ww][tid];
        sVbar[tid] = acc * (1.f/TT);
    }
    __syncthreads();
    if (tid < 150){
        #pragma unroll
        for (int e=0;e<HDD;e++) sVt[e][tid] = __float2half_rn(vv[e] + sVbar[e]);
        #pragma unroll
        for (int e=HDD;e<8;e++) sVt[e][tid] = __float2half_rn(0.f);
    } else if (tid < 152){
        #pragma unroll
        for (int e=0;e<8;e++) sVt[e][tid] = __float2half_rn(0.f);
    }
    __syncthreads();

    int r0 = w*32 + g;                     // rows r0, r0+8, r0+16, r0+24
    __half2 kA0 = *(const __half2*)&sKh[r0][e0];
    __half2 kA1 = *(const __half2*)&sKh[r0+8][e0];
    __half2 kA2 = *(const __half2*)&sKh[r0+16][e0];
    __half2 kA3 = *(const __half2*)&sKh[r0+24][e0];
    unsigned bfu[19];
    #pragma unroll
    for (int j=0;j<19;j++){
        int c = j*8 + g;
        __half2 bb = __halves2half2(sVt[e0][c], sVt[e0+1][c]);
        bfu[j] = h2u(bb);
    }

    const __half2 NEGBIG = __floats2half2_rn(-60000.f, -60000.f);
    #pragma unroll 1
    for (int a=0;a<ACH;a++){
        __half2 q2 = *(const __half2*)&sQh[a][e0];
        unsigned a0 = h2u(__hmul2(kA0, q2));
        unsigned a1 = h2u(__hmul2(kA1, q2));
        unsigned a2 = h2u(__hmul2(kA2, q2));
        unsigned a3 = h2u(__hmul2(kA3, q2));
        __half2 mA = NEGBIG, mB = NEGBIG, mC = NEGBIG, mD = NEGBIG;
        #pragma unroll
        for (int j=0;j<19;j++){
            unsigned d0, d1, f0, f1;
            mma8h(d0, d1, a0, a1, bfu[j]);
            mma8h(f0, f1, a2, a3, bfu[j]);
            bool ok = (j<18) || (qd!=3);   // exclude padded c=150,151
            if (ok){
                mA = __hmax2(mA, *(__half2*)&d0);
                mB = __hmax2(mB, *(__half2*)&d1);
                mC = __hmax2(mC, *(__half2*)&f0);
                mD = __hmax2(mD, *(__half2*)&f1);
            }
        }
        float rm0 = fmaxf(__low2float(mA), __high2float(mA));
        float rm1 = fmaxf(__low2float(mB), __high2float(mB));
        float rm2 = fmaxf(__low2float(mC), __high2float(mC));
        float rm3 = fmaxf(__low2float(mD), __high2float(mD));
        // quad reduce (full max over all 8 cols of each tile-row)
        #pragma unroll
        for (int o=1;o<=2;o<<=1){
            rm0 = fmaxf(rm0, __shfl_xor_sync(0xffffffffu, rm0, o));
            rm1 = fmaxf(rm1, __shfl_xor_sync(0xffffffffu, rm1, o));
            rm2 = fmaxf(rm2, __shfl_xor_sync(0xffffffffu, rm2, o));
            rm3 = fmaxf(rm3, __shfl_xor_sync(0xffffffffu, rm3, o));
        }
        float wm = -INFINITY;
        if (r0      < 150) wm = rm0;
        if (r0 + 8  < 150) wm = fmaxf(wm, rm1);
        if (r0 + 16 < 150) wm = fmaxf(wm, rm2);
        if (r0 + 24 < 150) wm = fmaxf(wm, rm3);
        #pragma unroll
        for (int o=4;o<=16;o<<=1) wm = fmaxf(wm, __shfl_xor_sync(0xffffffffu, wm, o));
        if (lane==0) sMaxP[a][w] = wm;
        if (qd==0){
            if (r0      < 150) sFused[a][r0]      = rm0;
            if (r0 + 8  < 150) sFused[a][r0 + 8]  = rm1;
            if (r0 + 16 < 150) sFused[a][r0 + 16] = rm2;
            if (r0 + 24 < 150) sFused[a][r0 + 24] = rm3;
        }
    }
    __syncthreads();

    if (tid < ACH){
        float mm = sMaxP[tid][0];
        #pragma unroll
        for (int ww=1;ww<5;ww++) mm = fmaxf(mm, sMaxP[tid][ww]);
        sBMax[tid] = mm;
    }
    __syncthreads();
    for (int idx=tid; idx<ACH*152; idx+=160){
        int a = idx / 152, b = idx - a*152;
        sFused[a][b] = __expf(sFused[a][b] - sBMax[a]);
    }
    __syncthreads();
    for (int idx=tid; idx<ACH*7; idx+=160){
        int a = idx / 7, j = idx % 7;
        const float4* ex4 = (const float4*)&sFused[a][0];
        const float4* q4  = (const float4*)&sQt[j][0];
        float acc = 0.f;
        #pragma unroll 5
        for (int b4=0;b4<38;b4++){
            float4 e4 = ex4[b4], qq = q4[b4];
            acc = fmaf(e4.x, qq.x, acc);
            acc = fmaf(e4.y, qq.y, acc);
            acc = fmaf(e4.z, qq.z, acc);
            acc = fmaf(e4.w, qq.w, acc);
        }
        sDot[a][j] = acc;
    }
    __syncthreads();
    int b_ = i/HH, h_ = i%HH;
    for (int idx=tid; idx<ACH*HDD; idx+=160){
        int a = idx / HDD, e = idx % HDD;
        g_attn[s][((ch*ACH+a)*BB + b_)*DD + h_*HDD + e] = sDot[a][e]/sDot[a][6];
    }
}

// ---------------- 3. ffn (+ next-layer Q; + head fused in block 149, l=2) -
__global__ void __launch_bounds__(512) k_ffnq(
                       const float* __restrict__ out_w, const float* __restrict__ out_b,
                       const float* __restrict__ w1, const float* __restrict__ b1,
                       const float* __restrict__ w2, const float* __restrict__ b2,
                       const float* __restrict__ n2g, const float* __restrict__ n2b,
                       const float* __restrict__ in_w, const float* __restrict__ in_b,
                       const float* __restrict__ n1g, const float* __restrict__ n1b,
                       const float* __restrict__ p1w, const float* __restrict__ p1b,
                       const float* __restrict__ p2w, const float* __restrict__ p2b,
                       const float* __restrict__ ow, const float* __restrict__ ob,
                       float* __restrict__ out, int l){
    extern __shared__ float dyn[];
    int tid = threadIdx.x;
    int w = tid >> 5, lane = tid & 31;
    int gw = blockIdx.x*16 + w;           // row index, t-major
    int t = gw >> 4;
    int r16 = gw & 15;
    int s = r16 >> 3, b = r16 & 7;
    __shared__ float sA[16][DD], sXn[16][DD], sHid[16][4*DD];
    __shared__ float sLast[BB*2*DD];      // head scratch (block 149 only)
    __shared__ float sC[BB][2*DD];

    #pragma unroll 1
    for (int s2=0; s2<2; s2++){
        int pl2 = s2*LL + l;
        const float* gw1 = w1 + pl2*4*DD*DD;        // [120][30]
        for (int g2=tid; g2<4*DD*DD; g2+=512){
            int j = g2 / DD, q = g2 - j*DD;
            dyn[W1T_OFF + s2*3840 + q*128 + j] = gw1[g2];
        }
        const float* gw2 = w2 + pl2*DD*4*DD;        // [30][120]
        for (int g2=tid; g2<4*DD*DD; g2+=512){
            int d = g2 / (4*DD), j = g2 - d*4*DD;
            dyn[W2T_OFF + s2*3840 + j*32 + d] = gw2[g2];
        }
        const float* go = out_w + pl2*DD*DD;        // [30][30]
        for (int g2=tid; g2<DD*DD; g2+=512){
            int o = g2 / DD, j = g2 - o*DD;
            dyn[OWT_OFF + s2*960 + j*32 + o] = go[g2];
        }
        if (l+1 < LL){
            const float* gi = in_w + (pl2+1)*3*DD*DD;   // q rows [30][30]
            for (int g2=tid; g2<DD*DD; g2+=512){
                int d = g2 / DD, j = g2 - d*DD;
                dyn[IWT_OFF + s2*960 + j*32 + d] = gi[g2];
            }
        }
    }
    int ro = (t*BB+b)*DD;
    if (lane<DD) sA[w][lane] = g_attn[s][ro+lane];
    __syncthreads();

    int pl_ = s*LL+l;
    const float* W1t = dyn + W1T_OFF + s*3840;
    const float* W2t = dyn + W2T_OFF + s*3840;
    const float* OWt = dyn + OWT_OFF + s*960;
    const float* IWt = dyn + IWT_OFF + s*960;

    float x = 0.f;
    if (lane<DD){
        float acc = out_b[pl_*DD + lane];
        #pragma unroll
        for (int j=0;j<DD;j++) acc = fmaf(sA[w][j], OWt[j*32+lane], acc);
        x = g_h[s][ro+lane] + acc;        // residual
    }
    float sum = warpsum(x), sq = warpsum(x*x);
    float m = sum*(1.f/DD), var = sq*(1.f/DD)-m*m, rr = rsqrtf(var+1e-5f);
    if (lane<DD) sXn[w][lane] = (x-m)*rr*n2g[pl_*DD+lane] + n2b[pl_*DD+lane];
    __syncwarp();
    #pragma unroll
    for (int mo=0; mo<4; mo++){
        int j = mo*32 + lane;
        if (j < 4*DD){
            float acc = b1[pl_*4*DD + j];
            #pragma unroll
            for (int q=0;q<DD;q++) acc = fmaf(sXn[w][q], W1t[q*128+j], acc);
            sHid[w][j] = fmaxf(acc, 0.f);
        }
    }
    __syncwarp();
    float hnew = 0.f;
    if (lane<DD){
        float acc = b2[pl_*DD + lane];
        #pragma unroll 4
        for (int j=0;j<4*DD;j++) acc = fmaf(sHid[w][j], W2t[j*32+lane], acc);
        hnew = x + acc;                   // residual 2
        g_h[s][ro+lane] = hnew;
    }
    if (l+1 < LL){
        float sum2 = warpsum(hnew), sq2 = warpsum(hnew*hnew);
        float m2 = sum2*(1.f/DD), var2 = sq2*(1.f/DD)-m2*m2, r2 = rsqrtf(var2+1e-5f);
        int pb = (pl_+1)*DD;
        if (lane<DD) sA[w][lane] = (hnew-m2)*r2*n1g[pb+lane] + n1b[pb+lane];
        __syncwarp();
        if (lane<DD){
            float acc = in_b[(pl_+1)*3*DD + lane];
            #pragma unroll
            for (int j=0;j<DD;j++) acc = fmaf(sA[w][j], IWt[j*32+lane], acc);
            acc *= 0.4082482904638631f;
            int i = b*HH + lane/HDD, e = lane%HDD;
            g_Q[s][(i*TT+t)*HDD+e] = acc;
        }
    } else if (blockIdx.x == 149){
        if (lane < DD){
            sLast[b*2*DD + s*DD + lane] = hnew;
            out[BB + b*2*DD + s*DD + lane] = hnew;   // last_hs output
        }
        __syncthreads();
        int bb = tid >> 6, j = tid & 63;
        if (j < 2*DD){
            float acc = p1b[j];
            const float* wr = p1w + j*2*DD;
            for (int q=0;q<2*DD;q++) acc = fmaf(sLast[bb*2*DD+q], wr[q], acc);
            sC[bb][j] = fmaxf(acc, 0.f);
        }
        __syncthreads();
        float a2 = 0.f;
        if (j < 2*DD){
            a2 = p2b[j];
            const float* wr = p2w + j*2*DD;
            for (int q=0;q<2*DD;q++) a2 = fmaf(sC[bb][q], wr[q], a2);
            a2 = (a2 + sLast[bb*2*DD+j]) * ow[j];
        }
        __syncthreads();
        if (j < 2*DD) sC[bb][j] = a2;
        __syncthreads();
        if (tid < BB){
            float a3 = ob[0];
            for (int q=0;q<2*DD;q++) a3 += sC[tid][q];
            out[tid] = a3;
        }
    }
}

// -------------------------------------------------------------------------
extern "C" void kernel_launch(void* const* d_in, const int* in_sizes, int n_in,
                              void* d_out, int out_size){
    const float* xl   = (const float*)d_in[0];
    const float* xa   = (const float*)d_in[1];
    const float* xv   = (const float*)d_in[2];
    const float* Wl   = (const float*)d_in[3];
    const float* Wa   = (const float*)d_in[4];
    const float* Wv   = (const float*)d_in[5];
    const float* in_w = (const float*)d_in[6];
    const float* in_b = (const float*)d_in[7];
    const float* outw = (const float*)d_in[8];
    const float* outb = (const float*)d_in[9];
    const float* l1w  = (const float*)d_in[10];
    const float* l1b  = (const float*)d_in[11];
    const float* l2w  = (const float*)d_in[12];
    const float* l2b  = (const float*)d_in[13];
    const float* n1g  = (const float*)d_in[14];
    const float* n1b  = (const float*)d_in[15];
    const float* n2g  = (const float*)d_in[16];
    const float* n2b  = (const float*)d_in[17];
    const float* p1w  = (const float*)d_in[18];
    const float* p1b  = (const float*)d_in[19];
    const float* p2w  = (const float*)d_in[20];
    const float* p2b  = (const float*)d_in[21];
    const float* ow   = (const float*)d_in[22];
    const float* ob   = (const float*)d_in[23];
    float* out = (float*)d_out;

    cudaFuncSetAttribute(k_ffnq, cudaFuncAttributeMaxDynamicSharedMemorySize,
                         DYN_FLOATS*4);
    cudaFuncSetAttribute(k_pre, cudaFuncAttributeMaxDynamicSharedMemorySize,
                         PRE_FLOATS*4);

    k_pre<<<TT, 256, PRE_FLOATS*4>>>(xl, xa, xv, Wl, Wa, Wv, in_w, in_b, n1g, n1b);
    for (int l=0; l<LL; l++){
        k_att<<<dim3(NCH, NI, 2), 160>>>(l);
        k_ffnq<<<(2*TT*BB)/16, 512, DYN_FLOATS*4>>>(
                                      outw, outb, l1w, l1b, l2w, l2b, n2g, n2b,
                                      in_w, in_b, n1g, n1b,
                                      p1w, p1b, p2w, p2b, ow, ob, out, l);
    }
}

// round 17
// speedup vs baseline: 1.9328x; 1.0232x over previous
#include <cuda_runtime.h>
#include <cuda_fp16.h>
#include <math.h>

#define BB   8
#define TT   150
#define DD   30
#define HH   5
#define HDD  6
#define LL   3
#define NI   40     // BB*HH
#define KL   300
#define KA   74
#define KV   35
#define ACH  15     // a-values per attention block
#define NCH  10     // a-chunks (ACH*NCH = TT)
#define EPAD 164    // padded row length (bank-friendly float4)

// dynamic smem layout for k_ffnq (floats)
#define W1T_OFF 0          // [2][30][128]  w1^T : (s,q,j)
#define W2T_OFF 7680       // [2][120][32]  w2^T : (s,j,d)
#define OWT_OFF 15360      // [2][30][32]   out_w^T : (s,j,o)
#define IWT_OFF 17280      // [2][30][32]   in_w(q)^T : (s,j,d)
#define DYN_FLOATS 19200   // 76.8 KB

// dynamic smem layout for k_pre (floats)
#define PW_OFF  0          // [409][30] transposed modality weights
#define PX_OFF  12270      // [8][409]  x rows per b
#define PAX_OFF 15542      // [8][3][30] ax per warp (k,v,q)
#define PIW_OFF 16262      // [30][90]  in_w^T per sl
#define PRE_FLOATS 18962   // ~75.8 KB

// ---------------- device scratch (no allocations allowed) ----------------
__device__ float g_h[2][TT*BB*DD];            // per-stream hidden state [T,B,D]
__device__ float g_K[2][LL][NI*TT*HDD];       // per (s,l): [i, t, e]
__device__ float g_V[2][LL][NI*TT*HDD];
__device__ float g_Q[2][NI*TT*HDD];           // current-layer Q
__device__ float g_attn[2][TT*BB*DD];         // attention output [T,B,D]

__device__ __forceinline__ float warpsum(float v){
    #pragma unroll
    for (int o=16;o>0;o>>=1) v += __shfl_xor_sync(0xffffffffu, v, o);
    return v;
}
// f16-accumulate MMA
__device__ __forceinline__ void mma8h(unsigned& d0, unsigned& d1,
                                      unsigned a0, unsigned a1, unsigned b0){
    asm volatile("mma.sync.aligned.m16n8k8.row.col.f16.f16.f16.f16 "
        "{%0,%1}, {%2,%3}, {%4}, {%5,%6};"
        : "=r"(d0),"=r"(d1)
        : "r"(a0),"r"(a1),"r"(b0),"r"(0u),"r"(0u));
}
__device__ __forceinline__ unsigned h2u(__half2 h){
    unsigned u; 
    asm("mov.b32 %0, %1;" : "=r"(u) : "r"(*reinterpret_cast<unsigned*>(&h)));
    return u;
}

// ---------------- 1. fused pre-stage: proj + all K/V + Q(l=0) -------------
// one block per t (256 threads, warp = b). Weights staged transposed in smem.
__global__ void __launch_bounds__(256) k_pre(
    const float* __restrict__ xl, const float* __restrict__ xa,
    const float* __restrict__ xv, const float* __restrict__ Wl,
    const float* __restrict__ Wa, const float* __restrict__ Wv,
    const float* __restrict__ in_w, const float* __restrict__ in_b,
    const float* __restrict__ n1g, const float* __restrict__ n1b){
    extern __shared__ float dyn[];
    int t = blockIdx.x;
    int tid = threadIdx.x;
    int b = tid >> 5, lane = tid & 31;
    float* sW  = dyn + PW_OFF;     // [k_global][30], k_global<409
    float* sx  = dyn + PX_OFF;     // [8][409]
    float* sAx = dyn + PAX_OFF;    // [8][3][30]
    float* sIw = dyn + PIW_OFF;    // [j][90]

    #pragma unroll 1
    for (int bb=0; bb<BB; bb++){
        const float* xr = xl + (bb*TT+t)*KL;
        for (int k=tid;k<KL;k+=256) sx[bb*409+k] = xr[k];
        const float* xar = xa + (bb*TT+t)*KA;
        for (int k=tid;k<KA;k+=256) sx[bb*409+300+k] = xar[k];
        const float* xvr = xv + (bb*TT+t)*KV;
        for (int k=tid;k<KV;k+=256) sx[bb*409+374+k] = xvr[k];
    }
    for (int g=tid; g<DD*KL; g+=256){ int d=g/KL, k=g-d*KL; sW[k*30+d] = Wl[g]; }
    for (int g=tid; g<DD*KA; g+=256){ int d=g/KA, k=g-d*KA; sW[(300+k)*30+d] = Wa[g]; }
    for (int g=tid; g<DD*KV; g+=256){ int d=g/KV, k=g-d*KV; sW[(374+k)*30+d] = Wv[g]; }
    __syncthreads();

    float p0=0.f, p1=0.f, p2=0.f;
    if (lane < DD){
        const float* xb = sx + b*409;
        for (int k=0;k<KL;k++) p0 = fmaf(xb[k],     sW[k*30+lane],       p0);
        for (int k=0;k<KA;k++) p1 = fmaf(xb[300+k], sW[(300+k)*30+lane], p1);
        for (int k=0;k<KV;k++) p2 = fmaf(xb[374+k], sW[(374+k)*30+lane], p2);
        int o=(t*BB+b)*DD+lane; g_h[0][o]=p0; g_h[1][o]=p0;
    }
    float xn0, xn1, xn2;
    {
        float s0=warpsum(p0), q0=warpsum(p0*p0);
        float m=s0*(1.f/DD), v=q0*(1.f/DD)-m*m; xn0=(p0-m)*rsqrtf(v+1e-5f);
        float s1=warpsum(p1), q1=warpsum(p1*p1);
        m=s1*(1.f/DD); v=q1*(1.f/DD)-m*m; xn1=(p1-m)*rsqrtf(v+1e-5f);
        float s2=warpsum(p2), q2=warpsum(p2*p2);
        m=s2*(1.f/DD); v=q2*(1.f/DD)-m*m; xn2=(p2-m)*rsqrtf(v+1e-5f);
    }
    __syncthreads();

    #pragma unroll 1
    for (int sl=0; sl<6; sl++){
        int s_ = sl/LL, l_ = sl%LL;
        const float* iw = in_w + sl*3*DD*DD;
        for (int g=tid; g<3*DD*DD; g+=256){ int r=g/DD, j=g-r*DD; sIw[j*90+r] = iw[g]; }
        int pb = sl*DD;
        if (lane<DD){
            float gg = n1g[pb+lane], be = n1b[pb+lane];
            float xk = (s_==0)? xn1 : xn2;
            float xv_= (s_==0)? xn2 : xn1;
            sAx[(b*3+0)*30+lane] = xk *gg + be;
            sAx[(b*3+1)*30+lane] = xv_*gg + be;
            sAx[(b*3+2)*30+lane] = xn0*gg + be;
        }
        __syncthreads();
        if (lane<DD){
            const float* ib  = in_b + sl*3*DD;
            const float* axk = sAx + (b*3+0)*30;
            const float* axv = sAx + (b*3+1)*30;
            const float* axq = sAx + (b*3+2)*30;
            int i = b*HH + lane/HDD, e = lane%HDD;
            int o = (i*TT + t)*HDD + e;
            float ka = ib[DD+lane], va = ib[2*DD+lane];
            #pragma unroll
            for (int j=0;j<DD;j++){
                ka = fmaf(axk[j], sIw[j*90 + DD+lane],   ka);
                va = fmaf(axv[j], sIw[j*90 + 2*DD+lane], va);
            }
            g_K[s_][l_][o] = ka;
            g_V[s_][l_][o] = va;
            if (l_==0){
                float qa = ib[lane];
                #pragma unroll
                for (int j=0;j<DD;j++) qa = fmaf(axq[j], sIw[j*90 + lane], qa);
                g_Q[s_][o] = qa * 0.4082482904638631f;
            }
        }
        __syncthreads();
    }
}

// ---------------- 2. attention core: tensor-core HMMA (f16 accum) ---------
__global__ void __launch_bounds__(160) k_att(int l){
    int s = blockIdx.z, i = blockIdx.y, ch = blockIdx.x;
    int tid = threadIdx.x;
    int lane = tid & 31, w = tid >> 5;
    int g = lane >> 2, qd = lane & 3;
    int e0 = qd*2;
    __shared__ __align__(16) __half sKh[160][8];
    __shared__ __align__(4)  __half sVt[8][152];
    __shared__ __align__(16) __half sQh[ACH][8];
    __shared__ __align__(16) float sQt[7][EPAD];
    __shared__ __align__(16) float sFused[ACH][EPAD];
    __shared__ float sP[5][8];
    __shared__ float sVbar[8];
    __shared__ float sBMax[ACH];
    __shared__ float sDot[ACH][8];
    const float* Kp = g_K[s][l] + i*TT*HDD;
    const float* Vp = g_V[s][l] + i*TT*HDD;
    const float* Qp = g_Q[s]    + i*TT*HDD;

    float vv[HDD];
    if (tid < 150){
        #pragma unroll
        for (int e=0;e<HDD;e++){
            sKh[tid][e] = __float2half_rn(Kp[tid*HDD+e]);
            vv[e] = Vp[tid*HDD+e];
        }
        sKh[tid][6] = __float2half_rn(0.f);
        sKh[tid][7] = __float2half_rn(0.f);
    } else {
        #pragma unroll
        for (int e=0;e<8;e++) sKh[tid][e] = __float2half_rn(0.f);
        #pragma unroll
        for (int e=0;e<HDD;e++) vv[e] = 0.f;
    }
    {
        float p[HDD];
        #pragma unroll
        for (int e=0;e<HDD;e++) p[e] = warpsum(vv[e]);
        if (lane==0){
            #pragma unroll
            for (int e=0;e<HDD;e++) sP[w][e] = p[e];
        }
    }
    for (int idx=tid; idx<7*152; idx+=160){
        int j = idx / 152, b = idx - j*152;
        float val = 0.f;
        if (b < 150) val = (j<6) ? Qp[b*HDD+j] : 1.f;
        sQt[j][b] = val;
    }
    for (int idx=tid; idx<ACH*8; idx+=160){
        int a = idx >> 3, e = idx & 7;
        sQh[a][e] = (e<HDD) ? __float2half_rn(Qp[(ch*ACH+a)*HDD+e]) : __float2half_rn(0.f);
    }
    if (tid < ACH*2){
        int a = tid >> 1;
        sFused[a][150 + (tid&1)] = -1e30f;
    }
    __syncthreads();
    if (tid < HDD){
        float acc = 0.f;
        #pragma unroll
        for (int ww=0;ww<5;ww++) acc += sP[ww][tid];
        sVbar[tid] = acc * (1.f/TT);
    }
    __syncthreads();
    if (tid < 150){
        #pragma unroll
        for (int e=0;e<HDD;e++) sVt[e][tid] = __float2half_rn(vv[e] + sVbar[e]);
        #pragma unroll
        for (int e=HDD;e<8;e++) sVt[e][tid] = __float2half_rn(0.f);
    } else if (tid < 152){
        #pragma unroll
        for (int e=0;e<8;e++) sVt[e][tid] = __float2half_rn(0.f);
    }
    __syncthreads();

    int r0 = w*32 + g;                     // rows r0, r0+8, r0+16, r0+24
    __half2 kA0 = *(const __half2*)&sKh[r0][e0];
    __half2 kA1 = *(const __half2*)&sKh[r0+8][e0];
    __half2 kA2 = *(const __half2*)&sKh[r0+16][e0];
    __half2 kA3 = *(const __half2*)&sKh[r0+24][e0];
    unsigned bfu[19];
    #pragma unroll
    for (int j=0;j<19;j++){
        int c = j*8 + g;
        __half2 bb = __halves2half2(sVt[e0][c], sVt[e0+1][c]);
        bfu[j] = h2u(bb);
    }

    const __half2 NEGBIG = __floats2half2_rn(-60000.f, -60000.f);
    #pragma unroll 2
    for (int a=0;a<ACH;a++){
        __half2 q2 = *(const __half2*)&sQh[a][e0];
        unsigned a0 = h2u(__hmul2(kA0, q2));
        unsigned a1 = h2u(__hmul2(kA1, q2));
        unsigned a2 = h2u(__hmul2(kA2, q2));
        unsigned a3 = h2u(__hmul2(kA3, q2));
        __half2 mA = NEGBIG, mB = NEGBIG, mC = NEGBIG, mD = NEGBIG;
        #pragma unroll
        for (int j=0;j<19;j++){
            unsigned d0, d1, f0, f1;
            mma8h(d0, d1, a0, a1, bfu[j]);
            mma8h(f0, f1, a2, a3, bfu[j]);
            bool ok = (j<18) || (qd!=3);   // exclude padded c=150,151
            if (ok){
                mA = __hmax2(mA, *(__half2*)&d0);
                mB = __hmax2(mB, *(__half2*)&d1);
                mC = __hmax2(mC, *(__half2*)&f0);
                mD = __hmax2(mD, *(__half2*)&f1);
            }
        }
        float rm0 = fmaxf(__low2float(mA), __high2float(mA));
        float rm1 = fmaxf(__low2float(mB), __high2float(mB));
        float rm2 = fmaxf(__low2float(mC), __high2float(mC));
        float rm3 = fmaxf(__low2float(mD), __high2float(mD));
        // quad reduce (full max over all 8 cols of each tile-row)
        #pragma unroll
        for (int o=1;o<=2;o<<=1){
            rm0 = fmaxf(rm0, __shfl_xor_sync(0xffffffffu, rm0, o));
            rm1 = fmaxf(rm1, __shfl_xor_sync(0xffffffffu, rm1, o));
            rm2 = fmaxf(rm2, __shfl_xor_sync(0xffffffffu, rm2, o));
            rm3 = fmaxf(rm3, __shfl_xor_sync(0xffffffffu, rm3, o));
        }
        if (qd==0){
            if (r0      < 150) sFused[a][r0]      = rm0;
            if (r0 + 8  < 150) sFused[a][r0 + 8]  = rm1;
            if (r0 + 16 < 150) sFused[a][r0 + 16] = rm2;
            if (r0 + 24 < 150) sFused[a][r0 + 24] = rm3;
        }
    }
    __syncthreads();

    // ---- pass 2: block max per a from sFused (warp w handles a = w, w+5, ...) ----
    #pragma unroll 1
    for (int a = w; a < ACH; a += 5){
        float mm = -INFINITY;
        #pragma unroll
        for (int bb = lane; bb < 152; bb += 32) mm = fmaxf(mm, sFused[a][bb]);
        #pragma unroll
        for (int o=16;o>0;o>>=1) mm = fmaxf(mm, __shfl_xor_sync(0xffffffffu, mm, o));
        if (lane==0) sBMax[a] = mm;
    }
    __syncthreads();
    for (int idx=tid; idx<ACH*152; idx+=160){
        int a = idx / 152, b = idx - a*152;
        sFused[a][b] = __expf(sFused[a][b] - sBMax[a]);
    }
    __syncthreads();
    for (int idx=tid; idx<ACH*7; idx+=160){
        int a = idx / 7, j = idx % 7;
        const float4* ex4 = (const float4*)&sFused[a][0];
        const float4* q4  = (const float4*)&sQt[j][0];
        float acc = 0.f;
        #pragma unroll 5
        for (int b4=0;b4<38;b4++){
            float4 e4 = ex4[b4], qq = q4[b4];
            acc = fmaf(e4.x, qq.x, acc);
            acc = fmaf(e4.y, qq.y, acc);
            acc = fmaf(e4.z, qq.z, acc);
            acc = fmaf(e4.w, qq.w, acc);
        }
        sDot[a][j] = acc;
    }
    __syncthreads();
    int b_ = i/HH, h_ = i%HH;
    for (int idx=tid; idx<ACH*HDD; idx+=160){
        int a = idx / HDD, e = idx % HDD;
        g_attn[s][((ch*ACH+a)*BB + b_)*DD + h_*HDD + e] = sDot[a][e]/sDot[a][6];
    }
}

// ---------------- 3. ffn (+ next-layer Q; + head fused in block 149, l=2) -
__global__ void __launch_bounds__(512) k_ffnq(
                       const float* __restrict__ out_w, const float* __restrict__ out_b,
                       const float* __restrict__ w1, const float* __restrict__ b1,
                       const float* __restrict__ w2, const float* __restrict__ b2,
                       const float* __restrict__ n2g, const float* __restrict__ n2b,
                       const float* __restrict__ in_w, const float* __restrict__ in_b,
                       const float* __restrict__ n1g, const float* __restrict__ n1b,
                       const float* __restrict__ p1w, const float* __restrict__ p1b,
                       const float* __restrict__ p2w, const float* __restrict__ p2b,
                       const float* __restrict__ ow, const float* __restrict__ ob,
                       float* __restrict__ out, int l){
    extern __shared__ float dyn[];
    int tid = threadIdx.x;
    int w = tid >> 5, lane = tid & 31;
    int gw = blockIdx.x*16 + w;           // row index, t-major
    int t = gw >> 4;
    int r16 = gw & 15;
    int s = r16 >> 3, b = r16 & 7;
    __shared__ float sA[16][DD], sXn[16][DD], sHid[16][4*DD];
    __shared__ float sLast[BB*2*DD];      // head scratch (block 149 only)
    __shared__ float sC[BB][2*DD];

    #pragma unroll 1
    for (int s2=0; s2<2; s2++){
        int pl2 = s2*LL + l;
        const float* gw1 = w1 + pl2*4*DD*DD;        // [120][30]
        for (int g2=tid; g2<4*DD*DD; g2+=512){
            int j = g2 / DD, q = g2 - j*DD;
            dyn[W1T_OFF + s2*3840 + q*128 + j] = gw1[g2];
        }
        const float* gw2 = w2 + pl2*DD*4*DD;        // [30][120]
        for (int g2=tid; g2<4*DD*DD; g2+=512){
            int d = g2 / (4*DD), j = g2 - d*4*DD;
            dyn[W2T_OFF + s2*3840 + j*32 + d] = gw2[g2];
        }
        const float* go = out_w + pl2*DD*DD;        // [30][30]
        for (int g2=tid; g2<DD*DD; g2+=512){
            int o = g2 / DD, j = g2 - o*DD;
            dyn[OWT_OFF + s2*960 + j*32 + o] = go[g2];
        }
        if (l+1 < LL){
            const float* gi = in_w + (pl2+1)*3*DD*DD;   // q rows [30][30]
            for (int g2=tid; g2<DD*DD; g2+=512){
                int d = g2 / DD, j = g2 - d*DD;
                dyn[IWT_OFF + s2*960 + j*32 + d] = gi[g2];
            }
        }
    }
    int ro = (t*BB+b)*DD;
    if (lane<DD) sA[w][lane] = g_attn[s][ro+lane];
    __syncthreads();

    int pl_ = s*LL+l;
    const float* W1t = dyn + W1T_OFF + s*3840;
    const float* W2t = dyn + W2T_OFF + s*3840;
    const float* OWt = dyn + OWT_OFF + s*960;
    const float* IWt = dyn + IWT_OFF + s*960;

    float x = 0.f;
    if (lane<DD){
        float acc = out_b[pl_*DD + lane];
        #pragma unroll
        for (int j=0;j<DD;j++) acc = fmaf(sA[w][j], OWt[j*32+lane], acc);
        x = g_h[s][ro+lane] + acc;        // residual
    }
    float sum = warpsum(x), sq = warpsum(x*x);
    float m = sum*(1.f/DD), var = sq*(1.f/DD)-m*m, rr = rsqrtf(var+1e-5f);
    if (lane<DD) sXn[w][lane] = (x-m)*rr*n2g[pl_*DD+lane] + n2b[pl_*DD+lane];
    __syncwarp();
    #pragma unroll
    for (int mo=0; mo<4; mo++){
        int j = mo*32 + lane;
        if (j < 4*DD){
            float acc = b1[pl_*4*DD + j];
            #pragma unroll
            for (int q=0;q<DD;q++) acc = fmaf(sXn[w][q], W1t[q*128+j], acc);
            sHid[w][j] = fmaxf(acc, 0.f);
        }
    }
    __syncwarp();
    float hnew = 0.f;
    if (lane<DD){
        float acc = b2[pl_*DD + lane];
        #pragma unroll 4
        for (int j=0;j<4*DD;j++) acc = fmaf(sHid[w][j], W2t[j*32+lane], acc);
        hnew = x + acc;                   // residual 2
        g_h[s][ro+lane] = hnew;
    }
    if (l+1 < LL){
        float sum2 = warpsum(hnew), sq2 = warpsum(hnew*hnew);
        float m2 = sum2*(1.f/DD), var2 = sq2*(1.f/DD)-m2*m2, r2 = rsqrtf(var2+1e-5f);
        int pb = (pl_+1)*DD;
        if (lane<DD) sA[w][lane] = (hnew-m2)*r2*n1g[pb+lane] + n1b[pb+lane];
        __syncwarp();
        if (lane<DD){
            float acc = in_b[(pl_+1)*3*DD + lane];
            #pragma unroll
            for (int j=0;j<DD;j++) acc = fmaf(sA[w][j], IWt[j*32+lane], acc);
            acc *= 0.4082482904638631f;
            int i = b*HH + lane/HDD, e = lane%HDD;
            g_Q[s][(i*TT+t)*HDD+e] = acc;
        }
    } else if (blockIdx.x == 149){
        if (lane < DD){
            sLast[b*2*DD + s*DD + lane] = hnew;
            out[BB + b*2*DD + s*DD + lane] = hnew;   // last_hs output
        }
        __syncthreads();
        int bb = tid >> 6, j = tid & 63;
        if (j < 2*DD){
            float acc = p1b[j];
            const float* wr = p1w + j*2*DD;
            for (int q=0;q<2*DD;q++) acc = fmaf(sLast[bb*2*DD+q], wr[q], acc);
            sC[bb][j] = fmaxf(acc, 0.f);
        }
        __syncthreads();
        float a2 = 0.f;
        if (j < 2*DD){
            a2 = p2b[j];
            const float* wr = p2w + j*2*DD;
            for (int q=0;q<2*DD;q++) a2 = fmaf(sC[bb][q], wr[q], a2);
            a2 = (a2 + sLast[bb*2*DD+j]) * ow[j];
        }
        __syncthreads();
        if (j < 2*DD) sC[bb][j] = a2;
        __syncthreads();
        if (tid < BB){
            float a3 = ob[0];
            for (int q=0;q<2*DD;q++) a3 += sC[tid][q];
            out[tid] = a3;
        }
    }
}

// -------------------------------------------------------------------------
extern "C" void kernel_launch(void* const* d_in, const int* in_sizes, int n_in,
                              void* d_out, int out_size){
    const float* xl   = (const float*)d_in[0];
    const float* xa   = (const float*)d_in[1];
    const float* xv   = (const float*)d_in[2];
    const float* Wl   = (const float*)d_in[3];
    const float* Wa   = (const float*)d_in[4];
    const float* Wv   = (const float*)d_in[5];
    const float* in_w = (const float*)d_in[6];
    const float* in_b = (const float*)d_in[7];
    const float* outw = (const float*)d_in[8];
    const float* outb = (const float*)d_in[9];
    const float* l1w  = (const float*)d_in[10];
    const float* l1b  = (const float*)d_in[11];
    const float* l2w  = (const float*)d_in[12];
    const float* l2b  = (const float*)d_in[13];
    const float* n1g  = (const float*)d_in[14];
    const float* n1b  = (const float*)d_in[15];
    const float* n2g  = (const float*)d_in[16];
    const float* n2b  = (const float*)d_in[17];
    const float* p1w  = (const float*)d_in[18];
    const float* p1b  = (const float*)d_in[19];
    const float* p2w  = (const float*)d_in[20];
    const float* p2b  = (const float*)d_in[21];
    const float* ow   = (const float*)d_in[22];
    const float* ob   = (const float*)d_in[23];
    float* out = (float*)d_out;

    cudaFuncSetAttribute(k_ffnq, cudaFuncAttributeMaxDynamicSharedMemorySize,
                         DYN_FLOATS*4);
    cudaFuncSetAttribute(k_pre, cudaFuncAttributeMaxDynamicSharedMemorySize,
                         PRE_FLOATS*4);

    k_pre<<<TT, 256, PRE_FLOATS*4>>>(xl, xa, xv, Wl, Wa, Wv, in_w, in_b, n1g, n1b);
    for (int l=0; l<LL; l++){
        k_att<<<dim3(NCH, NI, 2), 160>>>(l);
        k_ffnq<<<(2*TT*BB)/16, 512, DYN_FLOATS*4>>>(
                                      outw, outb, l1w, l1b, l2w, l2b, n2g, n2b,
                                      in_w, in_b, n1g, n1b,
                                      p1w, p1b, p2w, p2b, ow, ob, out, l);
    }
}